// round 1
// baseline (speedup 1.0000x reference)
#include <cuda_runtime.h>
#include <math.h>

#define N_   256
#define C_   512
#define T_   4
#define HW_  64
#define THW_ 256
#define ELEMS (N_ * C_ * THW_)   // 33554432 floats per tensor

// Scratch (static device globals; no runtime allocation)
__device__ float g_q[ELEMS];
__device__ float g_k[ELEMS];
__device__ float g_v[ELEMS];
__device__ float g_virt[ELEMS];

// ---------------------------------------------------------------------------
// conv 1x3x3, padding (0,1,1).  out[n,co,t,h,w] = sum_ci,ky,kx W[co,ci,ky,kx] *
// x[n,ci,t,h+ky-1,w+kx-1]  (+ optional residual)
// grid: (C_/128, N_*T_), block: 128 threads.
// Block computes a 128co x 64hw tile for one (n,t) slab.
// Thread (cog = tid>>3 in [0,16), hrow = tid&7): 8 co (stride 16) x one h-row (8 w).
// ---------------------------------------------------------------------------
__global__ __launch_bounds__(128, 2)
void conv3x3_kernel(const float* __restrict__ x, const float* __restrict__ w,
                    const float* __restrict__ res, float* __restrict__ out)
{
    __shared__ float xs[8][10][10];   // 8 ci, padded 10x10 plane
    __shared__ float ws[128][8][9];   // 128 co x 8 ci x 9 taps

    const int nt   = blockIdx.y;
    const int n    = nt >> 2;
    const int t    = nt & 3;
    const int co0  = blockIdx.x * 128;
    const int tid  = threadIdx.x;
    const int cog  = tid >> 3;   // 0..15
    const int hrow = tid & 7;    // 0..7

    const float* xb = x + ((size_t)n * C_ * T_ + t) * (size_t)HW_;  // + ci*256 + h*8 + w

    float acc[8][8];
#pragma unroll
    for (int u = 0; u < 8; u++)
#pragma unroll
        for (int p = 0; p < 8; p++) acc[u][p] = 0.f;

    for (int ci0 = 0; ci0 < C_; ci0 += 8) {
        // load padded x planes (800 floats)
        for (int idx = tid; idx < 800; idx += 128) {
            int ci = idx / 100;
            int r  = idx - ci * 100;
            int yy = r / 10, xx = r - yy * 10;
            int h = yy - 1, ww = xx - 1;
            float val = 0.f;
            if ((unsigned)h < 8u && (unsigned)ww < 8u)
                val = xb[(size_t)(ci0 + ci) * 256 + h * 8 + ww];
            (&xs[0][0][0])[idx] = val;
        }
        // load weights (9216 floats); w index ((co*C_+ci)*9 + tap)
        for (int idx = tid; idx < 128 * 72; idx += 128) {
            int co = idx / 72;
            int r  = idx - co * 72;  // = ci*9 + tap
            (&ws[0][0][0])[idx] = w[((size_t)(co0 + co) * C_ + ci0) * 9 + r];
        }
        __syncthreads();

#pragma unroll
        for (int ci = 0; ci < 8; ci++) {
#pragma unroll
            for (int ky = 0; ky < 3; ky++) {
                float xv[10];
#pragma unroll
                for (int i = 0; i < 10; i++) xv[i] = xs[ci][hrow + ky][i];
#pragma unroll
                for (int kx = 0; kx < 3; kx++) {
                    float wv[8];
#pragma unroll
                    for (int u = 0; u < 8; u++) wv[u] = ws[cog + 16 * u][ci][ky * 3 + kx];
#pragma unroll
                    for (int u = 0; u < 8; u++)
#pragma unroll
                        for (int p = 0; p < 8; p++)
                            acc[u][p] += wv[u] * xv[kx + p];
                }
            }
        }
        __syncthreads();
    }

#pragma unroll
    for (int u = 0; u < 8; u++) {
        int co = co0 + cog + 16 * u;
        size_t o = ((size_t)n * C_ + co) * THW_ + (size_t)t * HW_ + hrow * 8;
#pragma unroll
        for (int p = 0; p < 8; p++) {
            float val = acc[u][p];
            if (res) val += res[o + p];
            out[o + p] = val;
        }
    }
}

// ---------------------------------------------------------------------------
// Attention: per spatial location s (256 of them), A = softmax_group(Q K^T / sqrt(C)),
// virt = A V.  grid: (4 i-tiles of 64, 256 s), block 256, dynamic smem.
// smem layout (floats): A[64*257] | stage[256*65] | rois[256 ints]
// ---------------------------------------------------------------------------
#define SM_A      0
#define SM_STAGE  16448          // 64*257
#define SM_ROIS   (16448 + 16640)  // stage = 256*65 = 16640
#define SM_FLOATS (SM_ROIS + 256)  // 33344 floats = 133376 bytes

__global__ void attn_kernel(const float* __restrict__ q, const float* __restrict__ k,
                            const float* __restrict__ v, const int* __restrict__ roi,
                            float* __restrict__ virt)
{
    extern __shared__ float sm[];
    float* A     = sm + SM_A;
    float* stage = sm + SM_STAGE;
    int*   rois  = (int*)(sm + SM_ROIS);

    const int s   = blockIdx.y;
    const int i0  = blockIdx.x * 64;
    const int tid = threadIdx.x;

    rois[tid] = roi[tid];

    const int ti = tid >> 4;   // 0..15
    const int tj = tid & 15;   // 0..15

    // ---- GEMM1: A[64 x 256] = Q_s K_s^T ----
    float acc[4][16];
#pragma unroll
    for (int r = 0; r < 4; r++)
#pragma unroll
        for (int jj = 0; jj < 16; jj++) acc[r][jj] = 0.f;

    float* Qc = stage;          // 64*33
    float* Kc = stage + 2112;   // 256*33

    for (int c0 = 0; c0 < C_; c0 += 32) {
        __syncthreads();
        for (int idx = tid; idx < 64 * 32; idx += 256) {
            int i = idx >> 5, c = idx & 31;
            Qc[i * 33 + c] = q[((size_t)(i0 + i) * C_ + c0 + c) * THW_ + s];
        }
        for (int idx = tid; idx < 256 * 32; idx += 256) {
            int j = idx >> 5, c = idx & 31;
            Kc[j * 33 + c] = k[((size_t)j * C_ + c0 + c) * THW_ + s];
        }
        __syncthreads();
#pragma unroll
        for (int c = 0; c < 32; c++) {
            float xq[4], xk[16];
#pragma unroll
            for (int r = 0; r < 4; r++) xq[r] = Qc[(ti * 4 + r) * 33 + c];
#pragma unroll
            for (int jj = 0; jj < 16; jj++) xk[jj] = Kc[(tj + 16 * jj) * 33 + c];
#pragma unroll
            for (int r = 0; r < 4; r++)
#pragma unroll
                for (int jj = 0; jj < 16; jj++)
                    acc[r][jj] += xq[r] * xk[jj];
        }
    }

    // masked scores into A (masked -> large negative; exp underflows to 0)
    const float scale = 0.044194173824159216f;  // 1/sqrt(512)
#pragma unroll
    for (int r = 0; r < 4; r++) {
        int ig = i0 + ti * 4 + r;
        int ri = rois[ig];
#pragma unroll
        for (int jj = 0; jj < 16; jj++) {
            int j = tj + 16 * jj;
            A[(ti * 4 + r) * 257 + j] = (rois[j] == ri) ? acc[r][jj] * scale : -1e30f;
        }
    }
    __syncthreads();

    // ---- softmax over j, 4 threads per row ----
    {
        int row = tid >> 2;
        int l4  = tid & 3;
        float* Ar = A + row * 257;
        float m = -1e30f;
        for (int j = l4 * 64; j < l4 * 64 + 64; j++) m = fmaxf(m, Ar[j]);
        m = fmaxf(m, __shfl_xor_sync(0xffffffffu, m, 1));
        m = fmaxf(m, __shfl_xor_sync(0xffffffffu, m, 2));
        float sum = 0.f;
        for (int j = l4 * 64; j < l4 * 64 + 64; j++) {
            float e = expf(Ar[j] - m);
            Ar[j] = e;
            sum += e;
        }
        sum += __shfl_xor_sync(0xffffffffu, sum, 1);
        sum += __shfl_xor_sync(0xffffffffu, sum, 2);
        float inv = 1.f / sum;
        for (int j = l4 * 64; j < l4 * 64 + 64; j++) Ar[j] *= inv;
    }
    __syncthreads();

    // ---- GEMM2: virt[64 x 512] = A V_s ----
    const int tc = tid & 15;
    for (int c0 = 0; c0 < C_; c0 += 64) {
        for (int idx = tid; idx < 256 * 64; idx += 256) {
            int j = idx >> 6, c = idx & 63;
            stage[j * 65 + c] = v[((size_t)j * C_ + c0 + c) * THW_ + s];
        }
        __syncthreads();
        float acc2[4][4];
#pragma unroll
        for (int r = 0; r < 4; r++)
#pragma unroll
            for (int cc = 0; cc < 4; cc++) acc2[r][cc] = 0.f;
        for (int j = 0; j < 256; j++) {
            float a[4], vv[4];
#pragma unroll
            for (int r = 0; r < 4; r++) a[r] = A[(ti * 4 + r) * 257 + j];
#pragma unroll
            for (int cc = 0; cc < 4; cc++) vv[cc] = stage[j * 65 + tc + 16 * cc];
#pragma unroll
            for (int r = 0; r < 4; r++)
#pragma unroll
                for (int cc = 0; cc < 4; cc++)
                    acc2[r][cc] += a[r] * vv[cc];
        }
#pragma unroll
        for (int r = 0; r < 4; r++)
#pragma unroll
            for (int cc = 0; cc < 4; cc++)
                virt[((size_t)(i0 + ti * 4 + r) * C_ + c0 + tc + 16 * cc) * THW_ + s] = acc2[r][cc];
        __syncthreads();
    }
}

// ---------------------------------------------------------------------------
// GroupNorm (num_groups=1 over C,T,H,W) + affine + ReLU, in place.
// grid: 256 (one block per sample n), block 256.
// ---------------------------------------------------------------------------
__global__ __launch_bounds__(256)
void gn_relu_kernel(float* __restrict__ buf, const float* __restrict__ gamma,
                    const float* __restrict__ beta)
{
    __shared__ double red[256];
    __shared__ double red2[256];
    const int n = blockIdx.x;
    float* b = buf + (size_t)n * C_ * THW_;
    const int M = C_ * THW_;  // 131072

    double s = 0.0, s2 = 0.0;
    for (int i = threadIdx.x; i < M; i += 256) {
        float v = b[i];
        s  += v;
        s2 += (double)v * v;
    }
    red[threadIdx.x]  = s;
    red2[threadIdx.x] = s2;
    __syncthreads();
    for (int off = 128; off > 0; off >>= 1) {
        if (threadIdx.x < off) {
            red[threadIdx.x]  += red[threadIdx.x + off];
            red2[threadIdx.x] += red2[threadIdx.x + off];
        }
        __syncthreads();
    }
    double mu_d  = red[0] / M;
    double var_d = red2[0] / M - mu_d * mu_d;
    float mu   = (float)mu_d;
    float rstd = rsqrtf((float)var_d + 1e-5f);

    for (int i = threadIdx.x; i < M; i += 256) {
        int c = i >> 8;  // / THW_
        float v = (b[i] - mu) * rstd;
        v = v * gamma[c] + beta[c];
        b[i] = fmaxf(v, 0.f);
    }
}

// ---------------------------------------------------------------------------
extern "C" void kernel_launch(void* const* d_in, const int* in_sizes, int n_in,
                              void* d_out, int out_size)
{
    const float* x   = (const float*)d_in[0];
    const int*   roi = (const int*)d_in[1];
    const float* Wq  = (const float*)d_in[2];
    const float* Wk  = (const float*)d_in[3];
    const float* Wv  = (const float*)d_in[4];
    const float* Wc  = (const float*)d_in[5];
    const float* gam = (const float*)d_in[6];
    const float* bet = (const float*)d_in[7];
    float* out = (float*)d_out;

    float *q, *k, *v, *virt;
    cudaGetSymbolAddress((void**)&q,    g_q);
    cudaGetSymbolAddress((void**)&k,    g_k);
    cudaGetSymbolAddress((void**)&v,    g_v);
    cudaGetSymbolAddress((void**)&virt, g_virt);

    cudaFuncSetAttribute(attn_kernel, cudaFuncAttributeMaxDynamicSharedMemorySize,
                         SM_FLOATS * (int)sizeof(float));

    dim3 cgrid(C_ / 128, N_ * T_);
    conv3x3_kernel<<<cgrid, 128>>>(x, Wq, nullptr, q);
    conv3x3_kernel<<<cgrid, 128>>>(x, Wk, nullptr, k);
    conv3x3_kernel<<<cgrid, 128>>>(x, Wv, nullptr, v);

    attn_kernel<<<dim3(4, 256), 256, SM_FLOATS * sizeof(float)>>>(q, k, v, roi, virt);

    gn_relu_kernel<<<256, 256>>>(virt, gam, bet);

    conv3x3_kernel<<<cgrid, 128>>>(virt, Wc, x, out);
}

// round 2
// speedup vs baseline: 1.0027x; 1.0027x over previous
#include <cuda_runtime.h>
#include <math.h>

#define N_   256
#define C_   512
#define T_   4
#define HW_  64
#define THW_ 256
#define ELEMS (N_ * C_ * THW_)   // 33554432 floats per tensor

// Scratch (static device globals; no runtime allocation)
__device__ float g_q[ELEMS];
__device__ float g_k[ELEMS];
__device__ float g_v[ELEMS];
__device__ float g_virt[ELEMS];

// ---------------------------------------------------------------------------
// conv 1x3x3, padding (0,1,1).  out[n,co,t,h,w] = sum_ci,ky,kx W[co,ci,ky,kx] *
// x[n,ci,t,h+ky-1,w+kx-1]  (+ optional residual)
// grid: (C_/128, N_*T_), block: 128 threads.
// Block computes a 128co x 64hw tile for one (n,t) slab.
// Thread (cog = tid>>3 in [0,16), hrow = tid&7): 8 co (stride 16) x one h-row (8 w).
// ---------------------------------------------------------------------------
__global__ __launch_bounds__(128, 2)
void conv3x3_kernel(const float* __restrict__ x, const float* __restrict__ w,
                    const float* __restrict__ res, float* __restrict__ out)
{
    __shared__ float xs[8][10][10];   // 8 ci, padded 10x10 plane
    __shared__ float ws[128][8][9];   // 128 co x 8 ci x 9 taps

    const int nt   = blockIdx.y;
    const int n    = nt >> 2;
    const int t    = nt & 3;
    const int co0  = blockIdx.x * 128;
    const int tid  = threadIdx.x;
    const int cog  = tid >> 3;   // 0..15
    const int hrow = tid & 7;    // 0..7

    const float* xb = x + ((size_t)n * C_ * T_ + t) * (size_t)HW_;  // + ci*256 + h*8 + w

    float acc[8][8];
#pragma unroll
    for (int u = 0; u < 8; u++)
#pragma unroll
        for (int p = 0; p < 8; p++) acc[u][p] = 0.f;

    for (int ci0 = 0; ci0 < C_; ci0 += 8) {
        // load padded x planes (800 floats)
        for (int idx = tid; idx < 800; idx += 128) {
            int ci = idx / 100;
            int r  = idx - ci * 100;
            int yy = r / 10, xx = r - yy * 10;
            int h = yy - 1, ww = xx - 1;
            float val = 0.f;
            if ((unsigned)h < 8u && (unsigned)ww < 8u)
                val = xb[(size_t)(ci0 + ci) * 256 + h * 8 + ww];
            (&xs[0][0][0])[idx] = val;
        }
        // load weights (9216 floats); w index ((co*C_+ci)*9 + tap)
        for (int idx = tid; idx < 128 * 72; idx += 128) {
            int co = idx / 72;
            int r  = idx - co * 72;  // = ci*9 + tap
            (&ws[0][0][0])[idx] = w[((size_t)(co0 + co) * C_ + ci0) * 9 + r];
        }
        __syncthreads();

#pragma unroll
        for (int ci = 0; ci < 8; ci++) {
#pragma unroll
            for (int ky = 0; ky < 3; ky++) {
                float xv[10];
#pragma unroll
                for (int i = 0; i < 10; i++) xv[i] = xs[ci][hrow + ky][i];
#pragma unroll
                for (int kx = 0; kx < 3; kx++) {
                    float wv[8];
#pragma unroll
                    for (int u = 0; u < 8; u++) wv[u] = ws[cog + 16 * u][ci][ky * 3 + kx];
#pragma unroll
                    for (int u = 0; u < 8; u++)
#pragma unroll
                        for (int p = 0; p < 8; p++)
                            acc[u][p] += wv[u] * xv[kx + p];
                }
            }
        }
        __syncthreads();
    }

#pragma unroll
    for (int u = 0; u < 8; u++) {
        int co = co0 + cog + 16 * u;
        size_t o = ((size_t)n * C_ + co) * THW_ + (size_t)t * HW_ + hrow * 8;
#pragma unroll
        for (int p = 0; p < 8; p++) {
            float val = acc[u][p];
            if (res) val += res[o + p];
            out[o + p] = val;
        }
    }
}

// ---------------------------------------------------------------------------
// Attention: per spatial location s (256 of them), A = softmax_group(Q K^T / sqrt(C)),
// virt = A V.  grid: (4 i-tiles of 64, 256 s), block 256, dynamic smem.
// smem layout (floats): A[64*257] | stage[256*65] | rois[256 ints]
// ---------------------------------------------------------------------------
#define SM_A      0
#define SM_STAGE  16448          // 64*257
#define SM_ROIS   (16448 + 16640)  // stage = 256*65 = 16640
#define SM_FLOATS (SM_ROIS + 256)  // 33344 floats = 133376 bytes

__global__ void attn_kernel(const float* __restrict__ q, const float* __restrict__ k,
                            const float* __restrict__ v, const int* __restrict__ roi,
                            float* __restrict__ virt)
{
    extern __shared__ float sm[];
    float* A     = sm + SM_A;
    float* stage = sm + SM_STAGE;
    int*   rois  = (int*)(sm + SM_ROIS);

    const int s   = blockIdx.y;
    const int i0  = blockIdx.x * 64;
    const int tid = threadIdx.x;

    rois[tid] = roi[tid];

    const int ti = tid >> 4;   // 0..15
    const int tj = tid & 15;   // 0..15

    // ---- GEMM1: A[64 x 256] = Q_s K_s^T ----
    float acc[4][16];
#pragma unroll
    for (int r = 0; r < 4; r++)
#pragma unroll
        for (int jj = 0; jj < 16; jj++) acc[r][jj] = 0.f;

    float* Qc = stage;          // 64*33
    float* Kc = stage + 2112;   // 256*33

    for (int c0 = 0; c0 < C_; c0 += 32) {
        __syncthreads();
        for (int idx = tid; idx < 64 * 32; idx += 256) {
            int i = idx >> 5, c = idx & 31;
            Qc[i * 33 + c] = q[((size_t)(i0 + i) * C_ + c0 + c) * THW_ + s];
        }
        for (int idx = tid; idx < 256 * 32; idx += 256) {
            int j = idx >> 5, c = idx & 31;
            Kc[j * 33 + c] = k[((size_t)j * C_ + c0 + c) * THW_ + s];
        }
        __syncthreads();
#pragma unroll
        for (int c = 0; c < 32; c++) {
            float xq[4], xk[16];
#pragma unroll
            for (int r = 0; r < 4; r++) xq[r] = Qc[(ti * 4 + r) * 33 + c];
#pragma unroll
            for (int jj = 0; jj < 16; jj++) xk[jj] = Kc[(tj + 16 * jj) * 33 + c];
#pragma unroll
            for (int r = 0; r < 4; r++)
#pragma unroll
                for (int jj = 0; jj < 16; jj++)
                    acc[r][jj] += xq[r] * xk[jj];
        }
    }

    // masked scores into A (masked -> large negative; exp underflows to 0)
    const float scale = 0.044194173824159216f;  // 1/sqrt(512)
#pragma unroll
    for (int r = 0; r < 4; r++) {
        int ig = i0 + ti * 4 + r;
        int ri = rois[ig];
#pragma unroll
        for (int jj = 0; jj < 16; jj++) {
            int j = tj + 16 * jj;
            A[(ti * 4 + r) * 257 + j] = (rois[j] == ri) ? acc[r][jj] * scale : -1e30f;
        }
    }
    __syncthreads();

    // ---- softmax over j, 4 threads per row ----
    {
        int row = tid >> 2;
        int l4  = tid & 3;
        float* Ar = A + row * 257;
        float m = -1e30f;
        for (int j = l4 * 64; j < l4 * 64 + 64; j++) m = fmaxf(m, Ar[j]);
        m = fmaxf(m, __shfl_xor_sync(0xffffffffu, m, 1));
        m = fmaxf(m, __shfl_xor_sync(0xffffffffu, m, 2));
        float sum = 0.f;
        for (int j = l4 * 64; j < l4 * 64 + 64; j++) {
            float e = expf(Ar[j] - m);
            Ar[j] = e;
            sum += e;
        }
        sum += __shfl_xor_sync(0xffffffffu, sum, 1);
        sum += __shfl_xor_sync(0xffffffffu, sum, 2);
        float inv = 1.f / sum;
        for (int j = l4 * 64; j < l4 * 64 + 64; j++) Ar[j] *= inv;
    }
    __syncthreads();

    // ---- GEMM2: virt[64 x 512] = A V_s ----
    const int tc = tid & 15;
    for (int c0 = 0; c0 < C_; c0 += 64) {
        for (int idx = tid; idx < 256 * 64; idx += 256) {
            int j = idx >> 6, c = idx & 63;
            stage[j * 65 + c] = v[((size_t)j * C_ + c0 + c) * THW_ + s];
        }
        __syncthreads();
        float acc2[4][4];
#pragma unroll
        for (int r = 0; r < 4; r++)
#pragma unroll
            for (int cc = 0; cc < 4; cc++) acc2[r][cc] = 0.f;
        for (int j = 0; j < 256; j++) {
            float a[4], vv[4];
#pragma unroll
            for (int r = 0; r < 4; r++) a[r] = A[(ti * 4 + r) * 257 + j];
#pragma unroll
            for (int cc = 0; cc < 4; cc++) vv[cc] = stage[j * 65 + tc + 16 * cc];
#pragma unroll
            for (int r = 0; r < 4; r++)
#pragma unroll
                for (int cc = 0; cc < 4; cc++)
                    acc2[r][cc] += a[r] * vv[cc];
        }
#pragma unroll
        for (int r = 0; r < 4; r++)
#pragma unroll
            for (int cc = 0; cc < 4; cc++)
                virt[((size_t)(i0 + ti * 4 + r) * C_ + c0 + tc + 16 * cc) * THW_ + s] = acc2[r][cc];
        __syncthreads();
    }
}

// ---------------------------------------------------------------------------
// GroupNorm (num_groups=1 over C,T,H,W) + affine + ReLU, in place.
// grid: 256 (one block per sample n), block 256.
// ---------------------------------------------------------------------------
__global__ __launch_bounds__(256)
void gn_relu_kernel(float* __restrict__ buf, const float* __restrict__ gamma,
                    const float* __restrict__ beta)
{
    __shared__ double red[256];
    __shared__ double red2[256];
    const int n = blockIdx.x;
    float* b = buf + (size_t)n * C_ * THW_;
    const int M = C_ * THW_;  // 131072

    double s = 0.0, s2 = 0.0;
    for (int i = threadIdx.x; i < M; i += 256) {
        float v = b[i];
        s  += v;
        s2 += (double)v * v;
    }
    red[threadIdx.x]  = s;
    red2[threadIdx.x] = s2;
    __syncthreads();
    for (int off = 128; off > 0; off >>= 1) {
        if (threadIdx.x < off) {
            red[threadIdx.x]  += red[threadIdx.x + off];
            red2[threadIdx.x] += red2[threadIdx.x + off];
        }
        __syncthreads();
    }
    double mu_d  = red[0] / M;
    double var_d = red2[0] / M - mu_d * mu_d;
    float mu   = (float)mu_d;
    float rstd = rsqrtf((float)var_d + 1e-5f);

    for (int i = threadIdx.x; i < M; i += 256) {
        int c = i >> 8;  // / THW_
        float v = (b[i] - mu) * rstd;
        v = v * gamma[c] + beta[c];
        b[i] = fmaxf(v, 0.f);
    }
}

// ---------------------------------------------------------------------------
extern "C" void kernel_launch(void* const* d_in, const int* in_sizes, int n_in,
                              void* d_out, int out_size)
{
    const float* x   = (const float*)d_in[0];
    const int*   roi = (const int*)d_in[1];
    const float* Wq  = (const float*)d_in[2];
    const float* Wk  = (const float*)d_in[3];
    const float* Wv  = (const float*)d_in[4];
    const float* Wc  = (const float*)d_in[5];
    const float* gam = (const float*)d_in[6];
    const float* bet = (const float*)d_in[7];
    float* out = (float*)d_out;

    float *q, *k, *v, *virt;
    cudaGetSymbolAddress((void**)&q,    g_q);
    cudaGetSymbolAddress((void**)&k,    g_k);
    cudaGetSymbolAddress((void**)&v,    g_v);
    cudaGetSymbolAddress((void**)&virt, g_virt);

    cudaFuncSetAttribute(attn_kernel, cudaFuncAttributeMaxDynamicSharedMemorySize,
                         SM_FLOATS * (int)sizeof(float));

    dim3 cgrid(C_ / 128, N_ * T_);
    conv3x3_kernel<<<cgrid, 128>>>(x, Wq, nullptr, q);
    conv3x3_kernel<<<cgrid, 128>>>(x, Wk, nullptr, k);
    conv3x3_kernel<<<cgrid, 128>>>(x, Wv, nullptr, v);

    attn_kernel<<<dim3(4, 256), 256, SM_FLOATS * sizeof(float)>>>(q, k, v, roi, virt);

    gn_relu_kernel<<<256, 256>>>(virt, gam, bet);

    conv3x3_kernel<<<cgrid, 128>>>(virt, Wc, x, out);
}

// round 6
// speedup vs baseline: 1.3926x; 1.3889x over previous
#include <cuda_runtime.h>
#include <math.h>
#include <stdint.h>

#define N_    256
#define C_    512
#define T_    4
#define HW_   64
#define THW_  256
#define K_TOT 4608              // 9 taps * 512 ci; k = tap*512 + ci
#define ELEMS (N_ * C_ * THW_)

__device__ float g_q[ELEMS];      // transposed [s][n][c]
__device__ float g_k[ELEMS];
__device__ float g_v[ELEMS];
__device__ float g_virt[ELEMS];   // standard [n][c][thw]
__device__ float g_whi[4][C_ * K_TOT];
__device__ float g_wlo[4][C_ * K_TOT];

// ---------------- helpers ----------------
__device__ __forceinline__ uint32_t f2tf32(float x) {
    uint32_t u; asm("cvt.rna.tf32.f32 %0, %1;" : "=r"(u) : "f"(x)); return u;
}
__device__ __forceinline__ void mma8(float* d, const uint32_t* a, const uint32_t* b) {
    asm volatile(
        "mma.sync.aligned.m16n8k8.row.col.f32.tf32.tf32.f32 "
        "{%0,%1,%2,%3}, {%4,%5,%6,%7}, {%8,%9}, {%0,%1,%2,%3};"
        : "+f"(d[0]), "+f"(d[1]), "+f"(d[2]), "+f"(d[3])
        : "r"(a[0]), "r"(a[1]), "r"(a[2]), "r"(a[3]), "r"(b[0]), "r"(b[1]));
}

// ---------------- weight split prepass ----------------
// W[co][ci][tap] fp32 -> Whi/Wlo[co][tap*512+ci] (tf32 hi + residual tf32 lo)
__global__ void wsplit_kernel(const float* __restrict__ W, float* __restrict__ Whi,
                              float* __restrict__ Wlo) {
    int kk  = blockIdx.x * 256 + threadIdx.x;   // 0..4607
    int co  = blockIdx.y;
    int tap = kk >> 9, ci = kk & 511;
    float v = W[((size_t)co * 512 + ci) * 9 + tap];
    uint32_t hi = f2tf32(v);
    uint32_t lo = f2tf32(v - __uint_as_float(hi));
    Whi[(size_t)co * K_TOT + kk] = __uint_as_float(hi);
    Wlo[(size_t)co * K_TOT + kk] = __uint_as_float(lo);
}

// ---------------- split-tf32 conv via mma.sync (legacy tensor path) ----------------
// GEMM per n: out[512co x 256s] = W[512 x 4608] @ im2col(x)[4608 x 256]
// grid (256 n, 4 co-tiles, 2 s-tiles), block 256 (8 warps of 64co x 32s).
// K chunks of 16, double-buffered smem; rows padded to stride 20 (conflict-free frags).
#define AH_OFF 0
#define AL_OFF 2560
#define BH_OFF 5120
#define BL_OFF 7680
#define BUF_FLOATS 10240
#define CONV_SMEM  (2 * BUF_FLOATS * 4)   // 81920 bytes
#define NCHUNK 288

__device__ __forceinline__ void stage_chunk(
    float* buf, const float* __restrict__ Wh, const float* __restrict__ Wl,
    const float* __restrict__ x, int n, int co0, int s0, int chunk, int tid)
{
    const int tap = chunk >> 5;            // 32 chunks per tap
    const int ci0 = (chunk & 31) << 4;     // 16 ci per chunk
    const int dy  = tap / 3 - 1;
    const int dx  = tap % 3 - 1;

    // A: 128co x 16k hi/lo  (2 float4 per thread per array)
#pragma unroll
    for (int r = 0; r < 2; ++r) {
        int i  = tid + 256 * r;            // 0..511 float4 slots
        int co = i >> 2, q4 = i & 3;
        const float* ph = Wh + (size_t)(co0 + co) * K_TOT + tap * 512 + ci0 + q4 * 4;
        const float* pl = Wl + (size_t)(co0 + co) * K_TOT + tap * 512 + ci0 + q4 * 4;
        float4 h = *(const float4*)ph;
        float4 l = *(const float4*)pl;
        float* dh = buf + AH_OFF + co * 20 + q4 * 4;
        float* dl = buf + AL_OFF + co * 20 + q4 * 4;
        dh[0] = h.x; dh[1] = h.y; dh[2] = h.z; dh[3] = h.w;
        dl[0] = l.x; dl[1] = l.y; dl[2] = l.z; dl[3] = l.w;
    }
    // B: 128cols x 16k im2col, split on the fly
    const int col = tid & 127;
    const int kk0 = (tid >> 7) * 8;
    const int s  = s0 + col;
    const int bt = s >> 6, bh = (s >> 3) & 7, bw = s & 7;
    const int hs = bh + dy, ws = bw + dx;
    const bool valid = ((unsigned)hs < 8u) && ((unsigned)ws < 8u);
    const float* xp = x + (((size_t)n * C_ + ci0 + kk0) * T_ + bt) * HW_ + hs * 8 + ws;
    float* ph = buf + BH_OFF + col * 20 + kk0;
    float* pl = buf + BL_OFF + col * 20 + kk0;
#pragma unroll
    for (int j = 0; j < 8; ++j) {
        float v = valid ? xp[(size_t)j * 256] : 0.f;
        uint32_t hi = f2tf32(v);
        ph[j] = __uint_as_float(hi);
        pl[j] = __uint_as_float(f2tf32(v - __uint_as_float(hi)));
    }
}

__global__ __launch_bounds__(256)
void conv_mma_kernel(const float* __restrict__ x, const float* __restrict__ Whi,
                     const float* __restrict__ Wlo, const float* __restrict__ res,
                     float* __restrict__ out, int transposed)
{
    extern __shared__ float smf[];
    const int tid = threadIdx.x;
    const int wid = tid >> 5;
    const int lid = tid & 31;
    const int n   = blockIdx.x;
    const int co0 = blockIdx.y * 128;
    const int s0  = blockIdx.z * 128;
    const int wm  = wid & 1;     // 0/1 -> 64-co halves
    const int wn  = wid >> 1;    // 0..3 -> 32-s quarters
    const int g   = lid >> 2;    // 0..7
    const int tg  = lid & 3;     // 0..3

    float acc[4][4][4];
#pragma unroll
    for (int mi = 0; mi < 4; mi++)
#pragma unroll
        for (int ni = 0; ni < 4; ni++)
#pragma unroll
            for (int r = 0; r < 4; r++) acc[mi][ni][r] = 0.f;

    stage_chunk(smf, Whi, Wlo, x, n, co0, s0, 0, tid);
    __syncthreads();

    for (int c = 0; c < NCHUNK; ++c) {
        if (c + 1 < NCHUNK)
            stage_chunk(smf + ((c + 1) & 1) * BUF_FLOATS, Whi, Wlo, x, n, co0, s0, c + 1, tid);

        const uint32_t* cu = (const uint32_t*)(smf + (c & 1) * BUF_FLOATS);
#pragma unroll
        for (int ks = 0; ks < 2; ++ks) {
            const int k0 = ks * 8;
            uint32_t ah[4][4], al[4][4], bh[4][2], bl[4][2];
#pragma unroll
            for (int mi = 0; mi < 4; mi++) {
                int base = (wm * 64 + mi * 16 + g) * 20 + k0 + tg;
                ah[mi][0] = cu[AH_OFF + base];
                ah[mi][1] = cu[AH_OFF + base + 160];
                ah[mi][2] = cu[AH_OFF + base + 4];
                ah[mi][3] = cu[AH_OFF + base + 164];
                al[mi][0] = cu[AL_OFF + base];
                al[mi][1] = cu[AL_OFF + base + 160];
                al[mi][2] = cu[AL_OFF + base + 4];
                al[mi][3] = cu[AL_OFF + base + 164];
            }
#pragma unroll
            for (int ni = 0; ni < 4; ni++) {
                int base = (wn * 32 + ni * 8 + g) * 20 + k0 + tg;
                bh[ni][0] = cu[BH_OFF + base];
                bh[ni][1] = cu[BH_OFF + base + 4];
                bl[ni][0] = cu[BL_OFF + base];
                bl[ni][1] = cu[BL_OFF + base + 4];
            }
#pragma unroll
            for (int mi = 0; mi < 4; mi++)
#pragma unroll
                for (int ni = 0; ni < 4; ni++) {
                    mma8(acc[mi][ni], ah[mi], bh[ni]);
                    mma8(acc[mi][ni], ah[mi], bl[ni]);
                    mma8(acc[mi][ni], al[mi], bh[ni]);
                }
        }
        __syncthreads();
    }

    // epilogue: D lane layout: c0->(r, c), c1->(r, c+1), c2->(r+8, c), c3->(r+8, c+1)
#pragma unroll
    for (int mi = 0; mi < 4; mi++) {
        const int row = co0 + wm * 64 + mi * 16 + g;
#pragma unroll
        for (int ni = 0; ni < 4; ni++) {
            const int colb = s0 + wn * 32 + ni * 8 + 2 * tg;
#pragma unroll
            for (int r = 0; r < 4; r++) {
                const int rr  = row + (r >= 2 ? 8 : 0);
                const int cc  = colb + (r & 1);
                float v = acc[mi][ni][r];
                if (transposed) {
                    out[((size_t)cc * N_ + n) * C_ + rr] = v;
                } else {
                    size_t o = ((size_t)n * C_ + rr) * THW_ + cc;
                    out[o] = res ? (v + res[o]) : v;
                }
            }
        }
    }
}

// ---------------- attention (q/k/v transposed [s][n][c]) ----------------
#define SM_A      0
#define SM_STAGE  16448
#define SM_ROIS   (16448 + 16640)
#define SM_FLOATS (SM_ROIS + 256)

__global__ void attn_kernel(const float* __restrict__ q, const float* __restrict__ k,
                            const float* __restrict__ v, const int* __restrict__ roi,
                            float* __restrict__ virt)
{
    extern __shared__ float smf[];
    float* A     = smf + SM_A;
    float* stage = smf + SM_STAGE;
    int*   rois  = (int*)(smf + SM_ROIS);

    const int s   = blockIdx.y;
    const int i0  = blockIdx.x * 64;
    const int tid = threadIdx.x;
    rois[tid] = roi[tid];

    const int ti = tid >> 4;
    const int tj = tid & 15;
    const size_t sb = (size_t)s * (N_ * C_);

    float acc[4][16];
#pragma unroll
    for (int r = 0; r < 4; r++)
#pragma unroll
        for (int jj = 0; jj < 16; jj++) acc[r][jj] = 0.f;

    float* Qc = stage;
    float* Kc = stage + 2112;

    for (int c0 = 0; c0 < C_; c0 += 32) {
        __syncthreads();
        for (int idx = tid; idx < 64 * 32; idx += 256) {
            int i = idx >> 5, c = idx & 31;
            Qc[i * 33 + c] = q[sb + (size_t)(i0 + i) * C_ + c0 + c];
        }
        for (int idx = tid; idx < 256 * 32; idx += 256) {
            int j = idx >> 5, c = idx & 31;
            Kc[j * 33 + c] = k[sb + (size_t)j * C_ + c0 + c];
        }
        __syncthreads();
#pragma unroll
        for (int c = 0; c < 32; c++) {
            float xq[4], xk[16];
#pragma unroll
            for (int r = 0; r < 4; r++) xq[r] = Qc[(ti * 4 + r) * 33 + c];
#pragma unroll
            for (int jj = 0; jj < 16; jj++) xk[jj] = Kc[(tj + 16 * jj) * 33 + c];
#pragma unroll
            for (int r = 0; r < 4; r++)
#pragma unroll
                for (int jj = 0; jj < 16; jj++)
                    acc[r][jj] += xq[r] * xk[jj];
        }
    }

    const float scale = 0.044194173824159216f;
#pragma unroll
    for (int r = 0; r < 4; r++) {
        int ri = rois[i0 + ti * 4 + r];
#pragma unroll
        for (int jj = 0; jj < 16; jj++) {
            int j = tj + 16 * jj;
            A[(ti * 4 + r) * 257 + j] = (rois[j] == ri) ? acc[r][jj] * scale : -1e30f;
        }
    }
    __syncthreads();

    {
        int row = tid >> 2;
        int l4  = tid & 3;
        float* Ar = A + row * 257;
        float m = -1e30f;
        for (int j = l4 * 64; j < l4 * 64 + 64; j++) m = fmaxf(m, Ar[j]);
        m = fmaxf(m, __shfl_xor_sync(0xffffffffu, m, 1));
        m = fmaxf(m, __shfl_xor_sync(0xffffffffu, m, 2));
        float sum = 0.f;
        for (int j = l4 * 64; j < l4 * 64 + 64; j++) {
            float e = expf(Ar[j] - m);
            Ar[j] = e;
            sum += e;
        }
        sum += __shfl_xor_sync(0xffffffffu, sum, 1);
        sum += __shfl_xor_sync(0xffffffffu, sum, 2);
        float inv = 1.f / sum;
        for (int j = l4 * 64; j < l4 * 64 + 64; j++) Ar[j] *= inv;
    }
    __syncthreads();

    const int tc = tid & 15;
    for (int c0 = 0; c0 < C_; c0 += 64) {
        for (int idx = tid; idx < 256 * 64; idx += 256) {
            int j = idx >> 6, c = idx & 63;
            stage[j * 65 + c] = v[sb + (size_t)j * C_ + c0 + c];
        }
        __syncthreads();
        float acc2[4][4];
#pragma unroll
        for (int r = 0; r < 4; r++)
#pragma unroll
            for (int cc = 0; cc < 4; cc++) acc2[r][cc] = 0.f;
        for (int j = 0; j < 256; j++) {
            float a[4], vv[4];
#pragma unroll
            for (int r = 0; r < 4; r++) a[r] = A[(ti * 4 + r) * 257 + j];
#pragma unroll
            for (int cc = 0; cc < 4; cc++) vv[cc] = stage[j * 65 + tc + 16 * cc];
#pragma unroll
            for (int r = 0; r < 4; r++)
#pragma unroll
                for (int cc = 0; cc < 4; cc++)
                    acc2[r][cc] += a[r] * vv[cc];
        }
#pragma unroll
        for (int r = 0; r < 4; r++)
#pragma unroll
            for (int cc = 0; cc < 4; cc++)
                virt[((size_t)(i0 + ti * 4 + r) * C_ + c0 + tc + 16 * cc) * THW_ + s] = acc2[r][cc];
        __syncthreads();
    }
}

// ---------------- GroupNorm(1 group) + affine + ReLU ----------------
__global__ __launch_bounds__(256)
void gn_relu_kernel(float* __restrict__ buf, const float* __restrict__ gamma,
                    const float* __restrict__ beta)
{
    __shared__ double red[256];
    __shared__ double red2[256];
    const int n = blockIdx.x;
    float* b = buf + (size_t)n * C_ * THW_;
    const int M = C_ * THW_;

    double s = 0.0, s2 = 0.0;
    for (int i = threadIdx.x; i < M; i += 256) {
        float v = b[i];
        s  += v;
        s2 += (double)v * v;
    }
    red[threadIdx.x]  = s;
    red2[threadIdx.x] = s2;
    __syncthreads();
    for (int off = 128; off > 0; off >>= 1) {
        if (threadIdx.x < off) {
            red[threadIdx.x]  += red[threadIdx.x + off];
            red2[threadIdx.x] += red2[threadIdx.x + off];
        }
        __syncthreads();
    }
    double mu_d  = red[0] / M;
    double var_d = red2[0] / M - mu_d * mu_d;
    float mu   = (float)mu_d;
    float rstd = rsqrtf((float)var_d + 1e-5f);

    for (int i = threadIdx.x; i < M; i += 256) {
        int c = i >> 8;
        float v = (b[i] - mu) * rstd;
        v = v * gamma[c] + beta[c];
        b[i] = fmaxf(v, 0.f);
    }
}

// ---------------------------------------------------------------------------
extern "C" void kernel_launch(void* const* d_in, const int* in_sizes, int n_in,
                              void* d_out, int out_size)
{
    const float* x   = (const float*)d_in[0];
    const int*   roi = (const int*)d_in[1];
    const float* Wq  = (const float*)d_in[2];
    const float* Wk  = (const float*)d_in[3];
    const float* Wv  = (const float*)d_in[4];
    const float* Wc  = (const float*)d_in[5];
    const float* gam = (const float*)d_in[6];
    const float* bet = (const float*)d_in[7];
    float* out = (float*)d_out;

    float *q, *k, *v, *virt, *whi, *wlo;
    cudaGetSymbolAddress((void**)&q,    g_q);
    cudaGetSymbolAddress((void**)&k,    g_k);
    cudaGetSymbolAddress((void**)&v,    g_v);
    cudaGetSymbolAddress((void**)&virt, g_virt);
    cudaGetSymbolAddress((void**)&whi,  g_whi);
    cudaGetSymbolAddress((void**)&wlo,  g_wlo);
    const size_t WS = (size_t)C_ * K_TOT;

    cudaFuncSetAttribute(conv_mma_kernel, cudaFuncAttributeMaxDynamicSharedMemorySize,
                         CONV_SMEM);
    cudaFuncSetAttribute(attn_kernel, cudaFuncAttributeMaxDynamicSharedMemorySize,
                         SM_FLOATS * (int)sizeof(float));

    dim3 wgrid(18, 512);
    wsplit_kernel<<<wgrid, 256>>>(Wq, whi + 0 * WS, wlo + 0 * WS);
    wsplit_kernel<<<wgrid, 256>>>(Wk, whi + 1 * WS, wlo + 1 * WS);
    wsplit_kernel<<<wgrid, 256>>>(Wv, whi + 2 * WS, wlo + 2 * WS);
    wsplit_kernel<<<wgrid, 256>>>(Wc, whi + 3 * WS, wlo + 3 * WS);

    dim3 cgrid(256, 4, 2);
    conv_mma_kernel<<<cgrid, 256, CONV_SMEM>>>(x, whi + 0 * WS, wlo + 0 * WS, nullptr, q, 1);
    conv_mma_kernel<<<cgrid, 256, CONV_SMEM>>>(x, whi + 1 * WS, wlo + 1 * WS, nullptr, k, 1);
    conv_mma_kernel<<<cgrid, 256, CONV_SMEM>>>(x, whi + 2 * WS, wlo + 2 * WS, nullptr, v, 1);

    attn_kernel<<<dim3(4, 256), 256, SM_FLOATS * sizeof(float)>>>(q, k, v, roi, virt);

    gn_relu_kernel<<<256, 256>>>(virt, gam, bet);

    conv_mma_kernel<<<cgrid, 256, CONV_SMEM>>>(virt, whi + 3 * WS, wlo + 3 * WS, x, out, 0);
}

// round 7
// speedup vs baseline: 2.9139x; 2.0924x over previous
#include <cuda_runtime.h>
#include <cuda_bf16.h>
#include <math.h>
#include <stdint.h>

#define N_    256
#define C_    512
#define T_    4
#define HW_   64
#define THW_  256
#define K2TOT 2304              // K_TOT/2 pairs; k = tap*512 + ci, pair = (ci, ci+1)
#define ELEMS (N_ * C_ * THW_)

__device__ float    g_q[ELEMS];      // transposed [s][n][c]
__device__ float    g_k[ELEMS];
__device__ float    g_v[ELEMS];
__device__ float    g_virt[ELEMS];   // standard [n][c][thw]
__device__ uint32_t g_w2hi[4][C_ * K2TOT];   // packed bf16x2 hi
__device__ uint32_t g_w2lo[4][C_ * K2TOT];   // packed bf16x2 lo

// ---------------- helpers ----------------
__device__ __forceinline__ void mma_bf16(float* d, const uint32_t* a, const uint32_t* b) {
    asm volatile(
        "mma.sync.aligned.m16n8k16.row.col.f32.bf16.bf16.f32 "
        "{%0,%1,%2,%3}, {%4,%5,%6,%7}, {%8,%9}, {%0,%1,%2,%3};"
        : "+f"(d[0]), "+f"(d[1]), "+f"(d[2]), "+f"(d[3])
        : "r"(a[0]), "r"(a[1]), "r"(a[2]), "r"(a[3]), "r"(b[0]), "r"(b[1]));
}
__device__ __forceinline__ uint32_t split_pack(float v0, float v1, uint32_t& lo) {
    __nv_bfloat162 h = __floats2bfloat162_rn(v0, v1);
    float r0 = v0 - __bfloat162float(h.x);
    float r1 = v1 - __bfloat162float(h.y);
    __nv_bfloat162 l = __floats2bfloat162_rn(r0, r1);
    lo = *(uint32_t*)&l;
    return *(uint32_t*)&h;
}

// ---------------- weight split prepass ----------------
// W[co][ci][tap] fp32 -> packed bf16x2 hi/lo arrays [co][k2], k2 = tap*256 + ci/2
__global__ void wsplit_kernel(const float* __restrict__ W, uint32_t* __restrict__ Whi,
                              uint32_t* __restrict__ Wlo) {
    int k2  = blockIdx.x * 256 + threadIdx.x;   // 0..2303
    int co  = blockIdx.y;
    int tap = k2 >> 8;
    int ci  = (k2 & 255) << 1;
    float v0 = W[((size_t)co * 512 + ci) * 9 + tap];
    float v1 = W[((size_t)co * 512 + ci + 1) * 9 + tap];
    uint32_t lo, hi = split_pack(v0, v1, lo);
    Whi[(size_t)co * K2TOT + k2] = hi;
    Wlo[(size_t)co * K2TOT + k2] = lo;
}

// ---------------- split-bf16 conv via mma.sync m16n8k16 ----------------
// GEMM per n: out[512co x 256s] = W[512 x 4608] @ im2col(x)[4608 x 256]
// grid (256 n, 4 co-tiles, 2 s-tiles), block 256 (8 warps of 64co x 32s).
// K chunks of 32 (16 k2-pairs), double-buffered k-major smem, row stride 136 u32
// -> frag LDS banks = 8*tg + g + 8*ni/16*mi : conflict-free.
#define SA  136
#define AH  0
#define AL  2176
#define BH  4352
#define BL  6528
#define BUF_U32 8704
#define CONV_SMEM (2 * BUF_U32 * 4)   // 69632 bytes
#define NCHUNK 144

__device__ __forceinline__ void stage(
    uint32_t* buf, const uint32_t* __restrict__ W2h, const uint32_t* __restrict__ W2l,
    const float* __restrict__ x, int n, int co0, int s0, int chunk, int tid)
{
    const int tap = chunk >> 4;            // 16 chunks per tap
    const int ci0 = (chunk & 15) << 5;     // 32 ci per chunk
    const int dy  = tap / 3 - 1;
    const int dx  = tap % 3 - 1;
    const int col = tid & 127;
    const int k2b = (tid >> 7) << 3;       // 0 or 8

    // A: weights, transpose [co][k2] -> As[k2][co]
    {
        size_t gidx = (size_t)(co0 + col) * K2TOT + tap * 256 + (ci0 >> 1) + k2b;
        uint4 h0 = *(const uint4*)(W2h + gidx);
        uint4 h1 = *(const uint4*)(W2h + gidx + 4);
        uint4 l0 = *(const uint4*)(W2l + gidx);
        uint4 l1 = *(const uint4*)(W2l + gidx + 4);
        uint32_t* ah = buf + AH + k2b * SA + col;
        uint32_t* al = buf + AL + k2b * SA + col;
        ah[0 * SA] = h0.x; ah[1 * SA] = h0.y; ah[2 * SA] = h0.z; ah[3 * SA] = h0.w;
        ah[4 * SA] = h1.x; ah[5 * SA] = h1.y; ah[6 * SA] = h1.z; ah[7 * SA] = h1.w;
        al[0 * SA] = l0.x; al[1 * SA] = l0.y; al[2 * SA] = l0.z; al[3 * SA] = l0.w;
        al[4 * SA] = l1.x; al[5 * SA] = l1.y; al[6 * SA] = l1.z; al[7 * SA] = l1.w;
    }
    // B: im2col + on-the-fly bf16 split, Bs[k2][col]
    {
        const int s  = s0 + col;
        const int bt = s >> 6, bhh = (s >> 3) & 7, bw = s & 7;
        const int hs = bhh + dy, ws = bw + dx;
        const bool valid = ((unsigned)hs < 8u) && ((unsigned)ws < 8u);
        const float* xp = x + (((size_t)n * C_ + ci0 + 2 * k2b) * T_ + bt) * HW_ + hs * 8 + ws;
        uint32_t* bh = buf + BH + k2b * SA + col;
        uint32_t* bl = buf + BL + k2b * SA + col;
#pragma unroll
        for (int j = 0; j < 8; ++j) {
            float v0 = valid ? xp[(size_t)(2 * j) * 256]     : 0.f;
            float v1 = valid ? xp[(size_t)(2 * j + 1) * 256] : 0.f;
            uint32_t lo, hi = split_pack(v0, v1, lo);
            bh[j * SA] = hi;
            bl[j * SA] = lo;
        }
    }
}

__global__ __launch_bounds__(256)
void conv_mma_kernel(const float* __restrict__ x, const uint32_t* __restrict__ Whi,
                     const uint32_t* __restrict__ Wlo, const float* __restrict__ res,
                     float* __restrict__ out, int transposed)
{
    extern __shared__ uint32_t smu[];
    const int tid = threadIdx.x;
    const int wid = tid >> 5;
    const int lid = tid & 31;
    const int n   = blockIdx.x;
    const int co0 = blockIdx.y * 128;
    const int s0  = blockIdx.z * 128;
    const int wm  = wid & 1;     // 64-co half
    const int wn  = wid >> 1;    // 32-s quarter
    const int g   = lid >> 2;    // 0..7
    const int tg  = lid & 3;     // 0..3

    float acc[4][4][4];
#pragma unroll
    for (int mi = 0; mi < 4; mi++)
#pragma unroll
        for (int ni = 0; ni < 4; ni++)
#pragma unroll
            for (int r = 0; r < 4; r++) acc[mi][ni][r] = 0.f;

    stage(smu, Whi, Wlo, x, n, co0, s0, 0, tid);
    __syncthreads();

    for (int c = 0; c < NCHUNK; ++c) {
        if (c + 1 < NCHUNK)
            stage(smu + ((c + 1) & 1) * BUF_U32, Whi, Wlo, x, n, co0, s0, c + 1, tid);

        const uint32_t* cu = smu + (c & 1) * BUF_U32;
#pragma unroll
        for (int ks = 0; ks < 2; ++ks) {
            const int k2o = ks * 8;
            uint32_t ah[4][4], al[4][4], bh[4][2], bl[4][2];
#pragma unroll
            for (int mi = 0; mi < 4; mi++) {
                int a0 = AH + (k2o + tg) * SA + wm * 64 + mi * 16 + g;
                ah[mi][0] = cu[a0];
                ah[mi][1] = cu[a0 + 8];
                ah[mi][2] = cu[a0 + 4 * SA];
                ah[mi][3] = cu[a0 + 4 * SA + 8];
                int a1 = a0 + (AL - AH);
                al[mi][0] = cu[a1];
                al[mi][1] = cu[a1 + 8];
                al[mi][2] = cu[a1 + 4 * SA];
                al[mi][3] = cu[a1 + 4 * SA + 8];
            }
#pragma unroll
            for (int ni = 0; ni < 4; ni++) {
                int b0 = BH + (k2o + tg) * SA + wn * 32 + ni * 8 + g;
                bh[ni][0] = cu[b0];
                bh[ni][1] = cu[b0 + 4 * SA];
                int b1 = b0 + (BL - BH);
                bl[ni][0] = cu[b1];
                bl[ni][1] = cu[b1 + 4 * SA];
            }
#pragma unroll
            for (int mi = 0; mi < 4; mi++)
#pragma unroll
                for (int ni = 0; ni < 4; ni++) {
                    mma_bf16(acc[mi][ni], ah[mi], bh[ni]);
                    mma_bf16(acc[mi][ni], ah[mi], bl[ni]);
                    mma_bf16(acc[mi][ni], al[mi], bh[ni]);
                }
        }
        __syncthreads();
    }

    // epilogue: D lane layout: c0->(g, 2tg), c1->(g, 2tg+1), c2->(g+8, 2tg), c3->(g+8, 2tg+1)
#pragma unroll
    for (int mi = 0; mi < 4; mi++) {
        const int row = co0 + wm * 64 + mi * 16 + g;
#pragma unroll
        for (int ni = 0; ni < 4; ni++) {
            const int colb = s0 + wn * 32 + ni * 8 + 2 * tg;
#pragma unroll
            for (int r = 0; r < 4; r++) {
                const int rr = row + (r >= 2 ? 8 : 0);
                const int cc = colb + (r & 1);
                float v = acc[mi][ni][r];
                if (transposed) {
                    out[((size_t)cc * N_ + n) * C_ + rr] = v;
                } else {
                    size_t o = ((size_t)n * C_ + rr) * THW_ + cc;
                    out[o] = res ? (v + res[o]) : v;
                }
            }
        }
    }
}

// ---------------- attention (q/k/v transposed [s][n][c]) ----------------
#define SM_A      0
#define SM_STAGE  16448
#define SM_ROIS   (16448 + 16640)
#define SM_FLOATS (SM_ROIS + 256)

__global__ void attn_kernel(const float* __restrict__ q, const float* __restrict__ k,
                            const float* __restrict__ v, const int* __restrict__ roi,
                            float* __restrict__ virt)
{
    extern __shared__ float smf[];
    float* A     = smf + SM_A;
    float* stage = smf + SM_STAGE;
    int*   rois  = (int*)(smf + SM_ROIS);

    const int s   = blockIdx.y;
    const int i0  = blockIdx.x * 64;
    const int tid = threadIdx.x;
    rois[tid] = roi[tid];

    const int ti = tid >> 4;
    const int tj = tid & 15;
    const size_t sb = (size_t)s * (N_ * C_);

    float acc[4][16];
#pragma unroll
    for (int r = 0; r < 4; r++)
#pragma unroll
        for (int jj = 0; jj < 16; jj++) acc[r][jj] = 0.f;

    float* Qc = stage;
    float* Kc = stage + 2112;

    for (int c0 = 0; c0 < C_; c0 += 32) {
        __syncthreads();
        for (int idx = tid; idx < 64 * 32; idx += 256) {
            int i = idx >> 5, c = idx & 31;
            Qc[i * 33 + c] = q[sb + (size_t)(i0 + i) * C_ + c0 + c];
        }
        for (int idx = tid; idx < 256 * 32; idx += 256) {
            int j = idx >> 5, c = idx & 31;
            Kc[j * 33 + c] = k[sb + (size_t)j * C_ + c0 + c];
        }
        __syncthreads();
#pragma unroll
        for (int c = 0; c < 32; c++) {
            float xq[4], xk[16];
#pragma unroll
            for (int r = 0; r < 4; r++) xq[r] = Qc[(ti * 4 + r) * 33 + c];
#pragma unroll
            for (int jj = 0; jj < 16; jj++) xk[jj] = Kc[(tj + 16 * jj) * 33 + c];
#pragma unroll
            for (int r = 0; r < 4; r++)
#pragma unroll
                for (int jj = 0; jj < 16; jj++)
                    acc[r][jj] += xq[r] * xk[jj];
        }
    }

    const float scale = 0.044194173824159216f;
#pragma unroll
    for (int r = 0; r < 4; r++) {
        int ri = rois[i0 + ti * 4 + r];
#pragma unroll
        for (int jj = 0; jj < 16; jj++) {
            int j = tj + 16 * jj;
            A[(ti * 4 + r) * 257 + j] = (rois[j] == ri) ? acc[r][jj] * scale : -1e30f;
        }
    }
    __syncthreads();

    {
        int row = tid >> 2;
        int l4  = tid & 3;
        float* Ar = A + row * 257;
        float m = -1e30f;
        for (int j = l4 * 64; j < l4 * 64 + 64; j++) m = fmaxf(m, Ar[j]);
        m = fmaxf(m, __shfl_xor_sync(0xffffffffu, m, 1));
        m = fmaxf(m, __shfl_xor_sync(0xffffffffu, m, 2));
        float sum = 0.f;
        for (int j = l4 * 64; j < l4 * 64 + 64; j++) {
            float e = expf(Ar[j] - m);
            Ar[j] = e;
            sum += e;
        }
        sum += __shfl_xor_sync(0xffffffffu, sum, 1);
        sum += __shfl_xor_sync(0xffffffffu, sum, 2);
        float inv = 1.f / sum;
        for (int j = l4 * 64; j < l4 * 64 + 64; j++) Ar[j] *= inv;
    }
    __syncthreads();

    const int tc = tid & 15;
    for (int c0 = 0; c0 < C_; c0 += 64) {
        for (int idx = tid; idx < 256 * 64; idx += 256) {
            int j = idx >> 6, c = idx & 63;
            stage[j * 65 + c] = v[sb + (size_t)j * C_ + c0 + c];
        }
        __syncthreads();
        float acc2[4][4];
#pragma unroll
        for (int r = 0; r < 4; r++)
#pragma unroll
            for (int cc = 0; cc < 4; cc++) acc2[r][cc] = 0.f;
        for (int j = 0; j < 256; j++) {
            float a[4], vv[4];
#pragma unroll
            for (int r = 0; r < 4; r++) a[r] = A[(ti * 4 + r) * 257 + j];
#pragma unroll
            for (int cc = 0; cc < 4; cc++) vv[cc] = stage[j * 65 + tc + 16 * cc];
#pragma unroll
            for (int r = 0; r < 4; r++)
#pragma unroll
                for (int cc = 0; cc < 4; cc++)
                    acc2[r][cc] += a[r] * vv[cc];
        }
#pragma unroll
        for (int r = 0; r < 4; r++)
#pragma unroll
            for (int cc = 0; cc < 4; cc++)
                virt[((size_t)(i0 + ti * 4 + r) * C_ + c0 + tc + 16 * cc) * THW_ + s] = acc2[r][cc];
        __syncthreads();
    }
}

// ---------------- GroupNorm(1 group) + affine + ReLU ----------------
__global__ __launch_bounds__(256)
void gn_relu_kernel(float* __restrict__ buf, const float* __restrict__ gamma,
                    const float* __restrict__ beta)
{
    __shared__ double red[256];
    __shared__ double red2[256];
    const int n = blockIdx.x;
    float* b = buf + (size_t)n * C_ * THW_;
    const int M = C_ * THW_;

    double s = 0.0, s2 = 0.0;
    for (int i = threadIdx.x; i < M; i += 256) {
        float v = b[i];
        s  += v;
        s2 += (double)v * v;
    }
    red[threadIdx.x]  = s;
    red2[threadIdx.x] = s2;
    __syncthreads();
    for (int off = 128; off > 0; off >>= 1) {
        if (threadIdx.x < off) {
            red[threadIdx.x]  += red[threadIdx.x + off];
            red2[threadIdx.x] += red2[threadIdx.x + off];
        }
        __syncthreads();
    }
    double mu_d  = red[0] / M;
    double var_d = red2[0] / M - mu_d * mu_d;
    float mu   = (float)mu_d;
    float rstd = rsqrtf((float)var_d + 1e-5f);

    for (int i = threadIdx.x; i < M; i += 256) {
        int c = i >> 8;
        float v = (b[i] - mu) * rstd;
        v = v * gamma[c] + beta[c];
        b[i] = fmaxf(v, 0.f);
    }
}

// ---------------------------------------------------------------------------
extern "C" void kernel_launch(void* const* d_in, const int* in_sizes, int n_in,
                              void* d_out, int out_size)
{
    const float* x   = (const float*)d_in[0];
    const int*   roi = (const int*)d_in[1];
    const float* Wq  = (const float*)d_in[2];
    const float* Wk  = (const float*)d_in[3];
    const float* Wv  = (const float*)d_in[4];
    const float* Wc  = (const float*)d_in[5];
    const float* gam = (const float*)d_in[6];
    const float* bet = (const float*)d_in[7];
    float* out = (float*)d_out;

    float *q, *k, *v, *virt;
    uint32_t *whi, *wlo;
    cudaGetSymbolAddress((void**)&q,    g_q);
    cudaGetSymbolAddress((void**)&k,    g_k);
    cudaGetSymbolAddress((void**)&v,    g_v);
    cudaGetSymbolAddress((void**)&virt, g_virt);
    cudaGetSymbolAddress((void**)&whi,  g_w2hi);
    cudaGetSymbolAddress((void**)&wlo,  g_w2lo);
    const size_t WS = (size_t)C_ * K2TOT;

    cudaFuncSetAttribute(conv_mma_kernel, cudaFuncAttributeMaxDynamicSharedMemorySize,
                         CONV_SMEM);
    cudaFuncSetAttribute(attn_kernel, cudaFuncAttributeMaxDynamicSharedMemorySize,
                         SM_FLOATS * (int)sizeof(float));

    dim3 wgrid(9, 512);
    wsplit_kernel<<<wgrid, 256>>>(Wq, whi + 0 * WS, wlo + 0 * WS);
    wsplit_kernel<<<wgrid, 256>>>(Wk, whi + 1 * WS, wlo + 1 * WS);
    wsplit_kernel<<<wgrid, 256>>>(Wv, whi + 2 * WS, wlo + 2 * WS);
    wsplit_kernel<<<wgrid, 256>>>(Wc, whi + 3 * WS, wlo + 3 * WS);

    dim3 cgrid(256, 4, 2);
    conv_mma_kernel<<<cgrid, 256, CONV_SMEM>>>(x, whi + 0 * WS, wlo + 0 * WS, nullptr, q, 1);
    conv_mma_kernel<<<cgrid, 256, CONV_SMEM>>>(x, whi + 1 * WS, wlo + 1 * WS, nullptr, k, 1);
    conv_mma_kernel<<<cgrid, 256, CONV_SMEM>>>(x, whi + 2 * WS, wlo + 2 * WS, nullptr, v, 1);

    attn_kernel<<<dim3(4, 256), 256, SM_FLOATS * sizeof(float)>>>(q, k, v, roi, virt);

    gn_relu_kernel<<<256, 256>>>(virt, gam, bet);

    conv_mma_kernel<<<cgrid, 256, CONV_SMEM>>>(virt, whi + 3 * WS, wlo + 3 * WS, x, out, 0);
}

// round 8
// speedup vs baseline: 3.9722x; 1.3632x over previous
#include <cuda_runtime.h>
#include <cuda_bf16.h>
#include <math.h>
#include <stdint.h>

#define N_    256
#define C_    512
#define T_    4
#define HW_   64
#define THW_  256
#define ELEMS (N_ * C_ * THW_)
#define K2TOT 2304               // 512ci/2 * 9 taps
#define HPAIR (ELEMS / 2)

__device__ float    g_q[ELEMS];      // transposed [s][n][c]
__device__ float    g_k[ELEMS];
__device__ float    g_v[ELEMS];
__device__ float    g_virt[ELEMS];   // [n][c][thw]
__device__ uint32_t g_xhi[HPAIR];    // packed bf16x2 [n][ci2][thw]
__device__ uint32_t g_xlo[HPAIR];
__device__ uint32_t g_vhi[HPAIR];
__device__ uint32_t g_vlo[HPAIR];
__device__ uint32_t g_wghi[4][K2TOT * C_];   // [chunk(32)][k2l(72)][co(512)]
__device__ uint32_t g_wglo[4][K2TOT * C_];

// ---------------- helpers ----------------
__device__ __forceinline__ void mma_bf16(float* d, const uint32_t* a, const uint32_t* b) {
    asm volatile(
        "mma.sync.aligned.m16n8k16.row.col.f32.bf16.bf16.f32 "
        "{%0,%1,%2,%3}, {%4,%5,%6,%7}, {%8,%9}, {%0,%1,%2,%3};"
        : "+f"(d[0]), "+f"(d[1]), "+f"(d[2]), "+f"(d[3])
        : "r"(a[0]), "r"(a[1]), "r"(a[2]), "r"(a[3]), "r"(b[0]), "r"(b[1]));
}
__device__ __forceinline__ uint32_t split_pack(float v0, float v1, uint32_t& lo) {
    __nv_bfloat162 h = __floats2bfloat162_rn(v0, v1);
    float r0 = v0 - __bfloat162float(h.x);
    float r1 = v1 - __bfloat162float(h.y);
    __nv_bfloat162 l = __floats2bfloat162_rn(r0, r1);
    lo = *(uint32_t*)&l;
    return *(uint32_t*)&h;
}

// ---------------- prepass: split x into packed bf16x2 hi/lo ----------------
// x fp32 [n][c][thw] -> hi/lo u32 [n][ci2][thw] pairing (2*ci2, 2*ci2+1)
__global__ void xsplit_kernel(const float* __restrict__ src, uint32_t* __restrict__ hi,
                              uint32_t* __restrict__ lo) {
    int idx = blockIdx.x * 256 + threadIdx.x;     // < HPAIR
    int n   = idx >> 16;
    int r   = idx & 65535;
    int ci2 = r >> 8, pos = r & 255;
    size_t base = ((size_t)n * C_ + 2 * ci2) * THW_ + pos;
    uint32_t l, h = split_pack(src[base], src[base + THW_], l);
    hi[idx] = h;
    lo[idx] = l;
}

// ---------------- prepass: weights -> k-major packed layout ----------------
// W[co][ci][tap] fp32 -> out[(chunk*72 + tap*8 + ci2l)*512 + co] bf16x2 hi/lo
__global__ void wsplit_kernel(const float* __restrict__ W, uint32_t* __restrict__ Whi,
                              uint32_t* __restrict__ Wlo) {
    int k2g = blockIdx.x;                // 0..2303
    int co  = blockIdx.y * 512 + threadIdx.x;   // grid.y=1, block 512
    int chunk = k2g / 72;
    int k2l   = k2g - chunk * 72;
    int tap   = k2l >> 3;
    int ci    = chunk * 16 + (k2l & 7) * 2;
    float v0 = W[((size_t)co * 512 + ci) * 9 + tap];
    float v1 = W[((size_t)co * 512 + ci + 1) * 9 + tap];
    uint32_t lo, hi = split_pack(v0, v1, lo);
    Whi[(size_t)k2g * 512 + co] = hi;
    Wlo[(size_t)k2g * 512 + co] = lo;
}

// ---------------- conv: split-bf16 mma.sync with tap-resident B slab ----------------
// out[512co x 256s] = W[512 x 4608] @ im2col(x);  grid (256 n, 4 co, 2 s), block 256.
// Per 16-ci chunk: stage A [72 k2][128 co] (stride 136) + B slab [8 k2][2t][10x10 pad]
// (stride 200); 9 taps of MMAs read B with shifted addresses (padding supplies zeros).
#define SA_A 136
#define SA_B 200
#define A_HI 0
#define A_LO 9792
#define B_HI 19584
#define B_LO 21184
#define CONV_SMEM (22784 * 4)   // 91136 bytes

__global__ __launch_bounds__(256, 2)
void conv_mma_kernel(const uint32_t* __restrict__ xhi, const uint32_t* __restrict__ xlo,
                     const uint32_t* __restrict__ whi, const uint32_t* __restrict__ wlo,
                     const float* __restrict__ res, float* __restrict__ out, int transposed)
{
    extern __shared__ uint32_t smu[];
    uint32_t* Ah = smu + A_HI;
    uint32_t* Al = smu + A_LO;
    uint32_t* Bh = smu + B_HI;
    uint32_t* Bl = smu + B_LO;

    const int tid = threadIdx.x;
    const int wid = tid >> 5, lid = tid & 31;
    const int n   = blockIdx.x;
    const int co0 = blockIdx.y * 128;
    const int s0  = blockIdx.z * 128;
    const int t0  = blockIdx.z * 2;
    const int wm  = wid & 1, wn = wid >> 1;
    const int g   = lid >> 2, tg = lid & 3;

    // zero B slabs once (borders persist as zero)
    for (int i = tid; i < 1600; i += 256) { Bh[i] = 0; Bl[i] = 0; }

    // per-ni B column bases (t*100 + h*10 + w)
    int tcb[4];
#pragma unroll
    for (int ni = 0; ni < 4; ni++) {
        int col = wn * 32 + ni * 8 + g;
        tcb[ni] = (col >> 6) * 100 + ((col >> 3) & 7) * 10 + (col & 7);
    }

    float acc[4][4][4];
#pragma unroll
    for (int mi = 0; mi < 4; mi++)
#pragma unroll
        for (int ni = 0; ni < 4; ni++)
#pragma unroll
            for (int r = 0; r < 4; r++) acc[mi][ni][r] = 0.f;

    for (int cc = 0; cc < 32; ++cc) {
        __syncthreads();
        // ---- stage A: [72 k2][128 co], coalesced uint4 ----
        {
            const uint32_t* wsh = whi + (size_t)cc * 72 * 512 + co0;
            const uint32_t* wsl = wlo + (size_t)cc * 72 * 512 + co0;
#pragma unroll
            for (int r = 0; r < 9; r++) {
                int i4  = tid + 256 * r;           // 0..2303
                int row = i4 >> 5;
                int c4  = (i4 & 31) << 2;
                uint4 h = *(const uint4*)(wsh + (size_t)row * 512 + c4);
                uint4 l = *(const uint4*)(wsl + (size_t)row * 512 + c4);
                *(uint4*)(Ah + row * SA_A + c4) = h;
                *(uint4*)(Al + row * SA_A + c4) = l;
            }
        }
        // ---- stage B slab interior: [8 k2][2 t][10x10] ----
        {
#pragma unroll
            for (int r = 0; r < 4; r++) {
                int i  = tid + 256 * r;            // 0..1023
                int j  = i >> 7;
                int t  = (i >> 6) & 1;
                int hw = i & 63;
                int h  = hw >> 3, w = hw & 7;
                size_t src = ((size_t)n * 256 + cc * 8 + j) * 256 + (size_t)(t0 + t) * 64 + hw;
                int dst = j * SA_B + t * 100 + (h + 1) * 10 + (w + 1);
                Bh[dst] = xhi[src];
                Bl[dst] = xlo[src];
            }
        }
        __syncthreads();

        // ---- 9 taps of MMAs ----
#pragma unroll
        for (int tap = 0; tap < 9; tap++) {
            const int sh = (tap / 3) * 10 + (tap % 3);
            const int ka = tap * 8;

            uint32_t fa[4][4], fbh[4][2], fbl[4][2];
            int bb = tg * SA_B + sh;
#pragma unroll
            for (int ni = 0; ni < 4; ni++) {
                int b0 = bb + tcb[ni];
                fbh[ni][0] = Bh[b0];
                fbh[ni][1] = Bh[b0 + 4 * SA_B];
                fbl[ni][0] = Bl[b0];
                fbl[ni][1] = Bl[b0 + 4 * SA_B];
            }
            // hi x hi
#pragma unroll
            for (int mi = 0; mi < 4; mi++) {
                int a0 = (ka + tg) * SA_A + wm * 64 + mi * 16 + g;
                fa[mi][0] = Ah[a0];
                fa[mi][1] = Ah[a0 + 8];
                fa[mi][2] = Ah[a0 + 4 * SA_A];
                fa[mi][3] = Ah[a0 + 4 * SA_A + 8];
            }
#pragma unroll
            for (int mi = 0; mi < 4; mi++)
#pragma unroll
                for (int ni = 0; ni < 4; ni++)
                    mma_bf16(acc[mi][ni], fa[mi], fbh[ni]);
            // hi x lo
#pragma unroll
            for (int mi = 0; mi < 4; mi++)
#pragma unroll
                for (int ni = 0; ni < 4; ni++)
                    mma_bf16(acc[mi][ni], fa[mi], fbl[ni]);
            // lo x hi
#pragma unroll
            for (int mi = 0; mi < 4; mi++) {
                int a0 = (ka + tg) * SA_A + wm * 64 + mi * 16 + g;
                fa[mi][0] = Al[a0];
                fa[mi][1] = Al[a0 + 8];
                fa[mi][2] = Al[a0 + 4 * SA_A];
                fa[mi][3] = Al[a0 + 4 * SA_A + 8];
            }
#pragma unroll
            for (int mi = 0; mi < 4; mi++)
#pragma unroll
                for (int ni = 0; ni < 4; ni++)
                    mma_bf16(acc[mi][ni], fa[mi], fbh[ni]);
        }
    }

    // epilogue: c0->(g,2tg) c1->(g,2tg+1) c2->(g+8,2tg) c3->(g+8,2tg+1)
#pragma unroll
    for (int mi = 0; mi < 4; mi++) {
        const int row = co0 + wm * 64 + mi * 16 + g;
#pragma unroll
        for (int ni = 0; ni < 4; ni++) {
            const int colb = s0 + wn * 32 + ni * 8 + 2 * tg;
#pragma unroll
            for (int r = 0; r < 4; r++) {
                const int rr = row + (r >= 2 ? 8 : 0);
                const int cc = colb + (r & 1);
                float v = acc[mi][ni][r];
                if (transposed) {
                    out[((size_t)cc * N_ + n) * C_ + rr] = v;
                } else {
                    size_t o = ((size_t)n * C_ + rr) * THW_ + cc;
                    out[o] = res ? (v + res[o]) : v;
                }
            }
        }
    }
}

// ---------------- attention (q/k/v transposed [s][n][c]) ----------------
#define SM_A      0
#define SM_STAGE  16448
#define SM_ROIS   (16448 + 16640)
#define SM_FLOATS (SM_ROIS + 256)

__global__ void attn_kernel(const float* __restrict__ q, const float* __restrict__ k,
                            const float* __restrict__ v, const int* __restrict__ roi,
                            float* __restrict__ virt)
{
    extern __shared__ float smf[];
    float* A     = smf + SM_A;
    float* stage = smf + SM_STAGE;
    int*   rois  = (int*)(smf + SM_ROIS);

    const int s   = blockIdx.y;
    const int i0  = blockIdx.x * 64;
    const int tid = threadIdx.x;
    rois[tid] = roi[tid];

    const int ti = tid >> 4;
    const int tj = tid & 15;
    const size_t sb = (size_t)s * (N_ * C_);

    float acc[4][16];
#pragma unroll
    for (int r = 0; r < 4; r++)
#pragma unroll
        for (int jj = 0; jj < 16; jj++) acc[r][jj] = 0.f;

    float* Qc = stage;
    float* Kc = stage + 2112;

    for (int c0 = 0; c0 < C_; c0 += 32) {
        __syncthreads();
        for (int idx = tid; idx < 64 * 32; idx += 256) {
            int i = idx >> 5, c = idx & 31;
            Qc[i * 33 + c] = q[sb + (size_t)(i0 + i) * C_ + c0 + c];
        }
        for (int idx = tid; idx < 256 * 32; idx += 256) {
            int j = idx >> 5, c = idx & 31;
            Kc[j * 33 + c] = k[sb + (size_t)j * C_ + c0 + c];
        }
        __syncthreads();
#pragma unroll
        for (int c = 0; c < 32; c++) {
            float xq[4], xk[16];
#pragma unroll
            for (int r = 0; r < 4; r++) xq[r] = Qc[(ti * 4 + r) * 33 + c];
#pragma unroll
            for (int jj = 0; jj < 16; jj++) xk[jj] = Kc[(tj + 16 * jj) * 33 + c];
#pragma unroll
            for (int r = 0; r < 4; r++)
#pragma unroll
                for (int jj = 0; jj < 16; jj++)
                    acc[r][jj] += xq[r] * xk[jj];
        }
    }

    const float scale = 0.044194173824159216f;
#pragma unroll
    for (int r = 0; r < 4; r++) {
        int ri = rois[i0 + ti * 4 + r];
#pragma unroll
        for (int jj = 0; jj < 16; jj++) {
            int j = tj + 16 * jj;
            A[(ti * 4 + r) * 257 + j] = (rois[j] == ri) ? acc[r][jj] * scale : -1e30f;
        }
    }
    __syncthreads();

    {
        int row = tid >> 2;
        int l4  = tid & 3;
        float* Ar = A + row * 257;
        float m = -1e30f;
        for (int j = l4 * 64; j < l4 * 64 + 64; j++) m = fmaxf(m, Ar[j]);
        m = fmaxf(m, __shfl_xor_sync(0xffffffffu, m, 1));
        m = fmaxf(m, __shfl_xor_sync(0xffffffffu, m, 2));
        float sum = 0.f;
        for (int j = l4 * 64; j < l4 * 64 + 64; j++) {
            float e = expf(Ar[j] - m);
            Ar[j] = e;
            sum += e;
        }
        sum += __shfl_xor_sync(0xffffffffu, sum, 1);
        sum += __shfl_xor_sync(0xffffffffu, sum, 2);
        float inv = 1.f / sum;
        for (int j = l4 * 64; j < l4 * 64 + 64; j++) Ar[j] *= inv;
    }
    __syncthreads();

    const int tc = tid & 15;
    for (int c0 = 0; c0 < C_; c0 += 64) {
        for (int idx = tid; idx < 256 * 64; idx += 256) {
            int j = idx >> 6, c = idx & 63;
            stage[j * 65 + c] = v[sb + (size_t)j * C_ + c0 + c];
        }
        __syncthreads();
        float acc2[4][4];
#pragma unroll
        for (int r = 0; r < 4; r++)
#pragma unroll
            for (int cc = 0; cc < 4; cc++) acc2[r][cc] = 0.f;
        for (int j = 0; j < 256; j++) {
            float a[4], vv[4];
#pragma unroll
            for (int r = 0; r < 4; r++) a[r] = A[(ti * 4 + r) * 257 + j];
#pragma unroll
            for (int cc = 0; cc < 4; cc++) vv[cc] = stage[j * 65 + tc + 16 * cc];
#pragma unroll
            for (int r = 0; r < 4; r++)
#pragma unroll
                for (int cc = 0; cc < 4; cc++)
                    acc2[r][cc] += a[r] * vv[cc];
        }
#pragma unroll
        for (int r = 0; r < 4; r++)
#pragma unroll
            for (int cc = 0; cc < 4; cc++)
                virt[((size_t)(i0 + ti * 4 + r) * C_ + c0 + tc + 16 * cc) * THW_ + s] = acc2[r][cc];
        __syncthreads();
    }
}

// ---------------- GroupNorm(1 group) + affine + ReLU + bf16 split-pack ----------------
__global__ __launch_bounds__(256)
void gn_relu_pack_kernel(const float* __restrict__ buf, const float* __restrict__ gamma,
                         const float* __restrict__ beta, uint32_t* __restrict__ vhi,
                         uint32_t* __restrict__ vlo)
{
    __shared__ double red[256];
    __shared__ double red2[256];
    const int n = blockIdx.x;
    const float* b = buf + (size_t)n * C_ * THW_;
    const int M = C_ * THW_;

    double s = 0.0, s2 = 0.0;
    for (int i = threadIdx.x; i < M; i += 256) {
        float v = b[i];
        s  += v;
        s2 += (double)v * v;
    }
    red[threadIdx.x]  = s;
    red2[threadIdx.x] = s2;
    __syncthreads();
    for (int off = 128; off > 0; off >>= 1) {
        if (threadIdx.x < off) {
            red[threadIdx.x]  += red[threadIdx.x + off];
            red2[threadIdx.x] += red2[threadIdx.x + off];
        }
        __syncthreads();
    }
    double mu_d  = red[0] / M;
    double var_d = red2[0] / M - mu_d * mu_d;
    float mu   = (float)mu_d;
    float rstd = rsqrtf((float)var_d + 1e-5f);

    for (int i = threadIdx.x; i < M / 2; i += 256) {
        int c2 = i >> 8, pos = i & 255;
        int c0 = 2 * c2;
        float v0 = (b[(size_t)c0 * THW_ + pos] - mu) * rstd * gamma[c0] + beta[c0];
        float v1 = (b[(size_t)(c0 + 1) * THW_ + pos] - mu) * rstd * gamma[c0 + 1] + beta[c0 + 1];
        v0 = fmaxf(v0, 0.f);
        v1 = fmaxf(v1, 0.f);
        uint32_t lo, hi = split_pack(v0, v1, lo);
        size_t o = ((size_t)n * 256 + c2) * 256 + pos;
        vhi[o] = hi;
        vlo[o] = lo;
    }
}

// ---------------------------------------------------------------------------
extern "C" void kernel_launch(void* const* d_in, const int* in_sizes, int n_in,
                              void* d_out, int out_size)
{
    const float* x   = (const float*)d_in[0];
    const int*   roi = (const int*)d_in[1];
    const float* Wq  = (const float*)d_in[2];
    const float* Wk  = (const float*)d_in[3];
    const float* Wv  = (const float*)d_in[4];
    const float* Wc  = (const float*)d_in[5];
    const float* gam = (const float*)d_in[6];
    const float* bet = (const float*)d_in[7];
    float* out = (float*)d_out;

    float *q, *k, *v, *virt;
    uint32_t *xhi, *xlo, *vhi, *vlo, *wghi, *wglo;
    cudaGetSymbolAddress((void**)&q,    g_q);
    cudaGetSymbolAddress((void**)&k,    g_k);
    cudaGetSymbolAddress((void**)&v,    g_v);
    cudaGetSymbolAddress((void**)&virt, g_virt);
    cudaGetSymbolAddress((void**)&xhi,  g_xhi);
    cudaGetSymbolAddress((void**)&xlo,  g_xlo);
    cudaGetSymbolAddress((void**)&vhi,  g_vhi);
    cudaGetSymbolAddress((void**)&vlo,  g_vlo);
    cudaGetSymbolAddress((void**)&wghi, g_wghi);
    cudaGetSymbolAddress((void**)&wglo, g_wglo);
    const size_t WS = (size_t)K2TOT * C_;

    cudaFuncSetAttribute(conv_mma_kernel, cudaFuncAttributeMaxDynamicSharedMemorySize,
                         CONV_SMEM);
    cudaFuncSetAttribute(attn_kernel, cudaFuncAttributeMaxDynamicSharedMemorySize,
                         SM_FLOATS * (int)sizeof(float));

    // prepasses
    xsplit_kernel<<<HPAIR / 256, 256>>>(x, xhi, xlo);
    wsplit_kernel<<<dim3(K2TOT, 1), 512>>>(Wq, wghi + 0 * WS, wglo + 0 * WS);
    wsplit_kernel<<<dim3(K2TOT, 1), 512>>>(Wk, wghi + 1 * WS, wglo + 1 * WS);
    wsplit_kernel<<<dim3(K2TOT, 1), 512>>>(Wv, wghi + 2 * WS, wglo + 2 * WS);
    wsplit_kernel<<<dim3(K2TOT, 1), 512>>>(Wc, wghi + 3 * WS, wglo + 3 * WS);

    // q, k, v convs (transposed outputs)
    dim3 cgrid(256, 4, 2);
    conv_mma_kernel<<<cgrid, 256, CONV_SMEM>>>(xhi, xlo, wghi + 0 * WS, wglo + 0 * WS,
                                               nullptr, q, 1);
    conv_mma_kernel<<<cgrid, 256, CONV_SMEM>>>(xhi, xlo, wghi + 1 * WS, wglo + 1 * WS,
                                               nullptr, k, 1);
    conv_mma_kernel<<<cgrid, 256, CONV_SMEM>>>(xhi, xlo, wghi + 2 * WS, wglo + 2 * WS,
                                               nullptr, v, 1);

    attn_kernel<<<dim3(4, 256), 256, SM_FLOATS * sizeof(float)>>>(q, k, v, roi, virt);

    gn_relu_pack_kernel<<<256, 256>>>(virt, gam, bet, vhi, vlo);

    conv_mma_kernel<<<cgrid, 256, CONV_SMEM>>>(vhi, vlo, wghi + 3 * WS, wglo + 3 * WS,
                                               x, out, 0);
}

// round 9
// speedup vs baseline: 5.7089x; 1.4372x over previous
#include <cuda_runtime.h>
#include <cuda_fp16.h>
#include <math.h>
#include <stdint.h>

#define N_    256
#define C_    512
#define T_    4
#define HW_   64
#define THW_  256
#define ELEMS (N_ * C_ * THW_)
#define K2TOT 2304               // 512ci/2 * 9 taps
#define HPAIR (ELEMS / 2)

__device__ float    g_q[ELEMS];      // transposed [s][n][c]
__device__ float    g_k[ELEMS];
__device__ float    g_v[ELEMS];
__device__ float    g_virt[ELEMS];   // [n][c][thw]
__device__ uint32_t g_xhi[HPAIR];    // packed fp16x2 [n][ci2][thw]
__device__ uint32_t g_xlo[HPAIR];
__device__ uint32_t g_vhi[HPAIR];
__device__ uint32_t g_vlo[HPAIR];
__device__ uint32_t g_wgh[4][K2TOT * C_];   // fp16x2 weights [chunk(32)][k2l(72)][co(512)]

// ---------------- helpers ----------------
__device__ __forceinline__ uint32_t smem_u32(const void* p) {
    uint32_t a;
    asm("{ .reg .u64 t; cvta.to.shared.u64 t, %1; cvt.u32.u64 %0, t; }" : "=r"(a) : "l"(p));
    return a;
}
__device__ __forceinline__ void mma_f16(float* d, const uint32_t* a, const uint32_t* b) {
    asm volatile(
        "mma.sync.aligned.m16n8k16.row.col.f32.f16.f16.f32 "
        "{%0,%1,%2,%3}, {%4,%5,%6,%7}, {%8,%9}, {%0,%1,%2,%3};"
        : "+f"(d[0]), "+f"(d[1]), "+f"(d[2]), "+f"(d[3])
        : "r"(a[0]), "r"(a[1]), "r"(a[2]), "r"(a[3]), "r"(b[0]), "r"(b[1]));
}
__device__ __forceinline__ uint32_t split_pack_h(float v0, float v1, uint32_t& lo) {
    __half2 h = __floats2half2_rn(v0, v1);
    float r0 = v0 - __half2float(__low2half(h));
    float r1 = v1 - __half2float(__high2half(h));
    __half2 l = __floats2half2_rn(r0, r1);
    lo = *(uint32_t*)&l;
    return *(uint32_t*)&h;
}
__device__ __forceinline__ void cpa16(uint32_t dst, const void* src) {
    asm volatile("cp.async.cg.shared.global [%0], [%1], 16;" :: "r"(dst), "l"(src));
}
__device__ __forceinline__ void cpa4(uint32_t dst, const void* src) {
    asm volatile("cp.async.ca.shared.global [%0], [%1], 4;" :: "r"(dst), "l"(src));
}

// ---------------- prepass: split x into packed fp16x2 hi/lo ----------------
__global__ void xsplit_kernel(const float* __restrict__ src, uint32_t* __restrict__ hi,
                              uint32_t* __restrict__ lo) {
    int idx = blockIdx.x * 256 + threadIdx.x;     // < HPAIR
    int n   = idx >> 16;
    int r   = idx & 65535;
    int ci2 = r >> 8, pos = r & 255;
    size_t base = ((size_t)n * C_ + 2 * ci2) * THW_ + pos;
    uint32_t l, h = split_pack_h(src[base], src[base + THW_], l);
    hi[idx] = h;
    lo[idx] = l;
}

// ---------------- prepass: weights -> k-major fp16x2 (single precision term) ----------------
// W[co][ci][tap] fp32 -> out[(chunk*72 + tap*8 + ci2l)*512 + co]
__global__ void wsplit_kernel(const float* __restrict__ W, uint32_t* __restrict__ Wh) {
    int k2g = blockIdx.x;                       // 0..2303
    int co  = threadIdx.x;                      // block 512
    int chunk = k2g / 72;
    int k2l   = k2g - chunk * 72;
    int tap   = k2l >> 3;
    int ci    = chunk * 16 + (k2l & 7) * 2;
    float v0 = W[((size_t)co * 512 + ci) * 9 + tap];
    float v1 = W[((size_t)co * 512 + ci + 1) * 9 + tap];
    __half2 h = __floats2half2_rn(v0, v1);
    Wh[(size_t)k2g * 512 + co] = *(uint32_t*)&h;
}

// ---------------- conv: fp16 2-term mma.sync, cp.async double-buffered ----------------
// out[512co x 256s] = W[512 x 4608] @ im2col(x);  grid (256 n, 4 co, 2 s), block 256.
#define SA_A 136
#define SA_B 200
#define BUF_U32 12992           // A 9792 | Bh 1600 | Bl 1600
#define BH_OFF  9792
#define BL_OFF  11392
#define CONV_SMEM (2 * BUF_U32 * 4)   // 103936 bytes

__device__ __forceinline__ void stage_async(
    uint32_t bufb, const uint32_t* __restrict__ wh, const uint32_t* __restrict__ xhi,
    const uint32_t* __restrict__ xlo, int n, int co0, int t0, int cc, int tid)
{
    // A: [72 k2][128 co] u32, 16B ops
    const uint32_t* wsrc = wh + (size_t)cc * 72 * 512 + co0;
#pragma unroll
    for (int r = 0; r < 9; r++) {
        int i   = tid + 256 * r;          // 0..2303
        int row = i >> 5;
        int c4  = (i & 31) << 2;
        cpa16(bufb + (uint32_t)(row * SA_A + c4) * 4, wsrc + (size_t)row * 512 + c4);
    }
    // B: [8 j][2 t][8x8 interior] hi/lo, 4B ops
#pragma unroll
    for (int r = 0; r < 4; r++) {
        int i  = tid + 256 * r;           // 0..1023
        int j  = i >> 7;
        int t  = (i >> 6) & 1;
        int hw = i & 63;
        int h  = hw >> 3, w = hw & 7;
        size_t src = ((size_t)n * 256 + cc * 8 + j) * 256 + (size_t)(t0 + t) * 64 + hw;
        uint32_t d = bufb + (uint32_t)(BH_OFF + j * SA_B + t * 100 + (h + 1) * 10 + (w + 1)) * 4;
        cpa4(d, xhi + src);
        cpa4(d + 1600 * 4, xlo + src);
    }
}

__global__ __launch_bounds__(256, 2)
void conv_mma_kernel(const uint32_t* __restrict__ xhi, const uint32_t* __restrict__ xlo,
                     const uint32_t* __restrict__ wh, const float* __restrict__ res,
                     float* __restrict__ out, int transposed)
{
    extern __shared__ uint32_t smu[];
    const uint32_t smb = smem_u32(smu);

    const int tid = threadIdx.x;
    const int wid = tid >> 5, lid = tid & 31;
    const int n   = blockIdx.x;
    const int co0 = blockIdx.y * 128;
    const int s0  = blockIdx.z * 128;
    const int t0  = blockIdx.z * 2;
    const int wm  = wid & 1, wn = wid >> 1;
    const int g   = lid >> 2, tg = lid & 3;

    // zero B regions of both buffers (borders persist as zero)
    for (int i = tid; i < 6400; i += 256) {
        int buf = i / 3200, off = i - buf * 3200;
        smu[buf * BUF_U32 + BH_OFF + off] = 0;
    }
    __syncthreads();

    // per-ni B column bases (t*100 + h*10 + w)
    int tcb[4];
#pragma unroll
    for (int ni = 0; ni < 4; ni++) {
        int col = wn * 32 + ni * 8 + g;
        tcb[ni] = (col >> 6) * 100 + ((col >> 3) & 7) * 10 + (col & 7);
    }

    float acc[4][4][4];
#pragma unroll
    for (int mi = 0; mi < 4; mi++)
#pragma unroll
        for (int ni = 0; ni < 4; ni++)
#pragma unroll
            for (int r = 0; r < 4; r++) acc[mi][ni][r] = 0.f;

    stage_async(smb, wh, xhi, xlo, n, co0, t0, 0, tid);
    asm volatile("cp.async.commit_group;" ::: "memory");

    for (int cc = 0; cc < 32; ++cc) {
        if (cc + 1 < 32) {
            stage_async(smb + ((cc + 1) & 1) * (BUF_U32 * 4), wh, xhi, xlo,
                        n, co0, t0, cc + 1, tid);
            asm volatile("cp.async.commit_group;" ::: "memory");
            asm volatile("cp.async.wait_group 1;" ::: "memory");
        } else {
            asm volatile("cp.async.wait_group 0;" ::: "memory");
        }
        __syncthreads();

        const uint32_t* Ah = smu + (cc & 1) * BUF_U32;
        const uint32_t* Bh = Ah + BH_OFF;
        const uint32_t* Bl = Ah + BL_OFF;

#pragma unroll
        for (int tap = 0; tap < 9; tap++) {
            const int sh = (tap / 3) * 10 + (tap % 3);
            const int ka = tap * 8;

            uint32_t fa[4][4], fbh[4][2], fbl[4][2];
            int bb = tg * SA_B + sh;
#pragma unroll
            for (int ni = 0; ni < 4; ni++) {
                int b0 = bb + tcb[ni];
                fbh[ni][0] = Bh[b0];
                fbh[ni][1] = Bh[b0 + 4 * SA_B];
                fbl[ni][0] = Bl[b0];
                fbl[ni][1] = Bl[b0 + 4 * SA_B];
            }
#pragma unroll
            for (int mi = 0; mi < 4; mi++) {
                int a0 = (ka + tg) * SA_A + wm * 64 + mi * 16 + g;
                fa[mi][0] = Ah[a0];
                fa[mi][1] = Ah[a0 + 8];
                fa[mi][2] = Ah[a0 + 4 * SA_A];
                fa[mi][3] = Ah[a0 + 4 * SA_A + 8];
            }
#pragma unroll
            for (int mi = 0; mi < 4; mi++)
#pragma unroll
                for (int ni = 0; ni < 4; ni++)
                    mma_f16(acc[mi][ni], fa[mi], fbh[ni]);
#pragma unroll
            for (int mi = 0; mi < 4; mi++)
#pragma unroll
                for (int ni = 0; ni < 4; ni++)
                    mma_f16(acc[mi][ni], fa[mi], fbl[ni]);
        }
        __syncthreads();
    }

    // epilogue: c0->(g,2tg) c1->(g,2tg+1) c2->(g+8,2tg) c3->(g+8,2tg+1)
#pragma unroll
    for (int mi = 0; mi < 4; mi++) {
        const int row = co0 + wm * 64 + mi * 16 + g;
#pragma unroll
        for (int ni = 0; ni < 4; ni++) {
            const int colb = s0 + wn * 32 + ni * 8 + 2 * tg;
#pragma unroll
            for (int r = 0; r < 4; r++) {
                const int rr = row + (r >= 2 ? 8 : 0);
                const int cc2 = colb + (r & 1);
                float v = acc[mi][ni][r];
                if (transposed) {
                    out[((size_t)cc2 * N_ + n) * C_ + rr] = v;
                } else {
                    size_t o = ((size_t)n * C_ + rr) * THW_ + cc2;
                    out[o] = res ? (v + res[o]) : v;
                }
            }
        }
    }
}

// ---------------- attention (q/k/v transposed [s][n][c]) ----------------
#define SM_A      0
#define SM_STAGE  16448
#define SM_ROIS   (16448 + 16640)
#define SM_FLOATS (SM_ROIS + 256)

__global__ void attn_kernel(const float* __restrict__ q, const float* __restrict__ k,
                            const float* __restrict__ v, const int* __restrict__ roi,
                            float* __restrict__ virt)
{
    extern __shared__ float smf[];
    float* A     = smf + SM_A;
    float* stage = smf + SM_STAGE;
    int*   rois  = (int*)(smf + SM_ROIS);

    const int s   = blockIdx.y;
    const int i0  = blockIdx.x * 64;
    const int tid = threadIdx.x;
    rois[tid] = roi[tid];

    const int ti = tid >> 4;
    const int tj = tid & 15;
    const size_t sb = (size_t)s * (N_ * C_);

    float acc[4][16];
#pragma unroll
    for (int r = 0; r < 4; r++)
#pragma unroll
        for (int jj = 0; jj < 16; jj++) acc[r][jj] = 0.f;

    float* Qc = stage;
    float* Kc = stage + 2112;

    for (int c0 = 0; c0 < C_; c0 += 32) {
        __syncthreads();
        for (int idx = tid; idx < 64 * 32; idx += 256) {
            int i = idx >> 5, c = idx & 31;
            Qc[i * 33 + c] = q[sb + (size_t)(i0 + i) * C_ + c0 + c];
        }
        for (int idx = tid; idx < 256 * 32; idx += 256) {
            int j = idx >> 5, c = idx & 31;
            Kc[j * 33 + c] = k[sb + (size_t)j * C_ + c0 + c];
        }
        __syncthreads();
#pragma unroll
        for (int c = 0; c < 32; c++) {
            float xq[4], xk[16];
#pragma unroll
            for (int r = 0; r < 4; r++) xq[r] = Qc[(ti * 4 + r) * 33 + c];
#pragma unroll
            for (int jj = 0; jj < 16; jj++) xk[jj] = Kc[(tj + 16 * jj) * 33 + c];
#pragma unroll
            for (int r = 0; r < 4; r++)
#pragma unroll
                for (int jj = 0; jj < 16; jj++)
                    acc[r][jj] += xq[r] * xk[jj];
        }
    }

    const float scale = 0.044194173824159216f;
#pragma unroll
    for (int r = 0; r < 4; r++) {
        int ri = rois[i0 + ti * 4 + r];
#pragma unroll
        for (int jj = 0; jj < 16; jj++) {
            int j = tj + 16 * jj;
            A[(ti * 4 + r) * 257 + j] = (rois[j] == ri) ? acc[r][jj] * scale : -1e30f;
        }
    }
    __syncthreads();

    {
        int row = tid >> 2;
        int l4  = tid & 3;
        float* Ar = A + row * 257;
        float m = -1e30f;
        for (int j = l4 * 64; j < l4 * 64 + 64; j++) m = fmaxf(m, Ar[j]);
        m = fmaxf(m, __shfl_xor_sync(0xffffffffu, m, 1));
        m = fmaxf(m, __shfl_xor_sync(0xffffffffu, m, 2));
        float sum = 0.f;
        for (int j = l4 * 64; j < l4 * 64 + 64; j++) {
            float e = expf(Ar[j] - m);
            Ar[j] = e;
            sum += e;
        }
        sum += __shfl_xor_sync(0xffffffffu, sum, 1);
        sum += __shfl_xor_sync(0xffffffffu, sum, 2);
        float inv = 1.f / sum;
        for (int j = l4 * 64; j < l4 * 64 + 64; j++) Ar[j] *= inv;
    }
    __syncthreads();

    const int tc = tid & 15;
    for (int c0 = 0; c0 < C_; c0 += 64) {
        for (int idx = tid; idx < 256 * 64; idx += 256) {
            int j = idx >> 6, c = idx & 63;
            stage[j * 65 + c] = v[sb + (size_t)j * C_ + c0 + c];
        }
        __syncthreads();
        float acc2[4][4];
#pragma unroll
        for (int r = 0; r < 4; r++)
#pragma unroll
            for (int cc = 0; cc < 4; cc++) acc2[r][cc] = 0.f;
        for (int j = 0; j < 256; j++) {
            float a[4], vv[4];
#pragma unroll
            for (int r = 0; r < 4; r++) a[r] = A[(ti * 4 + r) * 257 + j];
#pragma unroll
            for (int cc = 0; cc < 4; cc++) vv[cc] = stage[j * 65 + tc + 16 * cc];
#pragma unroll
            for (int r = 0; r < 4; r++)
#pragma unroll
                for (int cc = 0; cc < 4; cc++)
                    acc2[r][cc] += a[r] * vv[cc];
        }
#pragma unroll
        for (int r = 0; r < 4; r++)
#pragma unroll
            for (int cc = 0; cc < 4; cc++)
                virt[((size_t)(i0 + ti * 4 + r) * C_ + c0 + tc + 16 * cc) * THW_ + s] = acc2[r][cc];
        __syncthreads();
    }
}

// ---------------- GroupNorm(1 group) + affine + ReLU + fp16 split-pack ----------------
__global__ __launch_bounds__(256)
void gn_relu_pack_kernel(const float* __restrict__ buf, const float* __restrict__ gamma,
                         const float* __restrict__ beta, uint32_t* __restrict__ vhi,
                         uint32_t* __restrict__ vlo)
{
    __shared__ double red[256];
    __shared__ double red2[256];
    const int n = blockIdx.x;
    const float* b = buf + (size_t)n * C_ * THW_;
    const int M = C_ * THW_;

    double s = 0.0, s2 = 0.0;
    for (int i = threadIdx.x; i < M; i += 256) {
        float v = b[i];
        s  += v;
        s2 += (double)v * v;
    }
    red[threadIdx.x]  = s;
    red2[threadIdx.x] = s2;
    __syncthreads();
    for (int off = 128; off > 0; off >>= 1) {
        if (threadIdx.x < off) {
            red[threadIdx.x]  += red[threadIdx.x + off];
            red2[threadIdx.x] += red2[threadIdx.x + off];
        }
        __syncthreads();
    }
    double mu_d  = red[0] / M;
    double var_d = red2[0] / M - mu_d * mu_d;
    float mu   = (float)mu_d;
    float rstd = rsqrtf((float)var_d + 1e-5f);

    for (int i = threadIdx.x; i < M / 2; i += 256) {
        int c2 = i >> 8, pos = i & 255;
        int c0 = 2 * c2;
        float v0 = (b[(size_t)c0 * THW_ + pos] - mu) * rstd * gamma[c0] + beta[c0];
        float v1 = (b[(size_t)(c0 + 1) * THW_ + pos] - mu) * rstd * gamma[c0 + 1] + beta[c0 + 1];
        v0 = fmaxf(v0, 0.f);
        v1 = fmaxf(v1, 0.f);
        uint32_t lo, hi = split_pack_h(v0, v1, lo);
        size_t o = ((size_t)n * 256 + c2) * 256 + pos;
        vhi[o] = hi;
        vlo[o] = lo;
    }
}

// ---------------------------------------------------------------------------
extern "C" void kernel_launch(void* const* d_in, const int* in_sizes, int n_in,
                              void* d_out, int out_size)
{
    const float* x   = (const float*)d_in[0];
    const int*   roi = (const int*)d_in[1];
    const float* Wq  = (const float*)d_in[2];
    const float* Wk  = (const float*)d_in[3];
    const float* Wv  = (const float*)d_in[4];
    const float* Wc  = (const float*)d_in[5];
    const float* gam = (const float*)d_in[6];
    const float* bet = (const float*)d_in[7];
    float* out = (float*)d_out;

    float *q, *k, *v, *virt;
    uint32_t *xhi, *xlo, *vhi, *vlo, *wgh;
    cudaGetSymbolAddress((void**)&q,    g_q);
    cudaGetSymbolAddress((void**)&k,    g_k);
    cudaGetSymbolAddress((void**)&v,    g_v);
    cudaGetSymbolAddress((void**)&virt, g_virt);
    cudaGetSymbolAddress((void**)&xhi,  g_xhi);
    cudaGetSymbolAddress((void**)&xlo,  g_xlo);
    cudaGetSymbolAddress((void**)&vhi,  g_vhi);
    cudaGetSymbolAddress((void**)&vlo,  g_vlo);
    cudaGetSymbolAddress((void**)&wgh,  g_wgh);
    const size_t WS = (size_t)K2TOT * C_;

    cudaFuncSetAttribute(conv_mma_kernel, cudaFuncAttributeMaxDynamicSharedMemorySize,
                         CONV_SMEM);
    cudaFuncSetAttribute(attn_kernel, cudaFuncAttributeMaxDynamicSharedMemorySize,
                         SM_FLOATS * (int)sizeof(float));

    // prepasses
    xsplit_kernel<<<HPAIR / 256, 256>>>(x, xhi, xlo);
    wsplit_kernel<<<K2TOT, 512>>>(Wq, wgh + 0 * WS);
    wsplit_kernel<<<K2TOT, 512>>>(Wk, wgh + 1 * WS);
    wsplit_kernel<<<K2TOT, 512>>>(Wv, wgh + 2 * WS);
    wsplit_kernel<<<K2TOT, 512>>>(Wc, wgh + 3 * WS);

    // q, k, v convs (transposed outputs)
    dim3 cgrid(256, 4, 2);
    conv_mma_kernel<<<cgrid, 256, CONV_SMEM>>>(xhi, xlo, wgh + 0 * WS, nullptr, q, 1);
    conv_mma_kernel<<<cgrid, 256, CONV_SMEM>>>(xhi, xlo, wgh + 1 * WS, nullptr, k, 1);
    conv_mma_kernel<<<cgrid, 256, CONV_SMEM>>>(xhi, xlo, wgh + 2 * WS, nullptr, v, 1);

    attn_kernel<<<dim3(4, 256), 256, SM_FLOATS * sizeof(float)>>>(q, k, v, roi, virt);

    gn_relu_pack_kernel<<<256, 256>>>(virt, gam, bet, vhi, vlo);

    conv_mma_kernel<<<cgrid, 256, CONV_SMEM>>>(vhi, vlo, wgh + 3 * WS, x, out, 0);
}

// round 10
// speedup vs baseline: 7.1069x; 1.2449x over previous
#include <cuda_runtime.h>
#include <cuda_fp16.h>
#include <math.h>
#include <stdint.h>

#define N_    256
#define C_    512
#define T_    4
#define HW_   64
#define THW_  256
#define ELEMS (N_ * C_ * THW_)
#define K2TOT 2304               // 512ci/2 * 9 taps
#define HPAIR (ELEMS / 2)

__device__ float    g_virt[ELEMS];   // [s][n][c]
__device__ __half   g_qh[ELEMS];     // [s][n][c]
__device__ __half   g_ql[ELEMS];
__device__ __half   g_kh[ELEMS];
__device__ __half   g_kl[ELEMS];
__device__ __half   g_vth[ELEMS];    // [s][c][n]
__device__ uint32_t g_xhi[HPAIR];    // packed fp16x2 [n][ci2][thw]
__device__ uint32_t g_xlo[HPAIR];
__device__ uint32_t g_vhi[HPAIR];
__device__ uint32_t g_vlo[HPAIR];
__device__ uint32_t g_wgh[4][K2TOT * C_];   // fp16x2 weights [chunk(32)][k2l(72)][co(512)]

// ---------------- helpers ----------------
__device__ __forceinline__ uint32_t smem_u32(const void* p) {
    uint32_t a;
    asm("{ .reg .u64 t; cvta.to.shared.u64 t, %1; cvt.u32.u64 %0, t; }" : "=r"(a) : "l"(p));
    return a;
}
__device__ __forceinline__ void mma_f16(float* d, const uint32_t* a, const uint32_t* b) {
    asm volatile(
        "mma.sync.aligned.m16n8k16.row.col.f32.f16.f16.f32 "
        "{%0,%1,%2,%3}, {%4,%5,%6,%7}, {%8,%9}, {%0,%1,%2,%3};"
        : "+f"(d[0]), "+f"(d[1]), "+f"(d[2]), "+f"(d[3])
        : "r"(a[0]), "r"(a[1]), "r"(a[2]), "r"(a[3]), "r"(b[0]), "r"(b[1]));
}
__device__ __forceinline__ uint32_t split_pack_h(float v0, float v1, uint32_t& lo) {
    __half2 h = __floats2half2_rn(v0, v1);
    float r0 = v0 - __half2float(__low2half(h));
    float r1 = v1 - __half2float(__high2half(h));
    __half2 l = __floats2half2_rn(r0, r1);
    lo = *(uint32_t*)&l;
    return *(uint32_t*)&h;
}
__device__ __forceinline__ void cpa16(uint32_t dst, const void* src) {
    asm volatile("cp.async.cg.shared.global [%0], [%1], 16;" :: "r"(dst), "l"(src));
}
__device__ __forceinline__ void cpa4(uint32_t dst, const void* src) {
    asm volatile("cp.async.ca.shared.global [%0], [%1], 4;" :: "r"(dst), "l"(src));
}

// ---------------- prepass: split x into packed fp16x2 hi/lo ----------------
__global__ void xsplit_kernel(const float* __restrict__ src, uint32_t* __restrict__ hi,
                              uint32_t* __restrict__ lo) {
    int idx = blockIdx.x * 256 + threadIdx.x;     // < HPAIR
    int n   = idx >> 16;
    int r   = idx & 65535;
    int ci2 = r >> 8, pos = r & 255;
    size_t base = ((size_t)n * C_ + 2 * ci2) * THW_ + pos;
    uint32_t l, h = split_pack_h(src[base], src[base + THW_], l);
    hi[idx] = h;
    lo[idx] = l;
}

// ---------------- prepass: weights -> k-major fp16x2 ----------------
__global__ void wsplit_kernel(const float* __restrict__ W, uint32_t* __restrict__ Wh) {
    int k2g = blockIdx.x;                       // 0..2303
    int co  = threadIdx.x;                      // block 512
    int chunk = k2g / 72;
    int k2l   = k2g - chunk * 72;
    int tap   = k2l >> 3;
    int ci    = chunk * 16 + (k2l & 7) * 2;
    float v0 = W[((size_t)co * 512 + ci) * 9 + tap];
    float v1 = W[((size_t)co * 512 + ci + 1) * 9 + tap];
    __half2 h = __floats2half2_rn(v0, v1);
    Wh[(size_t)k2g * 512 + co] = *(uint32_t*)&h;
}

// ---------------- conv: fp16 2-term mma.sync, cp.async double-buffered ----------------
#define SA_A 136
#define SA_B 200
#define BUF_U32 12992           // A 9792 | Bh 1600 | Bl 1600
#define BH_OFF  9792
#define BL_OFF  11392
#define CONV_SMEM (2 * BUF_U32 * 4)   // 103936 bytes

__device__ __forceinline__ void stage_async(
    uint32_t bufb, const uint32_t* __restrict__ wh, const uint32_t* __restrict__ xhi,
    const uint32_t* __restrict__ xlo, int n, int co0, int t0, int cc, int tid)
{
    const uint32_t* wsrc = wh + (size_t)cc * 72 * 512 + co0;
#pragma unroll
    for (int r = 0; r < 9; r++) {
        int i   = tid + 256 * r;
        int row = i >> 5;
        int c4  = (i & 31) << 2;
        cpa16(bufb + (uint32_t)(row * SA_A + c4) * 4, wsrc + (size_t)row * 512 + c4);
    }
#pragma unroll
    for (int r = 0; r < 4; r++) {
        int i  = tid + 256 * r;
        int j  = i >> 7;
        int t  = (i >> 6) & 1;
        int hw = i & 63;
        int h  = hw >> 3, w = hw & 7;
        size_t src = ((size_t)n * 256 + cc * 8 + j) * 256 + (size_t)(t0 + t) * 64 + hw;
        uint32_t d = bufb + (uint32_t)(BH_OFF + j * SA_B + t * 100 + (h + 1) * 10 + (w + 1)) * 4;
        cpa4(d, xhi + src);
        cpa4(d + 1600 * 4, xlo + src);
    }
}

// mode: 0 = fp32 + residual (out);  1 = q/k: __half hi/lo [s][n][c];  2 = v: __half hi [s][c][n]
__global__ __launch_bounds__(256, 2)
void conv_mma_kernel(const uint32_t* __restrict__ xhi, const uint32_t* __restrict__ xlo,
                     const uint32_t* __restrict__ wh, const float* __restrict__ res,
                     float* __restrict__ out, __half* __restrict__ oh,
                     __half* __restrict__ ol, int mode)
{
    extern __shared__ uint32_t smu[];
    const uint32_t smb = smem_u32(smu);

    const int tid = threadIdx.x;
    const int wid = tid >> 5, lid = tid & 31;
    const int n   = blockIdx.x;
    const int co0 = blockIdx.y * 128;
    const int s0  = blockIdx.z * 128;
    const int t0  = blockIdx.z * 2;
    const int wm  = wid & 1, wn = wid >> 1;
    const int g   = lid >> 2, tg = lid & 3;

    for (int i = tid; i < 6400; i += 256) {
        int buf = i / 3200, off = i - buf * 3200;
        smu[buf * BUF_U32 + BH_OFF + off] = 0;
    }
    __syncthreads();

    int tcb[4];
#pragma unroll
    for (int ni = 0; ni < 4; ni++) {
        int col = wn * 32 + ni * 8 + g;
        tcb[ni] = (col >> 6) * 100 + ((col >> 3) & 7) * 10 + (col & 7);
    }

    float acc[4][4][4];
#pragma unroll
    for (int mi = 0; mi < 4; mi++)
#pragma unroll
        for (int ni = 0; ni < 4; ni++)
#pragma unroll
            for (int r = 0; r < 4; r++) acc[mi][ni][r] = 0.f;

    stage_async(smb, wh, xhi, xlo, n, co0, t0, 0, tid);
    asm volatile("cp.async.commit_group;" ::: "memory");

    for (int cc = 0; cc < 32; ++cc) {
        if (cc + 1 < 32) {
            stage_async(smb + ((cc + 1) & 1) * (BUF_U32 * 4), wh, xhi, xlo,
                        n, co0, t0, cc + 1, tid);
            asm volatile("cp.async.commit_group;" ::: "memory");
            asm volatile("cp.async.wait_group 1;" ::: "memory");
        } else {
            asm volatile("cp.async.wait_group 0;" ::: "memory");
        }
        __syncthreads();

        const uint32_t* Ah = smu + (cc & 1) * BUF_U32;
        const uint32_t* Bh = Ah + BH_OFF;
        const uint32_t* Bl = Ah + BL_OFF;

#pragma unroll
        for (int tap = 0; tap < 9; tap++) {
            const int sh = (tap / 3) * 10 + (tap % 3);
            const int ka = tap * 8;

            uint32_t fa[4][4], fbh[4][2], fbl[4][2];
            int bb = tg * SA_B + sh;
#pragma unroll
            for (int ni = 0; ni < 4; ni++) {
                int b0 = bb + tcb[ni];
                fbh[ni][0] = Bh[b0];
                fbh[ni][1] = Bh[b0 + 4 * SA_B];
                fbl[ni][0] = Bl[b0];
                fbl[ni][1] = Bl[b0 + 4 * SA_B];
            }
#pragma unroll
            for (int mi = 0; mi < 4; mi++) {
                int a0 = (ka + tg) * SA_A + wm * 64 + mi * 16 + g;
                fa[mi][0] = Ah[a0];
                fa[mi][1] = Ah[a0 + 8];
                fa[mi][2] = Ah[a0 + 4 * SA_A];
                fa[mi][3] = Ah[a0 + 4 * SA_A + 8];
            }
#pragma unroll
            for (int mi = 0; mi < 4; mi++)
#pragma unroll
                for (int ni = 0; ni < 4; ni++)
                    mma_f16(acc[mi][ni], fa[mi], fbh[ni]);
#pragma unroll
            for (int mi = 0; mi < 4; mi++)
#pragma unroll
                for (int ni = 0; ni < 4; ni++)
                    mma_f16(acc[mi][ni], fa[mi], fbl[ni]);
        }
        __syncthreads();
    }

#pragma unroll
    for (int mi = 0; mi < 4; mi++) {
        const int row = co0 + wm * 64 + mi * 16 + g;
#pragma unroll
        for (int ni = 0; ni < 4; ni++) {
            const int colb = s0 + wn * 32 + ni * 8 + 2 * tg;
#pragma unroll
            for (int r = 0; r < 4; r++) {
                const int rr  = row + (r >= 2 ? 8 : 0);
                const int cc2 = colb + (r & 1);
                float v = acc[mi][ni][r];
                if (mode == 0) {
                    size_t o = ((size_t)n * C_ + rr) * THW_ + cc2;
                    out[o] = v + res[o];
                } else {
                    __half h = __float2half_rn(v);
                    if (mode == 1) {
                        size_t o = ((size_t)cc2 * N_ + n) * C_ + rr;
                        oh[o] = h;
                        ol[o] = __float2half_rn(v - __half2float(h));
                    } else {
                        oh[((size_t)cc2 * C_ + rr) * N_ + n] = h;
                    }
                }
            }
        }
    }
}

// ---------------- attention: fp16 mma, register softmax ----------------
// grid (4 i-tiles, 256 s), block 256.  smem (u32): A[64][136]=8704 | stage 16896 | rois 256 | red 256
#define AT_SMEM_U32 26112
#define AT_ST 8704

__global__ __launch_bounds__(256, 2)
void attn_mma_kernel(const __half* __restrict__ qh, const __half* __restrict__ ql,
                     const __half* __restrict__ kh, const __half* __restrict__ kl,
                     const __half* __restrict__ vt, const int* __restrict__ roi,
                     float* __restrict__ virt)
{
    extern __shared__ uint32_t smu[];
    uint32_t* A  = smu;                       // [64][136]
    int* rois    = (int*)(smu + 25600);
    float* red   = (float*)(smu + 25856);
    const uint32_t smb = smem_u32(smu);
    const uint32_t stb = smb + AT_ST * 4;

    const int tid = threadIdx.x, wid = tid >> 5, lid = tid & 31;
    const int g = lid >> 2, tg = lid & 3;
    const int s = blockIdx.y, i0 = blockIdx.x * 64;
    const int wm = wid & 1, wn = wid >> 1;

    rois[tid] = roi[tid];

    float acc[2][8][4];
#pragma unroll
    for (int mi = 0; mi < 2; mi++)
#pragma unroll
        for (int ni = 0; ni < 8; ni++)
#pragma unroll
            for (int r = 0; r < 4; r++) acc[mi][ni][r] = 0.f;

    // ---- GEMM1: S = Q K^T over c, 16 chunks of 32 ----
    for (int ch = 0; ch < 16; ch++) {
        __syncthreads();
#pragma unroll
        for (int r = 0; r < 2; r++) {
            int i = tid + 256 * r;            // 0..511 (Q hi then lo)
            int arr = i >> 8, rem = i & 255;
            int row = rem >> 2, t = rem & 3;
            const __half* src = (arr ? ql : qh) + ((size_t)s * 256 + i0 + row) * 512 + ch * 32 + t * 8;
            cpa16(stb + (uint32_t)(arr * 1280 + row * 20 + t * 4) * 4, src);
        }
#pragma unroll
        for (int r = 0; r < 8; r++) {
            int i = tid + 256 * r;            // 0..2047 (K hi then lo)
            int arr = i >> 10, rem = i & 1023;
            int row = rem >> 2, t = rem & 3;
            const __half* src = (arr ? kl : kh) + ((size_t)s * 256 + row) * 512 + ch * 32 + t * 8;
            cpa16(stb + (uint32_t)(2560 + arr * 5120 + row * 20 + t * 4) * 4, src);
        }
        asm volatile("cp.async.commit_group;" ::: "memory");
        asm volatile("cp.async.wait_group 0;" ::: "memory");
        __syncthreads();

        const uint32_t* Qh = smu + AT_ST;
        const uint32_t* Ql = Qh + 1280;
        const uint32_t* Kh = Qh + 2560;
        const uint32_t* Kl = Qh + 7680;
#pragma unroll
        for (int ks = 0; ks < 2; ks++) {
            const int kb = ks * 8;
            uint32_t ah[2][4], al[2][4], b[8][2];
#pragma unroll
            for (int mi = 0; mi < 2; mi++) {
                int a0 = (wm * 32 + mi * 16 + g) * 20 + kb + tg;
                ah[mi][0] = Qh[a0]; ah[mi][1] = Qh[a0 + 160];
                ah[mi][2] = Qh[a0 + 4]; ah[mi][3] = Qh[a0 + 164];
                al[mi][0] = Ql[a0]; al[mi][1] = Ql[a0 + 160];
                al[mi][2] = Ql[a0 + 4]; al[mi][3] = Ql[a0 + 164];
            }
#pragma unroll
            for (int ni = 0; ni < 8; ni++) {
                int b0 = (wn * 64 + ni * 8 + g) * 20 + kb + tg;
                b[ni][0] = Kh[b0]; b[ni][1] = Kh[b0 + 4];
            }
#pragma unroll
            for (int mi = 0; mi < 2; mi++)
#pragma unroll
                for (int ni = 0; ni < 8; ni++) {
                    mma_f16(acc[mi][ni], ah[mi], b[ni]);
                    mma_f16(acc[mi][ni], al[mi], b[ni]);
                }
#pragma unroll
            for (int ni = 0; ni < 8; ni++) {
                int b0 = (wn * 64 + ni * 8 + g) * 20 + kb + tg;
                b[ni][0] = Kl[b0]; b[ni][1] = Kl[b0 + 4];
            }
#pragma unroll
            for (int mi = 0; mi < 2; mi++)
#pragma unroll
                for (int ni = 0; ni < 8; ni++)
                    mma_f16(acc[mi][ni], ah[mi], b[ni]);
        }
    }

    // ---- mask + softmax in registers ----
    const float scale = 0.044194173824159216f;   // 1/sqrt(512)
    int rro[2][2], cro[8][2];
#pragma unroll
    for (int mi = 0; mi < 2; mi++)
#pragma unroll
        for (int h = 0; h < 2; h++)
            rro[mi][h] = rois[i0 + wm * 32 + mi * 16 + g + 8 * h];
#pragma unroll
    for (int ni = 0; ni < 8; ni++)
#pragma unroll
        for (int c = 0; c < 2; c++)
            cro[ni][c] = rois[wn * 64 + ni * 8 + 2 * tg + c];
#pragma unroll
    for (int mi = 0; mi < 2; mi++)
#pragma unroll
        for (int ni = 0; ni < 8; ni++)
#pragma unroll
            for (int r = 0; r < 4; r++) {
                float v = acc[mi][ni][r] * scale;
                acc[mi][ni][r] = (cro[ni][r & 1] == rro[mi][r >> 1]) ? v : -1e30f;
            }

    float mx[2][2] = {{-1e30f, -1e30f}, {-1e30f, -1e30f}};
#pragma unroll
    for (int mi = 0; mi < 2; mi++)
#pragma unroll
        for (int ni = 0; ni < 8; ni++)
#pragma unroll
            for (int r = 0; r < 4; r++)
                mx[mi][r >> 1] = fmaxf(mx[mi][r >> 1], acc[mi][ni][r]);
#pragma unroll
    for (int mi = 0; mi < 2; mi++)
#pragma unroll
        for (int h = 0; h < 2; h++) {
            mx[mi][h] = fmaxf(mx[mi][h], __shfl_xor_sync(0xffffffffu, mx[mi][h], 1));
            mx[mi][h] = fmaxf(mx[mi][h], __shfl_xor_sync(0xffffffffu, mx[mi][h], 2));
        }
    if (tg == 0)
#pragma unroll
        for (int mi = 0; mi < 2; mi++)
#pragma unroll
            for (int h = 0; h < 2; h++)
                red[wn * 64 + wm * 32 + mi * 16 + g + 8 * h] = mx[mi][h];
    __syncthreads();
#pragma unroll
    for (int mi = 0; mi < 2; mi++)
#pragma unroll
        for (int h = 0; h < 2; h++) {
            int row = wm * 32 + mi * 16 + g + 8 * h;
            mx[mi][h] = fmaxf(fmaxf(red[row], red[64 + row]),
                              fmaxf(red[128 + row], red[192 + row]));
        }
    __syncthreads();

    float sm[2][2] = {{0.f, 0.f}, {0.f, 0.f}};
#pragma unroll
    for (int mi = 0; mi < 2; mi++)
#pragma unroll
        for (int ni = 0; ni < 8; ni++)
#pragma unroll
            for (int r = 0; r < 4; r++) {
                float e = __expf(acc[mi][ni][r] - mx[mi][r >> 1]);
                acc[mi][ni][r] = e;
                sm[mi][r >> 1] += e;
            }
#pragma unroll
    for (int mi = 0; mi < 2; mi++)
#pragma unroll
        for (int h = 0; h < 2; h++) {
            sm[mi][h] += __shfl_xor_sync(0xffffffffu, sm[mi][h], 1);
            sm[mi][h] += __shfl_xor_sync(0xffffffffu, sm[mi][h], 2);
        }
    if (tg == 0)
#pragma unroll
        for (int mi = 0; mi < 2; mi++)
#pragma unroll
            for (int h = 0; h < 2; h++)
                red[wn * 64 + wm * 32 + mi * 16 + g + 8 * h] = sm[mi][h];
    __syncthreads();
#pragma unroll
    for (int mi = 0; mi < 2; mi++)
#pragma unroll
        for (int h = 0; h < 2; h++) {
            int row = wm * 32 + mi * 16 + g + 8 * h;
            float tot = red[row] + red[64 + row] + red[128 + row] + red[192 + row];
            sm[mi][h] = 1.f / tot;
        }

    // pack probabilities into A[row][j2] (fp16x2 pairs along j)
#pragma unroll
    for (int mi = 0; mi < 2; mi++)
#pragma unroll
        for (int ni = 0; ni < 8; ni++)
#pragma unroll
            for (int h = 0; h < 2; h++) {
                __half2 p = __floats2half2_rn(acc[mi][ni][2 * h] * sm[mi][h],
                                              acc[mi][ni][2 * h + 1] * sm[mi][h]);
                int row = wm * 32 + mi * 16 + g + 8 * h;
                A[row * 136 + wn * 32 + ni * 4 + tg] = *(uint32_t*)&p;
            }
    __syncthreads();

    // ---- GEMM2: virt^T[c][i] = V^T A^T, 8 chunks of 64 c, double-buffered ----
#pragma unroll
    for (int r = 0; r < 8; r++) {
        int i = tid + 256 * r;
        int row = i >> 5, t = i & 31;
        const __half* src = vt + ((size_t)s * 512 + row) * 256 + t * 8;
        cpa16(stb + (uint32_t)(row * 132 + t * 4) * 4, src);
    }
    asm volatile("cp.async.commit_group;" ::: "memory");

    for (int mc = 0; mc < 8; mc++) {
        if (mc + 1 < 8) {
#pragma unroll
            for (int r = 0; r < 8; r++) {
                int i = tid + 256 * r;
                int row = i >> 5, t = i & 31;
                const __half* src = vt + ((size_t)s * 512 + (mc + 1) * 64 + row) * 256 + t * 8;
                cpa16(stb + (uint32_t)(((mc + 1) & 1) * 8448 + row * 132 + t * 4) * 4, src);
            }
            asm volatile("cp.async.commit_group;" ::: "memory");
            asm volatile("cp.async.wait_group 1;" ::: "memory");
        } else {
            asm volatile("cp.async.wait_group 0;" ::: "memory");
        }
        __syncthreads();

        const uint32_t* Vt = smu + AT_ST + (mc & 1) * 8448;
        float acc2[4][4];
#pragma unroll
        for (int mt = 0; mt < 4; mt++)
#pragma unroll
            for (int r = 0; r < 4; r++) acc2[mt][r] = 0.f;

#pragma unroll
        for (int ks = 0; ks < 16; ks++) {
            uint32_t b2[2], a2[4][4];
            int bb = (wid * 8 + g) * 136 + ks * 8 + tg;
            b2[0] = A[bb]; b2[1] = A[bb + 4];
#pragma unroll
            for (int mt = 0; mt < 4; mt++) {
                int a0 = (mt * 16 + g) * 132 + ks * 8 + tg;
                a2[mt][0] = Vt[a0]; a2[mt][1] = Vt[a0 + 8 * 132];
                a2[mt][2] = Vt[a0 + 4]; a2[mt][3] = Vt[a0 + 8 * 132 + 4];
            }
#pragma unroll
            for (int mt = 0; mt < 4; mt++) mma_f16(acc2[mt], a2[mt], b2);
        }
#pragma unroll
        for (int mt = 0; mt < 4; mt++)
#pragma unroll
            for (int r = 0; r < 4; r++) {
                int c  = mc * 64 + mt * 16 + g + 8 * (r >> 1);
                int ig = i0 + wid * 8 + 2 * tg + (r & 1);
                virt[((size_t)s * 256 + ig) * 512 + c] = acc2[mt][r];
            }
        __syncthreads();
    }
}

// ---------------- GroupNorm + affine + ReLU + fp16 split-pack ----------------
// virt layout [s][n][c]; output vhi/vlo packed u32 [n][c2][s]
__global__ __launch_bounds__(256)
void gn_relu_pack_kernel(const float* __restrict__ buf, const float* __restrict__ gamma,
                         const float* __restrict__ beta, uint32_t* __restrict__ vhi,
                         uint32_t* __restrict__ vlo)
{
    __shared__ double red[256];
    __shared__ double red2[256];
    const int n = blockIdx.x;
    const int M = C_ * THW_;   // 131072

    double s = 0.0, s2 = 0.0;
    for (int i = threadIdx.x; i < M; i += 256) {
        int ss = i >> 9, c = i & 511;
        float v = buf[((size_t)ss * 256 + n) * 512 + c];
        s  += v;
        s2 += (double)v * v;
    }
    red[threadIdx.x]  = s;
    red2[threadIdx.x] = s2;
    __syncthreads();
    for (int off = 128; off > 0; off >>= 1) {
        if (threadIdx.x < off) {
            red[threadIdx.x]  += red[threadIdx.x + off];
            red2[threadIdx.x] += red2[threadIdx.x + off];
        }
        __syncthreads();
    }
    double mu_d  = red[0] / M;
    double var_d = red2[0] / M - mu_d * mu_d;
    float mu   = (float)mu_d;
    float rstd = rsqrtf((float)var_d + 1e-5f);

    for (int i = threadIdx.x; i < M / 2; i += 256) {
        int c2 = i & 255, ss = i >> 8;
        int c0 = 2 * c2;
        size_t src = ((size_t)ss * 256 + n) * 512 + c0;
        float v0 = (buf[src]     - mu) * rstd * gamma[c0]     + beta[c0];
        float v1 = (buf[src + 1] - mu) * rstd * gamma[c0 + 1] + beta[c0 + 1];
        v0 = fmaxf(v0, 0.f);
        v1 = fmaxf(v1, 0.f);
        uint32_t lo, hi = split_pack_h(v0, v1, lo);
        size_t o = ((size_t)n * 256 + c2) * 256 + ss;
        vhi[o] = hi;
        vlo[o] = lo;
    }
}

// ---------------------------------------------------------------------------
extern "C" void kernel_launch(void* const* d_in, const int* in_sizes, int n_in,
                              void* d_out, int out_size)
{
    const float* x   = (const float*)d_in[0];
    const int*   roi = (const int*)d_in[1];
    const float* Wq  = (const float*)d_in[2];
    const float* Wk  = (const float*)d_in[3];
    const float* Wv  = (const float*)d_in[4];
    const float* Wc  = (const float*)d_in[5];
    const float* gam = (const float*)d_in[6];
    const float* bet = (const float*)d_in[7];
    float* out = (float*)d_out;

    float *virt;
    __half *qh, *ql, *kh, *kl, *vth;
    uint32_t *xhi, *xlo, *vhi, *vlo, *wgh;
    cudaGetSymbolAddress((void**)&virt, g_virt);
    cudaGetSymbolAddress((void**)&qh,   g_qh);
    cudaGetSymbolAddress((void**)&ql,   g_ql);
    cudaGetSymbolAddress((void**)&kh,   g_kh);
    cudaGetSymbolAddress((void**)&kl,   g_kl);
    cudaGetSymbolAddress((void**)&vth,  g_vth);
    cudaGetSymbolAddress((void**)&xhi,  g_xhi);
    cudaGetSymbolAddress((void**)&xlo,  g_xlo);
    cudaGetSymbolAddress((void**)&vhi,  g_vhi);
    cudaGetSymbolAddress((void**)&vlo,  g_vlo);
    cudaGetSymbolAddress((void**)&wgh,  g_wgh);
    const size_t WS = (size_t)K2TOT * C_;

    cudaFuncSetAttribute(conv_mma_kernel, cudaFuncAttributeMaxDynamicSharedMemorySize,
                         CONV_SMEM);
    cudaFuncSetAttribute(attn_mma_kernel, cudaFuncAttributeMaxDynamicSharedMemorySize,
                         AT_SMEM_U32 * 4);

    xsplit_kernel<<<HPAIR / 256, 256>>>(x, xhi, xlo);
    wsplit_kernel<<<K2TOT, 512>>>(Wq, wgh + 0 * WS);
    wsplit_kernel<<<K2TOT, 512>>>(Wk, wgh + 1 * WS);
    wsplit_kernel<<<K2TOT, 512>>>(Wv, wgh + 2 * WS);
    wsplit_kernel<<<K2TOT, 512>>>(Wc, wgh + 3 * WS);

    dim3 cgrid(256, 4, 2);
    conv_mma_kernel<<<cgrid, 256, CONV_SMEM>>>(xhi, xlo, wgh + 0 * WS, nullptr,
                                               nullptr, qh, ql, 1);
    conv_mma_kernel<<<cgrid, 256, CONV_SMEM>>>(xhi, xlo, wgh + 1 * WS, nullptr,
                                               nullptr, kh, kl, 1);
    conv_mma_kernel<<<cgrid, 256, CONV_SMEM>>>(xhi, xlo, wgh + 2 * WS, nullptr,
                                               nullptr, vth, nullptr, 2);

    attn_mma_kernel<<<dim3(4, 256), 256, AT_SMEM_U32 * 4>>>(qh, ql, kh, kl, vth, roi, virt);

    gn_relu_pack_kernel<<<256, 256>>>(virt, gam, bet, vhi, vlo);

    conv_mma_kernel<<<cgrid, 256, CONV_SMEM>>>(vhi, vlo, wgh + 3 * WS, x,
                                               out, nullptr, nullptr, 0);
}

// round 11
// speedup vs baseline: 11.1027x; 1.5622x over previous
#include <cuda_runtime.h>
#include <cuda_fp16.h>
#include <math.h>
#include <stdint.h>

#define N_    256
#define C_    512
#define T_    4
#define HW_   64
#define THW_  256
#define ELEMS (N_ * C_ * THW_)
#define K2TOT 2304               // 512ci/2 * 9 taps
#define HPAIR (ELEMS / 2)

__device__ float    g_virt[ELEMS];   // [s][n][c]
__device__ __half   g_qh[ELEMS];     // [s][n][c]
__device__ __half   g_ql[ELEMS];
__device__ __half   g_kh[ELEMS];
__device__ __half   g_kl[ELEMS];
__device__ __half   g_vth[ELEMS];    // [s][c][n]
__device__ uint32_t g_xhi[HPAIR];    // packed fp16x2 [n][ci2][thw]
__device__ uint32_t g_vhi[HPAIR];
__device__ uint32_t g_wgh[4][K2TOT * C_];   // fp16x2 weights [chunk(32)][k2l(72)][co(512)]

// ---------------- helpers ----------------
__device__ __forceinline__ uint32_t smem_u32(const void* p) {
    uint32_t a;
    asm("{ .reg .u64 t; cvta.to.shared.u64 t, %1; cvt.u32.u64 %0, t; }" : "=r"(a) : "l"(p));
    return a;
}
__device__ __forceinline__ void mma_f16(float* d, const uint32_t* a, const uint32_t* b) {
    asm volatile(
        "mma.sync.aligned.m16n8k16.row.col.f32.f16.f16.f32 "
        "{%0,%1,%2,%3}, {%4,%5,%6,%7}, {%8,%9}, {%0,%1,%2,%3};"
        : "+f"(d[0]), "+f"(d[1]), "+f"(d[2]), "+f"(d[3])
        : "r"(a[0]), "r"(a[1]), "r"(a[2]), "r"(a[3]), "r"(b[0]), "r"(b[1]));
}
__device__ __forceinline__ uint32_t split_pack_h(float v0, float v1, uint32_t& lo) {
    __half2 h = __floats2half2_rn(v0, v1);
    float r0 = v0 - __half2float(__low2half(h));
    float r1 = v1 - __half2float(__high2half(h));
    __half2 l = __floats2half2_rn(r0, r1);
    lo = *(uint32_t*)&l;
    return *(uint32_t*)&h;
}
__device__ __forceinline__ void cpa16(uint32_t dst, const void* src) {
    asm volatile("cp.async.cg.shared.global [%0], [%1], 16;" :: "r"(dst), "l"(src));
}
__device__ __forceinline__ void cpa4(uint32_t dst, const void* src) {
    asm volatile("cp.async.ca.shared.global [%0], [%1], 4;" :: "r"(dst), "l"(src));
}

// ---------------- prepass: x -> packed fp16x2 (hi only) ----------------
__global__ void xsplit_kernel(const float* __restrict__ src, uint32_t* __restrict__ hi) {
    int idx = blockIdx.x * 256 + threadIdx.x;     // < HPAIR
    int n   = idx >> 16;
    int r   = idx & 65535;
    int ci2 = r >> 8, pos = r & 255;
    size_t base = ((size_t)n * C_ + 2 * ci2) * THW_ + pos;
    __half2 h = __floats2half2_rn(src[base], src[base + THW_]);
    hi[idx] = *(uint32_t*)&h;
}

// ---------------- prepass: weights -> k-major fp16x2 ----------------
__global__ void wsplit_kernel(const float* __restrict__ W, uint32_t* __restrict__ Wh) {
    int k2g = blockIdx.x;                       // 0..2303
    int co  = threadIdx.x;                      // block 512
    int chunk = k2g / 72;
    int k2l   = k2g - chunk * 72;
    int tap   = k2l >> 3;
    int ci    = chunk * 16 + (k2l & 7) * 2;
    float v0 = W[((size_t)co * 512 + ci) * 9 + tap];
    float v1 = W[((size_t)co * 512 + ci + 1) * 9 + tap];
    __half2 h = __floats2half2_rn(v0, v1);
    Wh[(size_t)k2g * 512 + co] = *(uint32_t*)&h;
}

// ---------------- conv: fp16 1-term mma.sync, cp.async double-buffered ----------------
#define SA_A 136
#define SA_B 200
#define BUF_U32 11392           // A 9792 | Bh 1600
#define BH_OFF  9792
#define CONV_SMEM (2 * BUF_U32 * 4)   // 91136 bytes

__device__ __forceinline__ void stage_async(
    uint32_t bufb, const uint32_t* __restrict__ wh, const uint32_t* __restrict__ xhi,
    int n, int co0, int t0, int cc, int tid)
{
    const uint32_t* wsrc = wh + (size_t)cc * 72 * 512 + co0;
#pragma unroll
    for (int r = 0; r < 9; r++) {
        int i   = tid + 256 * r;
        int row = i >> 5;
        int c4  = (i & 31) << 2;
        cpa16(bufb + (uint32_t)(row * SA_A + c4) * 4, wsrc + (size_t)row * 512 + c4);
    }
#pragma unroll
    for (int r = 0; r < 4; r++) {
        int i  = tid + 256 * r;
        int j  = i >> 7;
        int t  = (i >> 6) & 1;
        int hw = i & 63;
        int h  = hw >> 3, w = hw & 7;
        size_t src = ((size_t)n * 256 + cc * 8 + j) * 256 + (size_t)(t0 + t) * 64 + hw;
        uint32_t d = bufb + (uint32_t)(BH_OFF + j * SA_B + t * 100 + (h + 1) * 10 + (w + 1)) * 4;
        cpa4(d, xhi + src);
    }
}

// mode: 0 = fp32 + residual (out);  1 = q/k: __half hi/lo [s][n][c];  2 = v: __half hi [s][c][n]
__global__ __launch_bounds__(256, 2)
void conv_mma_kernel(const uint32_t* __restrict__ xhi, const uint32_t* __restrict__ wh,
                     const float* __restrict__ res, float* __restrict__ out,
                     __half* __restrict__ oh, __half* __restrict__ ol, int mode)
{
    extern __shared__ uint32_t smu[];
    const uint32_t smb = smem_u32(smu);

    const int tid = threadIdx.x;
    const int wid = tid >> 5, lid = tid & 31;
    const int n   = blockIdx.x;
    const int co0 = blockIdx.y * 128;
    const int s0  = blockIdx.z * 128;
    const int t0  = blockIdx.z * 2;
    const int wm  = wid & 1, wn = wid >> 1;
    const int g   = lid >> 2, tg = lid & 3;

    for (int i = tid; i < 3200; i += 256) {
        int buf = i >> 11, off = i & 2047;   // 2 buffers x 1600 (pad loop to 2048 safe)
        if (off < 1600) smu[buf * BUF_U32 + BH_OFF + off] = 0;
    }
    // cover remaining 1600-2047 region of buffer0 mapping: simpler full loop
    for (int i = tid; i < 1600; i += 256) smu[BUF_U32 + BH_OFF + i] = 0;
    for (int i = tid; i < 1600; i += 256) smu[BH_OFF + i] = 0;
    __syncthreads();

    int tcb[4];
#pragma unroll
    for (int ni = 0; ni < 4; ni++) {
        int col = wn * 32 + ni * 8 + g;
        tcb[ni] = (col >> 6) * 100 + ((col >> 3) & 7) * 10 + (col & 7);
    }

    float acc[4][4][4];
#pragma unroll
    for (int mi = 0; mi < 4; mi++)
#pragma unroll
        for (int ni = 0; ni < 4; ni++)
#pragma unroll
            for (int r = 0; r < 4; r++) acc[mi][ni][r] = 0.f;

    stage_async(smb, wh, xhi, n, co0, t0, 0, tid);
    asm volatile("cp.async.commit_group;" ::: "memory");

    for (int cc = 0; cc < 32; ++cc) {
        if (cc + 1 < 32) {
            stage_async(smb + ((cc + 1) & 1) * (BUF_U32 * 4), wh, xhi, n, co0, t0, cc + 1, tid);
            asm volatile("cp.async.commit_group;" ::: "memory");
            asm volatile("cp.async.wait_group 1;" ::: "memory");
        } else {
            asm volatile("cp.async.wait_group 0;" ::: "memory");
        }
        __syncthreads();

        const uint32_t* Ah = smu + (cc & 1) * BUF_U32;
        const uint32_t* Bh = Ah + BH_OFF;

#pragma unroll
        for (int tap = 0; tap < 9; tap++) {
            const int sh = (tap / 3) * 10 + (tap % 3);
            const int ka = tap * 8;

            uint32_t fa[4][4], fbh[4][2];
            int bb = tg * SA_B + sh;
#pragma unroll
            for (int ni = 0; ni < 4; ni++) {
                int b0 = bb + tcb[ni];
                fbh[ni][0] = Bh[b0];
                fbh[ni][1] = Bh[b0 + 4 * SA_B];
            }
#pragma unroll
            for (int mi = 0; mi < 4; mi++) {
                int a0 = (ka + tg) * SA_A + wm * 64 + mi * 16 + g;
                fa[mi][0] = Ah[a0];
                fa[mi][1] = Ah[a0 + 8];
                fa[mi][2] = Ah[a0 + 4 * SA_A];
                fa[mi][3] = Ah[a0 + 4 * SA_A + 8];
            }
#pragma unroll
            for (int mi = 0; mi < 4; mi++)
#pragma unroll
                for (int ni = 0; ni < 4; ni++)
                    mma_f16(acc[mi][ni], fa[mi], fbh[ni]);
        }
        __syncthreads();
    }

#pragma unroll
    for (int mi = 0; mi < 4; mi++) {
        const int row = co0 + wm * 64 + mi * 16 + g;
#pragma unroll
        for (int ni = 0; ni < 4; ni++) {
            const int colb = s0 + wn * 32 + ni * 8 + 2 * tg;
#pragma unroll
            for (int r = 0; r < 4; r++) {
                const int rr  = row + (r >= 2 ? 8 : 0);
                const int cc2 = colb + (r & 1);
                float v = acc[mi][ni][r];
                if (mode == 0) {
                    size_t o = ((size_t)n * C_ + rr) * THW_ + cc2;
                    out[o] = v + res[o];
                } else {
                    __half h = __float2half_rn(v);
                    if (mode == 1) {
                        size_t o = ((size_t)cc2 * N_ + n) * C_ + rr;
                        oh[o] = h;
                        ol[o] = __float2half_rn(v - __half2float(h));
                    } else {
                        oh[((size_t)cc2 * C_ + rr) * N_ + n] = h;
                    }
                }
            }
        }
    }
}

// ---------------- attention: fp16 mma, register softmax ----------------
#define AT_SMEM_U32 26112
#define AT_ST 8704

__global__ __launch_bounds__(256, 2)
void attn_mma_kernel(const __half* __restrict__ qh, const __half* __restrict__ ql,
                     const __half* __restrict__ kh, const __half* __restrict__ kl,
                     const __half* __restrict__ vt, const int* __restrict__ roi,
                     float* __restrict__ virt)
{
    extern __shared__ uint32_t smu[];
    uint32_t* A  = smu;                       // [64][136]
    int* rois    = (int*)(smu + 25600);
    float* red   = (float*)(smu + 25856);
    const uint32_t smb = smem_u32(smu);
    const uint32_t stb = smb + AT_ST * 4;

    const int tid = threadIdx.x, wid = tid >> 5, lid = tid & 31;
    const int g = lid >> 2, tg = lid & 3;
    const int s = blockIdx.y, i0 = blockIdx.x * 64;
    const int wm = wid & 1, wn = wid >> 1;

    rois[tid] = roi[tid];

    float acc[2][8][4];
#pragma unroll
    for (int mi = 0; mi < 2; mi++)
#pragma unroll
        for (int ni = 0; ni < 8; ni++)
#pragma unroll
            for (int r = 0; r < 4; r++) acc[mi][ni][r] = 0.f;

    for (int ch = 0; ch < 16; ch++) {
        __syncthreads();
#pragma unroll
        for (int r = 0; r < 2; r++) {
            int i = tid + 256 * r;
            int arr = i >> 8, rem = i & 255;
            int row = rem >> 2, t = rem & 3;
            const __half* src = (arr ? ql : qh) + ((size_t)s * 256 + i0 + row) * 512 + ch * 32 + t * 8;
            cpa16(stb + (uint32_t)(arr * 1280 + row * 20 + t * 4) * 4, src);
        }
#pragma unroll
        for (int r = 0; r < 8; r++) {
            int i = tid + 256 * r;
            int arr = i >> 10, rem = i & 1023;
            int row = rem >> 2, t = rem & 3;
            const __half* src = (arr ? kl : kh) + ((size_t)s * 256 + row) * 512 + ch * 32 + t * 8;
            cpa16(stb + (uint32_t)(2560 + arr * 5120 + row * 20 + t * 4) * 4, src);
        }
        asm volatile("cp.async.commit_group;" ::: "memory");
        asm volatile("cp.async.wait_group 0;" ::: "memory");
        __syncthreads();

        const uint32_t* Qh = smu + AT_ST;
        const uint32_t* Ql = Qh + 1280;
        const uint32_t* Kh = Qh + 2560;
        const uint32_t* Kl = Qh + 7680;
#pragma unroll
        for (int ks = 0; ks < 2; ks++) {
            const int kb = ks * 8;
            uint32_t ah[2][4], al[2][4], b[8][2];
#pragma unroll
            for (int mi = 0; mi < 2; mi++) {
                int a0 = (wm * 32 + mi * 16 + g) * 20 + kb + tg;
                ah[mi][0] = Qh[a0]; ah[mi][1] = Qh[a0 + 160];
                ah[mi][2] = Qh[a0 + 4]; ah[mi][3] = Qh[a0 + 164];
                al[mi][0] = Ql[a0]; al[mi][1] = Ql[a0 + 160];
                al[mi][2] = Ql[a0 + 4]; al[mi][3] = Ql[a0 + 164];
            }
#pragma unroll
            for (int ni = 0; ni < 8; ni++) {
                int b0 = (wn * 64 + ni * 8 + g) * 20 + kb + tg;
                b[ni][0] = Kh[b0]; b[ni][1] = Kh[b0 + 4];
            }
#pragma unroll
            for (int mi = 0; mi < 2; mi++)
#pragma unroll
                for (int ni = 0; ni < 8; ni++) {
                    mma_f16(acc[mi][ni], ah[mi], b[ni]);
                    mma_f16(acc[mi][ni], al[mi], b[ni]);
                }
#pragma unroll
            for (int ni = 0; ni < 8; ni++) {
                int b0 = (wn * 64 + ni * 8 + g) * 20 + kb + tg;
                b[ni][0] = Kl[b0]; b[ni][1] = Kl[b0 + 4];
            }
#pragma unroll
            for (int mi = 0; mi < 2; mi++)
#pragma unroll
                for (int ni = 0; ni < 8; ni++)
                    mma_f16(acc[mi][ni], ah[mi], b[ni]);
        }
    }

    const float scale = 0.044194173824159216f;
    int rro[2][2], cro[8][2];
#pragma unroll
    for (int mi = 0; mi < 2; mi++)
#pragma unroll
        for (int h = 0; h < 2; h++)
            rro[mi][h] = rois[i0 + wm * 32 + mi * 16 + g + 8 * h];
#pragma unroll
    for (int ni = 0; ni < 8; ni++)
#pragma unroll
        for (int c = 0; c < 2; c++)
            cro[ni][c] = rois[wn * 64 + ni * 8 + 2 * tg + c];
#pragma unroll
    for (int mi = 0; mi < 2; mi++)
#pragma unroll
        for (int ni = 0; ni < 8; ni++)
#pragma unroll
            for (int r = 0; r < 4; r++) {
                float v = acc[mi][ni][r] * scale;
                acc[mi][ni][r] = (cro[ni][r & 1] == rro[mi][r >> 1]) ? v : -1e30f;
            }

    float mx[2][2] = {{-1e30f, -1e30f}, {-1e30f, -1e30f}};
#pragma unroll
    for (int mi = 0; mi < 2; mi++)
#pragma unroll
        for (int ni = 0; ni < 8; ni++)
#pragma unroll
            for (int r = 0; r < 4; r++)
                mx[mi][r >> 1] = fmaxf(mx[mi][r >> 1], acc[mi][ni][r]);
#pragma unroll
    for (int mi = 0; mi < 2; mi++)
#pragma unroll
        for (int h = 0; h < 2; h++) {
            mx[mi][h] = fmaxf(mx[mi][h], __shfl_xor_sync(0xffffffffu, mx[mi][h], 1));
            mx[mi][h] = fmaxf(mx[mi][h], __shfl_xor_sync(0xffffffffu, mx[mi][h], 2));
        }
    if (tg == 0)
#pragma unroll
        for (int mi = 0; mi < 2; mi++)
#pragma unroll
            for (int h = 0; h < 2; h++)
                red[wn * 64 + wm * 32 + mi * 16 + g + 8 * h] = mx[mi][h];
    __syncthreads();
#pragma unroll
    for (int mi = 0; mi < 2; mi++)
#pragma unroll
        for (int h = 0; h < 2; h++) {
            int row = wm * 32 + mi * 16 + g + 8 * h;
            mx[mi][h] = fmaxf(fmaxf(red[row], red[64 + row]),
                              fmaxf(red[128 + row], red[192 + row]));
        }
    __syncthreads();

    float sm[2][2] = {{0.f, 0.f}, {0.f, 0.f}};
#pragma unroll
    for (int mi = 0; mi < 2; mi++)
#pragma unroll
        for (int ni = 0; ni < 8; ni++)
#pragma unroll
            for (int r = 0; r < 4; r++) {
                float e = __expf(acc[mi][ni][r] - mx[mi][r >> 1]);
                acc[mi][ni][r] = e;
                sm[mi][r >> 1] += e;
            }
#pragma unroll
    for (int mi = 0; mi < 2; mi++)
#pragma unroll
        for (int h = 0; h < 2; h++) {
            sm[mi][h] += __shfl_xor_sync(0xffffffffu, sm[mi][h], 1);
            sm[mi][h] += __shfl_xor_sync(0xffffffffu, sm[mi][h], 2);
        }
    if (tg == 0)
#pragma unroll
        for (int mi = 0; mi < 2; mi++)
#pragma unroll
            for (int h = 0; h < 2; h++)
                red[wn * 64 + wm * 32 + mi * 16 + g + 8 * h] = sm[mi][h];
    __syncthreads();
#pragma unroll
    for (int mi = 0; mi < 2; mi++)
#pragma unroll
        for (int h = 0; h < 2; h++) {
            int row = wm * 32 + mi * 16 + g + 8 * h;
            float tot = red[row] + red[64 + row] + red[128 + row] + red[192 + row];
            sm[mi][h] = 1.f / tot;
        }

#pragma unroll
    for (int mi = 0; mi < 2; mi++)
#pragma unroll
        for (int ni = 0; ni < 8; ni++)
#pragma unroll
            for (int h = 0; h < 2; h++) {
                __half2 p = __floats2half2_rn(acc[mi][ni][2 * h] * sm[mi][h],
                                              acc[mi][ni][2 * h + 1] * sm[mi][h]);
                int row = wm * 32 + mi * 16 + g + 8 * h;
                A[row * 136 + wn * 32 + ni * 4 + tg] = *(uint32_t*)&p;
            }
    __syncthreads();

#pragma unroll
    for (int r = 0; r < 8; r++) {
        int i = tid + 256 * r;
        int row = i >> 5, t = i & 31;
        const __half* src = vt + ((size_t)s * 512 + row) * 256 + t * 8;
        cpa16(stb + (uint32_t)(row * 132 + t * 4) * 4, src);
    }
    asm volatile("cp.async.commit_group;" ::: "memory");

    for (int mc = 0; mc < 8; mc++) {
        if (mc + 1 < 8) {
#pragma unroll
            for (int r = 0; r < 8; r++) {
                int i = tid + 256 * r;
                int row = i >> 5, t = i & 31;
                const __half* src = vt + ((size_t)s * 512 + (mc + 1) * 64 + row) * 256 + t * 8;
                cpa16(stb + (uint32_t)(((mc + 1) & 1) * 8448 + row * 132 + t * 4) * 4, src);
            }
            asm volatile("cp.async.commit_group;" ::: "memory");
            asm volatile("cp.async.wait_group 1;" ::: "memory");
        } else {
            asm volatile("cp.async.wait_group 0;" ::: "memory");
        }
        __syncthreads();

        const uint32_t* Vt = smu + AT_ST + (mc & 1) * 8448;
        float acc2[4][4];
#pragma unroll
        for (int mt = 0; mt < 4; mt++)
#pragma unroll
            for (int r = 0; r < 4; r++) acc2[mt][r] = 0.f;

#pragma unroll
        for (int ks = 0; ks < 16; ks++) {
            uint32_t b2[2], a2[4][4];
            int bb = (wid * 8 + g) * 136 + ks * 8 + tg;
            b2[0] = A[bb]; b2[1] = A[bb + 4];
#pragma unroll
            for (int mt = 0; mt < 4; mt++) {
                int a0 = (mt * 16 + g) * 132 + ks * 8 + tg;
                a2[mt][0] = Vt[a0]; a2[mt][1] = Vt[a0 + 8 * 132];
                a2[mt][2] = Vt[a0 + 4]; a2[mt][3] = Vt[a0 + 8 * 132 + 4];
            }
#pragma unroll
            for (int mt = 0; mt < 4; mt++) mma_f16(acc2[mt], a2[mt], b2);
        }
#pragma unroll
        for (int mt = 0; mt < 4; mt++)
#pragma unroll
            for (int r = 0; r < 4; r++) {
                int c  = mc * 64 + mt * 16 + g + 8 * (r >> 1);
                int ig = i0 + wid * 8 + 2 * tg + (r & 1);
                virt[((size_t)s * 256 + ig) * 512 + c] = acc2[mt][r];
            }
        __syncthreads();
    }
}

// ---------------- GroupNorm + affine + ReLU + fp16 pack (hi only) ----------------
// virt layout [s][n][c]; output vhi packed u32 [n][c2][s]
__global__ __launch_bounds__(256)
void gn_relu_pack_kernel(const float* __restrict__ buf, const float* __restrict__ gamma,
                         const float* __restrict__ beta, uint32_t* __restrict__ vhi)
{
    __shared__ double red[256];
    __shared__ double red2[256];
    const int n = blockIdx.x;
    const int M = C_ * THW_;   // 131072

    double s = 0.0, s2 = 0.0;
    for (int i = threadIdx.x; i < M; i += 256) {
        int ss = i >> 9, c = i & 511;
        float v = buf[((size_t)ss * 256 + n) * 512 + c];
        s  += v;
        s2 += (double)v * v;
    }
    red[threadIdx.x]  = s;
    red2[threadIdx.x] = s2;
    __syncthreads();
    for (int off = 128; off > 0; off >>= 1) {
        if (threadIdx.x < off) {
            red[threadIdx.x]  += red[threadIdx.x + off];
            red2[threadIdx.x] += red2[threadIdx.x + off];
        }
        __syncthreads();
    }
    double mu_d  = red[0] / M;
    double var_d = red2[0] / M - mu_d * mu_d;
    float mu   = (float)mu_d;
    float rstd = rsqrtf((float)var_d + 1e-5f);

    for (int i = threadIdx.x; i < M / 2; i += 256) {
        int c2 = i & 255, ss = i >> 8;
        int c0 = 2 * c2;
        size_t src = ((size_t)ss * 256 + n) * 512 + c0;
        float v0 = (buf[src]     - mu) * rstd * gamma[c0]     + beta[c0];
        float v1 = (buf[src + 1] - mu) * rstd * gamma[c0 + 1] + beta[c0 + 1];
        v0 = fmaxf(v0, 0.f);
        v1 = fmaxf(v1, 0.f);
        __half2 h = __floats2half2_rn(v0, v1);
        vhi[((size_t)n * 256 + c2) * 256 + ss] = *(uint32_t*)&h;
    }
}

// ---------------------------------------------------------------------------
extern "C" void kernel_launch(void* const* d_in, const int* in_sizes, int n_in,
                              void* d_out, int out_size)
{
    const float* x   = (const float*)d_in[0];
    const int*   roi = (const int*)d_in[1];
    const float* Wq  = (const float*)d_in[2];
    const float* Wk  = (const float*)d_in[3];
    const float* Wv  = (const float*)d_in[4];
    const float* Wc  = (const float*)d_in[5];
    const float* gam = (const float*)d_in[6];
    const float* bet = (const float*)d_in[7];
    float* out = (float*)d_out;

    float *virt;
    __half *qh, *ql, *kh, *kl, *vth;
    uint32_t *xhi, *vhi, *wgh;
    cudaGetSymbolAddress((void**)&virt, g_virt);
    cudaGetSymbolAddress((void**)&qh,   g_qh);
    cudaGetSymbolAddress((void**)&ql,   g_ql);
    cudaGetSymbolAddress((void**)&kh,   g_kh);
    cudaGetSymbolAddress((void**)&kl,   g_kl);
    cudaGetSymbolAddress((void**)&vth,  g_vth);
    cudaGetSymbolAddress((void**)&xhi,  g_xhi);
    cudaGetSymbolAddress((void**)&vhi,  g_vhi);
    cudaGetSymbolAddress((void**)&wgh,  g_wgh);
    const size_t WS = (size_t)K2TOT * C_;

    cudaFuncSetAttribute(conv_mma_kernel, cudaFuncAttributeMaxDynamicSharedMemorySize,
                         CONV_SMEM);
    cudaFuncSetAttribute(attn_mma_kernel, cudaFuncAttributeMaxDynamicSharedMemorySize,
                         AT_SMEM_U32 * 4);

    xsplit_kernel<<<HPAIR / 256, 256>>>(x, xhi);
    wsplit_kernel<<<K2TOT, 512>>>(Wq, wgh + 0 * WS);
    wsplit_kernel<<<K2TOT, 512>>>(Wk, wgh + 1 * WS);
    wsplit_kernel<<<K2TOT, 512>>>(Wv, wgh + 2 * WS);
    wsplit_kernel<<<K2TOT, 512>>>(Wc, wgh + 3 * WS);

    dim3 cgrid(256, 4, 2);
    conv_mma_kernel<<<cgrid, 256, CONV_SMEM>>>(xhi, wgh + 0 * WS, nullptr,
                                               nullptr, qh, ql, 1);
    conv_mma_kernel<<<cgrid, 256, CONV_SMEM>>>(xhi, wgh + 1 * WS, nullptr,
                                               nullptr, kh, kl, 1);
    conv_mma_kernel<<<cgrid, 256, CONV_SMEM>>>(xhi, wgh + 2 * WS, nullptr,
                                               nullptr, vth, nullptr, 2);

    attn_mma_kernel<<<dim3(4, 256), 256, AT_SMEM_U32 * 4>>>(qh, ql, kh, kl, vth, roi, virt);

    gn_relu_pack_kernel<<<256, 256>>>(virt, gam, bet, vhi);

    conv_mma_kernel<<<cgrid, 256, CONV_SMEM>>>(vhi, wgh + 3 * WS, x,
                                               out, nullptr, nullptr, 0);
}

// round 12
// speedup vs baseline: 12.1319x; 1.0927x over previous
#include <cuda_runtime.h>
#include <cuda_fp16.h>
#include <math.h>
#include <stdint.h>

#define N_    256
#define C_    512
#define T_    4
#define HW_   64
#define THW_  256
#define ELEMS (N_ * C_ * THW_)
#define HPAIR (ELEMS / 2)
#define WU32  (2304 * 512)          // u32 per conv weight array

__device__ float    g_virt[ELEMS];   // [s][n][c]
__device__ __half   g_qh[ELEMS];     // [s][n][c]
__device__ __half   g_ql[ELEMS];
__device__ __half   g_kh[ELEMS];
__device__ __half   g_kl[ELEMS];
__device__ __half   g_vth[ELEMS];    // [s][c][n]
__device__ uint32_t g_xhi[HPAIR];    // packed fp16x2 [n][ci2][thw]
__device__ uint32_t g_vhi[HPAIR];
__device__ uint32_t g_wgh[4][WU32];  // frag-order: [coblk4][chunk32][tap9][m8][lane32] x uint4

// ---------------- helpers ----------------
__device__ __forceinline__ uint32_t smem_u32(const void* p) {
    uint32_t a;
    asm("{ .reg .u64 t; cvta.to.shared.u64 t, %1; cvt.u32.u64 %0, t; }" : "=r"(a) : "l"(p));
    return a;
}
__device__ __forceinline__ void mma_f16(float* d, const uint32_t* a, const uint32_t* b) {
    asm volatile(
        "mma.sync.aligned.m16n8k16.row.col.f32.f16.f16.f32 "
        "{%0,%1,%2,%3}, {%4,%5,%6,%7}, {%8,%9}, {%0,%1,%2,%3};"
        : "+f"(d[0]), "+f"(d[1]), "+f"(d[2]), "+f"(d[3])
        : "r"(a[0]), "r"(a[1]), "r"(a[2]), "r"(a[3]), "r"(b[0]), "r"(b[1]));
}
__device__ __forceinline__ void cpa16(uint32_t dst, const void* src) {
    asm volatile("cp.async.cg.shared.global [%0], [%1], 16;" :: "r"(dst), "l"(src));
}
__device__ __forceinline__ void cpa4(uint32_t dst, const void* src) {
    asm volatile("cp.async.ca.shared.global [%0], [%1], 4;" :: "r"(dst), "l"(src));
}

// ---------------- prepass: x -> packed fp16x2 (hi only) ----------------
__global__ void xsplit_kernel(const float* __restrict__ src, uint32_t* __restrict__ hi) {
    int idx = blockIdx.x * 256 + threadIdx.x;     // < HPAIR
    int n   = idx >> 16;
    int r   = idx & 65535;
    int ci2 = r >> 8, pos = r & 255;
    size_t base = ((size_t)n * C_ + 2 * ci2) * THW_ + pos;
    __half2 h = __floats2half2_rn(src[base], src[base + THW_]);
    hi[idx] = *(uint32_t*)&h;
}

// ---------------- prepass: weights -> fragment-order uint4 layout ----------------
// grid 1152 = 4 coblk * 32 chunk * 9 tap; block 256 = 8 m * 32 lane.
__global__ void wsplit_kernel(const float* __restrict__ W, uint4* __restrict__ W4) {
    const int bid = blockIdx.x;
    const int tap = bid % 9;
    const int cb  = bid / 9;
    const int chunk = cb & 31;
    const int coblk = cb >> 5;
    const int tid  = threadIdx.x;
    const int m    = tid >> 5;
    const int lane = tid & 31;
    const int g    = lane >> 2, tg = lane & 3;

    const int ci0a = chunk * 16 + tg * 2;
    const int ci0b = chunk * 16 + (tg + 4) * 2;
    const int coA  = coblk * 128 + m * 16 + g;
    const int coB  = coA + 8;

    auto pack2 = [&](int co, int ci) -> uint32_t {
        float v0 = W[((size_t)co * 512 + ci) * 9 + tap];
        float v1 = W[((size_t)co * 512 + ci + 1) * 9 + tap];
        __half2 h = __floats2half2_rn(v0, v1);
        return *(uint32_t*)&h;
    };
    uint4 e;
    e.x = pack2(coA, ci0a);
    e.y = pack2(coB, ci0a);
    e.z = pack2(coA, ci0b);
    e.w = pack2(coB, ci0b);
    W4[(size_t)bid * 256 + tid] = e;
}

// ---------------- conv: fp16 1-term mma.sync, 64x64 warp tiles ----------------
// grid (256 n, 4 coblk), block 256 (8 warps; wm=co-half, wn=64-s quarter).
#define SA_B 408
#define BH_OFF 9216              // A = 9216 u32 (2304 uint4)
#define BUF_U32 12480            // + B 8*408 = 3264
#define CONV_SMEM (2 * BUF_U32 * 4)   // 99840 bytes

__device__ __forceinline__ void stage_async(
    uint32_t bufb, const uint32_t* __restrict__ wgh, const uint32_t* __restrict__ xhi,
    int n, int coblk, int cc, int tid)
{
    // A: linear copy, frag-order
    const uint32_t* wsrc = wgh + (size_t)(coblk * 32 + cc) * 9216;
#pragma unroll
    for (int r = 0; r < 9; r++) {
        int i = tid + 256 * r;            // uint4 index 0..2303
        cpa16(bufb + (uint32_t)i * 16, wsrc + (size_t)i * 4);
    }
    // B: [8 j][4 t][8x8 interior], row stride 408
#pragma unroll
    for (int r = 0; r < 8; r++) {
        int i  = tid + 256 * r;           // 0..2047
        int j  = i >> 8;
        int t  = (i >> 6) & 3;
        int hw = i & 63;
        int h  = hw >> 3, w = hw & 7;
        size_t src = ((size_t)n * 256 + cc * 8 + j) * 256 + (size_t)t * 64 + hw;
        uint32_t d = bufb + (uint32_t)(BH_OFF + j * SA_B + t * 100 + (h + 1) * 10 + (w + 1)) * 4;
        cpa4(d, xhi + src);
    }
}

// mode: 0 = fp32 + residual;  1 = q/k: __half hi/lo [s][n][c];  2 = v: __half hi [s][c][n]
__global__ __launch_bounds__(256, 1)
void conv_mma_kernel(const uint32_t* __restrict__ xhi, const uint32_t* __restrict__ wgh,
                     const float* __restrict__ res, float* __restrict__ out,
                     __half* __restrict__ oh, __half* __restrict__ ol, int mode)
{
    extern __shared__ uint32_t smu[];
    const uint32_t smb = smem_u32(smu);

    const int tid = threadIdx.x;
    const int wid = tid >> 5, lid = tid & 31;
    const int n     = blockIdx.x;
    const int coblk = blockIdx.y;
    const int co0   = coblk * 128;
    const int wm  = wid & 1, wn = wid >> 1;
    const int g   = lid >> 2, tg = lid & 3;

    // zero B regions of both buffers (borders persist as zero)
    for (int i = tid; i < 3264; i += 256) {
        smu[BH_OFF + i] = 0;
        smu[BUF_U32 + BH_OFF + i] = 0;
    }
    __syncthreads();

    int tcb[8];
#pragma unroll
    for (int ni = 0; ni < 8; ni++) {
        int col = wn * 64 + ni * 8 + g;
        tcb[ni] = (col >> 6) * 100 + (((col >> 3) & 7)) * 10 + (col & 7);
    }

    float acc[4][8][4];
#pragma unroll
    for (int mi = 0; mi < 4; mi++)
#pragma unroll
        for (int ni = 0; ni < 8; ni++)
#pragma unroll
            for (int r = 0; r < 4; r++) acc[mi][ni][r] = 0.f;

    stage_async(smb, wgh, xhi, n, coblk, 0, tid);
    asm volatile("cp.async.commit_group;" ::: "memory");

    for (int cc = 0; cc < 32; ++cc) {
        if (cc + 1 < 32) {
            stage_async(smb + ((cc + 1) & 1) * (BUF_U32 * 4), wgh, xhi, n, coblk, cc + 1, tid);
            asm volatile("cp.async.commit_group;" ::: "memory");
            asm volatile("cp.async.wait_group 1;" ::: "memory");
        } else {
            asm volatile("cp.async.wait_group 0;" ::: "memory");
        }
        __syncthreads();

        const uint32_t* Ah = smu + (cc & 1) * BUF_U32;
        const uint32_t* Bh = Ah + BH_OFF;

#pragma unroll
        for (int tap = 0; tap < 9; tap++) {
            const int sh = (tap / 3) * 10 + (tap % 3);

            uint32_t fbh[8][2];
            int bb = tg * SA_B + sh;
#pragma unroll
            for (int ni = 0; ni < 8; ni++) {
                int b0 = bb + tcb[ni];
                fbh[ni][0] = Bh[b0];
                fbh[ni][1] = Bh[b0 + 4 * SA_B];
            }
            uint4 av[4];
#pragma unroll
            for (int mi = 0; mi < 4; mi++) {
                int m = wm * 4 + mi;
                av[mi] = *(const uint4*)(Ah + ((tap * 8 + m) * 32 + lid) * 4);
            }
#pragma unroll
            for (int mi = 0; mi < 4; mi++)
#pragma unroll
                for (int ni = 0; ni < 8; ni++)
                    mma_f16(acc[mi][ni], (const uint32_t*)&av[mi], fbh[ni]);
        }
        __syncthreads();
    }

    // epilogue
#pragma unroll
    for (int mi = 0; mi < 4; mi++) {
        const int row = co0 + wm * 64 + mi * 16 + g;
#pragma unroll
        for (int ni = 0; ni < 8; ni++) {
            const int colb = wn * 64 + ni * 8 + 2 * tg;
#pragma unroll
            for (int r = 0; r < 4; r++) {
                const int rr = row + (r >= 2 ? 8 : 0);
                const int sc = colb + (r & 1);
                float v = acc[mi][ni][r];
                if (mode == 0) {
                    size_t o = ((size_t)n * C_ + rr) * THW_ + sc;
                    out[o] = v + res[o];
                } else {
                    __half h = __float2half_rn(v);
                    if (mode == 1) {
                        size_t o = ((size_t)sc * N_ + n) * C_ + rr;
                        oh[o] = h;
                        ol[o] = __float2half_rn(v - __half2float(h));
                    } else {
                        oh[((size_t)sc * C_ + rr) * N_ + n] = h;
                    }
                }
            }
        }
    }
}

// ---------------- attention: fp16 mma, register softmax ----------------
#define AT_SMEM_U32 26112
#define AT_ST 8704

__global__ __launch_bounds__(256, 2)
void attn_mma_kernel(const __half* __restrict__ qh, const __half* __restrict__ ql,
                     const __half* __restrict__ kh, const __half* __restrict__ kl,
                     const __half* __restrict__ vt, const int* __restrict__ roi,
                     float* __restrict__ virt)
{
    extern __shared__ uint32_t smu[];
    uint32_t* A  = smu;                       // [64][136]
    int* rois    = (int*)(smu + 25600);
    float* red   = (float*)(smu + 25856);
    const uint32_t smb = smem_u32(smu);
    const uint32_t stb = smb + AT_ST * 4;

    const int tid = threadIdx.x, wid = tid >> 5, lid = tid & 31;
    const int g = lid >> 2, tg = lid & 3;
    const int s = blockIdx.y, i0 = blockIdx.x * 64;
    const int wm = wid & 1, wn = wid >> 1;

    rois[tid] = roi[tid];

    float acc[2][8][4];
#pragma unroll
    for (int mi = 0; mi < 2; mi++)
#pragma unroll
        for (int ni = 0; ni < 8; ni++)
#pragma unroll
            for (int r = 0; r < 4; r++) acc[mi][ni][r] = 0.f;

    for (int ch = 0; ch < 16; ch++) {
        __syncthreads();
#pragma unroll
        for (int r = 0; r < 2; r++) {
            int i = tid + 256 * r;
            int arr = i >> 8, rem = i & 255;
            int row = rem >> 2, t = rem & 3;
            const __half* src = (arr ? ql : qh) + ((size_t)s * 256 + i0 + row) * 512 + ch * 32 + t * 8;
            cpa16(stb + (uint32_t)(arr * 1280 + row * 20 + t * 4) * 4, src);
        }
#pragma unroll
        for (int r = 0; r < 8; r++) {
            int i = tid + 256 * r;
            int arr = i >> 10, rem = i & 1023;
            int row = rem >> 2, t = rem & 3;
            const __half* src = (arr ? kl : kh) + ((size_t)s * 256 + row) * 512 + ch * 32 + t * 8;
            cpa16(stb + (uint32_t)(2560 + arr * 5120 + row * 20 + t * 4) * 4, src);
        }
        asm volatile("cp.async.commit_group;" ::: "memory");
        asm volatile("cp.async.wait_group 0;" ::: "memory");
        __syncthreads();

        const uint32_t* Qh = smu + AT_ST;
        const uint32_t* Ql = Qh + 1280;
        const uint32_t* Kh = Qh + 2560;
        const uint32_t* Kl = Qh + 7680;
#pragma unroll
        for (int ks = 0; ks < 2; ks++) {
            const int kb = ks * 8;
            uint32_t ah[2][4], al[2][4], b[8][2];
#pragma unroll
            for (int mi = 0; mi < 2; mi++) {
                int a0 = (wm * 32 + mi * 16 + g) * 20 + kb + tg;
                ah[mi][0] = Qh[a0]; ah[mi][1] = Qh[a0 + 160];
                ah[mi][2] = Qh[a0 + 4]; ah[mi][3] = Qh[a0 + 164];
                al[mi][0] = Ql[a0]; al[mi][1] = Ql[a0 + 160];
                al[mi][2] = Ql[a0 + 4]; al[mi][3] = Ql[a0 + 164];
            }
#pragma unroll
            for (int ni = 0; ni < 8; ni++) {
                int b0 = (wn * 64 + ni * 8 + g) * 20 + kb + tg;
                b[ni][0] = Kh[b0]; b[ni][1] = Kh[b0 + 4];
            }
#pragma unroll
            for (int mi = 0; mi < 2; mi++)
#pragma unroll
                for (int ni = 0; ni < 8; ni++) {
                    mma_f16(acc[mi][ni], ah[mi], b[ni]);
                    mma_f16(acc[mi][ni], al[mi], b[ni]);
                }
#pragma unroll
            for (int ni = 0; ni < 8; ni++) {
                int b0 = (wn * 64 + ni * 8 + g) * 20 + kb + tg;
                b[ni][0] = Kl[b0]; b[ni][1] = Kl[b0 + 4];
            }
#pragma unroll
            for (int mi = 0; mi < 2; mi++)
#pragma unroll
                for (int ni = 0; ni < 8; ni++)
                    mma_f16(acc[mi][ni], ah[mi], b[ni]);
        }
    }

    const float scale = 0.044194173824159216f;
    int rro[2][2], cro[8][2];
#pragma unroll
    for (int mi = 0; mi < 2; mi++)
#pragma unroll
        for (int h = 0; h < 2; h++)
            rro[mi][h] = rois[i0 + wm * 32 + mi * 16 + g + 8 * h];
#pragma unroll
    for (int ni = 0; ni < 8; ni++)
#pragma unroll
        for (int c = 0; c < 2; c++)
            cro[ni][c] = rois[wn * 64 + ni * 8 + 2 * tg + c];
#pragma unroll
    for (int mi = 0; mi < 2; mi++)
#pragma unroll
        for (int ni = 0; ni < 8; ni++)
#pragma unroll
            for (int r = 0; r < 4; r++) {
                float v = acc[mi][ni][r] * scale;
                acc[mi][ni][r] = (cro[ni][r & 1] == rro[mi][r >> 1]) ? v : -1e30f;
            }

    float mx[2][2] = {{-1e30f, -1e30f}, {-1e30f, -1e30f}};
#pragma unroll
    for (int mi = 0; mi < 2; mi++)
#pragma unroll
        for (int ni = 0; ni < 8; ni++)
#pragma unroll
            for (int r = 0; r < 4; r++)
                mx[mi][r >> 1] = fmaxf(mx[mi][r >> 1], acc[mi][ni][r]);
#pragma unroll
    for (int mi = 0; mi < 2; mi++)
#pragma unroll
        for (int h = 0; h < 2; h++) {
            mx[mi][h] = fmaxf(mx[mi][h], __shfl_xor_sync(0xffffffffu, mx[mi][h], 1));
            mx[mi][h] = fmaxf(mx[mi][h], __shfl_xor_sync(0xffffffffu, mx[mi][h], 2));
        }
    if (tg == 0)
#pragma unroll
        for (int mi = 0; mi < 2; mi++)
#pragma unroll
            for (int h = 0; h < 2; h++)
                red[wn * 64 + wm * 32 + mi * 16 + g + 8 * h] = mx[mi][h];
    __syncthreads();
#pragma unroll
    for (int mi = 0; mi < 2; mi++)
#pragma unroll
        for (int h = 0; h < 2; h++) {
            int row = wm * 32 + mi * 16 + g + 8 * h;
            mx[mi][h] = fmaxf(fmaxf(red[row], red[64 + row]),
                              fmaxf(red[128 + row], red[192 + row]));
        }
    __syncthreads();

    float sm[2][2] = {{0.f, 0.f}, {0.f, 0.f}};
#pragma unroll
    for (int mi = 0; mi < 2; mi++)
#pragma unroll
        for (int ni = 0; ni < 8; ni++)
#pragma unroll
            for (int r = 0; r < 4; r++) {
                float e = __expf(acc[mi][ni][r] - mx[mi][r >> 1]);
                acc[mi][ni][r] = e;
                sm[mi][r >> 1] += e;
            }
#pragma unroll
    for (int mi = 0; mi < 2; mi++)
#pragma unroll
        for (int h = 0; h < 2; h++) {
            sm[mi][h] += __shfl_xor_sync(0xffffffffu, sm[mi][h], 1);
            sm[mi][h] += __shfl_xor_sync(0xffffffffu, sm[mi][h], 2);
        }
    if (tg == 0)
#pragma unroll
        for (int mi = 0; mi < 2; mi++)
#pragma unroll
            for (int h = 0; h < 2; h++)
                red[wn * 64 + wm * 32 + mi * 16 + g + 8 * h] = sm[mi][h];
    __syncthreads();
#pragma unroll
    for (int mi = 0; mi < 2; mi++)
#pragma unroll
        for (int h = 0; h < 2; h++) {
            int row = wm * 32 + mi * 16 + g + 8 * h;
            float tot = red[row] + red[64 + row] + red[128 + row] + red[192 + row];
            sm[mi][h] = 1.f / tot;
        }

#pragma unroll
    for (int mi = 0; mi < 2; mi++)
#pragma unroll
        for (int ni = 0; ni < 8; ni++)
#pragma unroll
            for (int h = 0; h < 2; h++) {
                __half2 p = __floats2half2_rn(acc[mi][ni][2 * h] * sm[mi][h],
                                              acc[mi][ni][2 * h + 1] * sm[mi][h]);
                int row = wm * 32 + mi * 16 + g + 8 * h;
                A[row * 136 + wn * 32 + ni * 4 + tg] = *(uint32_t*)&p;
            }
    __syncthreads();

#pragma unroll
    for (int r = 0; r < 8; r++) {
        int i = tid + 256 * r;
        int row = i >> 5, t = i & 31;
        const __half* src = vt + ((size_t)s * 512 + row) * 256 + t * 8;
        cpa16(stb + (uint32_t)(row * 132 + t * 4) * 4, src);
    }
    asm volatile("cp.async.commit_group;" ::: "memory");

    for (int mc = 0; mc < 8; mc++) {
        if (mc + 1 < 8) {
#pragma unroll
            for (int r = 0; r < 8; r++) {
                int i = tid + 256 * r;
                int row = i >> 5, t = i & 31;
                const __half* src = vt + ((size_t)s * 512 + (mc + 1) * 64 + row) * 256 + t * 8;
                cpa16(stb + (uint32_t)(((mc + 1) & 1) * 8448 + row * 132 + t * 4) * 4, src);
            }
            asm volatile("cp.async.commit_group;" ::: "memory");
            asm volatile("cp.async.wait_group 1;" ::: "memory");
        } else {
            asm volatile("cp.async.wait_group 0;" ::: "memory");
        }
        __syncthreads();

        const uint32_t* Vt = smu + AT_ST + (mc & 1) * 8448;
        float acc2[4][4];
#pragma unroll
        for (int mt = 0; mt < 4; mt++)
#pragma unroll
            for (int r = 0; r < 4; r++) acc2[mt][r] = 0.f;

#pragma unroll
        for (int ks = 0; ks < 16; ks++) {
            uint32_t b2[2], a2[4][4];
            int bb = (wid * 8 + g) * 136 + ks * 8 + tg;
            b2[0] = A[bb]; b2[1] = A[bb + 4];
#pragma unroll
            for (int mt = 0; mt < 4; mt++) {
                int a0 = (mt * 16 + g) * 132 + ks * 8 + tg;
                a2[mt][0] = Vt[a0]; a2[mt][1] = Vt[a0 + 8 * 132];
                a2[mt][2] = Vt[a0 + 4]; a2[mt][3] = Vt[a0 + 8 * 132 + 4];
            }
#pragma unroll
            for (int mt = 0; mt < 4; mt++) mma_f16(acc2[mt], a2[mt], b2);
        }
#pragma unroll
        for (int mt = 0; mt < 4; mt++)
#pragma unroll
            for (int r = 0; r < 4; r++) {
                int c  = mc * 64 + mt * 16 + g + 8 * (r >> 1);
                int ig = i0 + wid * 8 + 2 * tg + (r & 1);
                virt[((size_t)s * 256 + ig) * 512 + c] = acc2[mt][r];
            }
        __syncthreads();
    }
}

// ---------------- GroupNorm + affine + ReLU + fp16 pack (hi only) ----------------
__global__ __launch_bounds__(256)
void gn_relu_pack_kernel(const float* __restrict__ buf, const float* __restrict__ gamma,
                         const float* __restrict__ beta, uint32_t* __restrict__ vhi)
{
    __shared__ double red[256];
    __shared__ double red2[256];
    const int n = blockIdx.x;
    const int M = C_ * THW_;

    double s = 0.0, s2 = 0.0;
    for (int i = threadIdx.x; i < M; i += 256) {
        int ss = i >> 9, c = i & 511;
        float v = buf[((size_t)ss * 256 + n) * 512 + c];
        s  += v;
        s2 += (double)v * v;
    }
    red[threadIdx.x]  = s;
    red2[threadIdx.x] = s2;
    __syncthreads();
    for (int off = 128; off > 0; off >>= 1) {
        if (threadIdx.x < off) {
            red[threadIdx.x]  += red[threadIdx.x + off];
            red2[threadIdx.x] += red2[threadIdx.x + off];
        }
        __syncthreads();
    }
    double mu_d  = red[0] / M;
    double var_d = red2[0] / M - mu_d * mu_d;
    float mu   = (float)mu_d;
    float rstd = rsqrtf((float)var_d + 1e-5f);

    for (int i = threadIdx.x; i < M / 2; i += 256) {
        int c2 = i & 255, ss = i >> 8;
        int c0 = 2 * c2;
        size_t src = ((size_t)ss * 256 + n) * 512 + c0;
        float v0 = (buf[src]     - mu) * rstd * gamma[c0]     + beta[c0];
        float v1 = (buf[src + 1] - mu) * rstd * gamma[c0 + 1] + beta[c0 + 1];
        v0 = fmaxf(v0, 0.f);
        v1 = fmaxf(v1, 0.f);
        __half2 h = __floats2half2_rn(v0, v1);
        vhi[((size_t)n * 256 + c2) * 256 + ss] = *(uint32_t*)&h;
    }
}

// ---------------------------------------------------------------------------
extern "C" void kernel_launch(void* const* d_in, const int* in_sizes, int n_in,
                              void* d_out, int out_size)
{
    const float* x   = (const float*)d_in[0];
    const int*   roi = (const int*)d_in[1];
    const float* Wq  = (const float*)d_in[2];
    const float* Wk  = (const float*)d_in[3];
    const float* Wv  = (const float*)d_in[4];
    const float* Wc  = (const float*)d_in[5];
    const float* gam = (const float*)d_in[6];
    const float* bet = (const float*)d_in[7];
    float* out = (float*)d_out;

    float *virt;
    __half *qh, *ql, *kh, *kl, *vth;
    uint32_t *xhi, *vhi, *wgh;
    cudaGetSymbolAddress((void**)&virt, g_virt);
    cudaGetSymbolAddress((void**)&qh,   g_qh);
    cudaGetSymbolAddress((void**)&ql,   g_ql);
    cudaGetSymbolAddress((void**)&kh,   g_kh);
    cudaGetSymbolAddress((void**)&kl,   g_kl);
    cudaGetSymbolAddress((void**)&vth,  g_vth);
    cudaGetSymbolAddress((void**)&xhi,  g_xhi);
    cudaGetSymbolAddress((void**)&vhi,  g_vhi);
    cudaGetSymbolAddress((void**)&wgh,  g_wgh);

    cudaFuncSetAttribute(conv_mma_kernel, cudaFuncAttributeMaxDynamicSharedMemorySize,
                         CONV_SMEM);
    cudaFuncSetAttribute(attn_mma_kernel, cudaFuncAttributeMaxDynamicSharedMemorySize,
                         AT_SMEM_U32 * 4);

    xsplit_kernel<<<HPAIR / 256, 256>>>(x, xhi);
    wsplit_kernel<<<1152, 256>>>(Wq, (uint4*)(wgh + 0 * (size_t)WU32));
    wsplit_kernel<<<1152, 256>>>(Wk, (uint4*)(wgh + 1 * (size_t)WU32));
    wsplit_kernel<<<1152, 256>>>(Wv, (uint4*)(wgh + 2 * (size_t)WU32));
    wsplit_kernel<<<1152, 256>>>(Wc, (uint4*)(wgh + 3 * (size_t)WU32));

    dim3 cgrid(256, 4);
    conv_mma_kernel<<<cgrid, 256, CONV_SMEM>>>(xhi, wgh + 0 * (size_t)WU32, nullptr,
                                               nullptr, qh, ql, 1);
    conv_mma_kernel<<<cgrid, 256, CONV_SMEM>>>(xhi, wgh + 1 * (size_t)WU32, nullptr,
                                               nullptr, kh, kl, 1);
    conv_mma_kernel<<<cgrid, 256, CONV_SMEM>>>(xhi, wgh + 2 * (size_t)WU32, nullptr,
                                               nullptr, vth, nullptr, 2);

    attn_mma_kernel<<<dim3(4, 256), 256, AT_SMEM_U32 * 4>>>(qh, ql, kh, kl, vth, roi, virt);

    gn_relu_pack_kernel<<<256, 256>>>(virt, gam, bet, vhi);

    conv_mma_kernel<<<cgrid, 256, CONV_SMEM>>>(vhi, wgh + 3 * (size_t)WU32, x,
                                               out, nullptr, nullptr, 0);
}

// round 14
// speedup vs baseline: 13.0365x; 1.0746x over previous
#include <cuda_runtime.h>
#include <cuda_fp16.h>
#include <math.h>
#include <stdint.h>

#define N_    256
#define C_    512
#define T_    4
#define HW_   64
#define THW_  256
#define ELEMS (N_ * C_ * THW_)
#define HPAIR (ELEMS / 2)
#define WU32  (2304 * 512)          // u32 per conv weight array

__device__ float    g_virt[ELEMS];   // [s][n][c]
__device__ __half   g_qh[ELEMS];     // [s][n][c]
__device__ __half   g_ql[ELEMS];
__device__ __half   g_kh[ELEMS];
__device__ __half   g_kl[ELEMS];
__device__ __half   g_vth[ELEMS];    // [s][c][n]
__device__ uint32_t g_xhi[HPAIR];    // packed fp16x2 [n][ci2][thw]
__device__ uint32_t g_vhi[HPAIR];
__device__ uint32_t g_wgh[4][WU32];  // frag-order: [coblk4][chunk32][tap9][m8][lane32] x uint4

// ---------------- helpers ----------------
__device__ __forceinline__ uint32_t smem_u32(const void* p) {
    uint32_t a;
    asm("{ .reg .u64 t; cvta.to.shared.u64 t, %1; cvt.u32.u64 %0, t; }" : "=r"(a) : "l"(p));
    return a;
}
__device__ __forceinline__ void mma_f16(float* d, const uint32_t* a, const uint32_t* b) {
    asm volatile(
        "mma.sync.aligned.m16n8k16.row.col.f32.f16.f16.f32 "
        "{%0,%1,%2,%3}, {%4,%5,%6,%7}, {%8,%9}, {%0,%1,%2,%3};"
        : "+f"(d[0]), "+f"(d[1]), "+f"(d[2]), "+f"(d[3])
        : "r"(a[0]), "r"(a[1]), "r"(a[2]), "r"(a[3]), "r"(b[0]), "r"(b[1]));
}
__device__ __forceinline__ void cpa16(uint32_t dst, const void* src) {
    asm volatile("cp.async.cg.shared.global [%0], [%1], 16;" :: "r"(dst), "l"(src));
}
__device__ __forceinline__ void cpa4(uint32_t dst, const void* src) {
    asm volatile("cp.async.ca.shared.global [%0], [%1], 4;" :: "r"(dst), "l"(src));
}

// ---------------- prepass: x -> packed fp16x2 (hi only) ----------------
__global__ void xsplit_kernel(const float* __restrict__ src, uint32_t* __restrict__ hi) {
    int idx = blockIdx.x * 256 + threadIdx.x;     // < HPAIR
    int n   = idx >> 16;
    int r   = idx & 65535;
    int ci2 = r >> 8, pos = r & 255;
    size_t base = ((size_t)n * C_ + 2 * ci2) * THW_ + pos;
    __half2 h = __floats2half2_rn(src[base], src[base + THW_]);
    hi[idx] = *(uint32_t*)&h;
}

// ---------------- prepass: weights -> fragment-order uint4 layout (4 convs in one) ----
// grid (1152, 4); block 256 = 8 m * 32 lane.  1152 = 4 coblk * 32 chunk * 9 tap
__global__ void wsplit_kernel(const float* __restrict__ Wq, const float* __restrict__ Wk,
                              const float* __restrict__ Wv, const float* __restrict__ Wc,
                              uint4* __restrict__ W4base) {
    const int conv = blockIdx.y;
    const float* W = (conv == 0) ? Wq : (conv == 1) ? Wk : (conv == 2) ? Wv : Wc;
    uint4* W4 = W4base + (size_t)conv * (WU32 / 4);

    const int bid = blockIdx.x;
    const int tap = bid % 9;
    const int cb  = bid / 9;
    const int chunk = cb & 31;
    const int coblk = cb >> 5;
    const int tid  = threadIdx.x;
    const int m    = tid >> 5;
    const int lane = tid & 31;
    const int g    = lane >> 2, tg = lane & 3;

    const int ci0a = chunk * 16 + tg * 2;
    const int ci0b = chunk * 16 + (tg + 4) * 2;
    const int coA  = coblk * 128 + m * 16 + g;
    const int coB  = coA + 8;

    auto pack2 = [&](int co, int ci) -> uint32_t {
        float v0 = W[((size_t)co * 512 + ci) * 9 + tap];
        float v1 = W[((size_t)co * 512 + ci + 1) * 9 + tap];
        __half2 h = __floats2half2_rn(v0, v1);
        return *(uint32_t*)&h;
    };
    uint4 e;
    e.x = pack2(coA, ci0a);
    e.y = pack2(coB, ci0a);
    e.z = pack2(coA, ci0b);
    e.w = pack2(coB, ci0b);
    W4[(size_t)bid * 256 + tid] = e;
}

// ---------------- conv mainloop: 128-thread CTA, 4 warps of 64co x 64s ----------------
// CTA covers 128co x 128s (2 t).  B slab [8 j][2 t][10x10 pad], stride 200.
#define SA_B 200
#define BH_OFF 9216              // A = 9216 u32 (2304 uint4)
#define BUF_U32 10848            // + B 8*200 = 1600 (+32 pad)
#define CONV_SMEM (2 * BUF_U32 * 4)   // 86784 bytes

__device__ __forceinline__ void stage_async(
    uint32_t bufb, const uint32_t* __restrict__ wptr, const uint32_t* __restrict__ xsrc,
    int n, int t0, int cc, int tid)
{
    const uint32_t* wsrc = wptr + (size_t)cc * 9216;
#pragma unroll
    for (int r = 0; r < 18; r++) {
        int i = tid + 128 * r;            // uint4 index 0..2303
        cpa16(bufb + (uint32_t)i * 16, wsrc + (size_t)i * 4);
    }
#pragma unroll
    for (int r = 0; r < 8; r++) {
        int i  = tid + 128 * r;           // 0..1023
        int j  = i >> 7;
        int t  = (i >> 6) & 1;
        int hw = i & 63;
        int h  = hw >> 3, w = hw & 7;
        size_t src = ((size_t)n * 256 + cc * 8 + j) * 256 + (size_t)(t0 + t) * 64 + hw;
        uint32_t d = bufb + (uint32_t)(BH_OFF + j * SA_B + t * 100 + (h + 1) * 10 + (w + 1)) * 4;
        cpa4(d, xsrc + src);
    }
}

__device__ __forceinline__ void conv_mainloop(
    uint32_t* smu, uint32_t smb, const uint32_t* __restrict__ xsrc,
    const uint32_t* __restrict__ wptr, int n, int t0, int tid,
    int wm, int wn, int g, int tg, int lid, float acc[4][8][4])
{
    for (int i = tid; i < 1632; i += 128) {
        smu[BH_OFF + i] = 0;
        smu[BUF_U32 + BH_OFF + i] = 0;
    }
    __syncthreads();

    int tcb[8];
#pragma unroll
    for (int ni = 0; ni < 8; ni++) {
        int col = wn * 64 + ni * 8 + g;      // 0..127 within slab
        tcb[ni] = (col >> 6) * 100 + ((col >> 3) & 7) * 10 + (col & 7);
    }

    stage_async(smb, wptr, xsrc, n, t0, 0, tid);
    asm volatile("cp.async.commit_group;" ::: "memory");

    for (int cc = 0; cc < 32; ++cc) {
        if (cc + 1 < 32) {
            stage_async(smb + ((cc + 1) & 1) * (BUF_U32 * 4), wptr, xsrc, n, t0, cc + 1, tid);
            asm volatile("cp.async.commit_group;" ::: "memory");
            asm volatile("cp.async.wait_group 1;" ::: "memory");
        } else {
            asm volatile("cp.async.wait_group 0;" ::: "memory");
        }
        __syncthreads();

        const uint32_t* Ah = smu + (cc & 1) * BUF_U32;
        const uint32_t* Bh = Ah + BH_OFF;

#pragma unroll
        for (int tap = 0; tap < 9; tap++) {
            const int sh = (tap / 3) * 10 + (tap % 3);

            uint32_t fbh[8][2];
            int bb = tg * SA_B + sh;
#pragma unroll
            for (int ni = 0; ni < 8; ni++) {
                int b0 = bb + tcb[ni];
                fbh[ni][0] = Bh[b0];
                fbh[ni][1] = Bh[b0 + 4 * SA_B];
            }
            uint4 av[4];
#pragma unroll
            for (int mi = 0; mi < 4; mi++) {
                int m = wm * 4 + mi;
                av[mi] = *(const uint4*)(Ah + ((tap * 8 + m) * 32 + lid) * 4);
            }
#pragma unroll
            for (int mi = 0; mi < 4; mi++)
#pragma unroll
                for (int ni = 0; ni < 8; ni++)
                    mma_f16(acc[mi][ni], (const uint32_t*)&av[mi], fbh[ni]);
        }
        __syncthreads();
    }
}

// ---- merged q/k/v conv: grid (256 n, 12 = conv*4+coblk, 2 t-half), block 128 ----
__global__ __launch_bounds__(128)
void conv_qkv_kernel(const uint32_t* __restrict__ xhi, const uint32_t* __restrict__ wgh,
                     __half* __restrict__ qh, __half* __restrict__ ql,
                     __half* __restrict__ kh, __half* __restrict__ kl,
                     __half* __restrict__ vth)
{
    extern __shared__ uint32_t smu[];
    const uint32_t smb = smem_u32(smu);

    const int tid = threadIdx.x;
    const int wid = tid >> 5, lid = tid & 31;
    const int n     = blockIdx.x;
    const int conv  = blockIdx.y >> 2;
    const int coblk = blockIdx.y & 3;
    const int co0   = coblk * 128;
    const int s0    = blockIdx.z * 128;
    const int t0    = blockIdx.z * 2;
    const int wm  = wid & 1, wn = wid >> 1;
    const int g   = lid >> 2, tg = lid & 3;

    const uint32_t* wptr = wgh + (size_t)conv * WU32 + (size_t)coblk * 32 * 9216;

    float acc[4][8][4];
#pragma unroll
    for (int mi = 0; mi < 4; mi++)
#pragma unroll
        for (int ni = 0; ni < 8; ni++)
#pragma unroll
            for (int r = 0; r < 4; r++) acc[mi][ni][r] = 0.f;

    conv_mainloop(smu, smb, xhi, wptr, n, t0, tid, wm, wn, g, tg, lid, acc);

    __half* oh = (conv == 0) ? qh : (conv == 1) ? kh : vth;
    __half* ol = (conv == 0) ? ql : kl;

#pragma unroll
    for (int mi = 0; mi < 4; mi++) {
        const int row = co0 + wm * 64 + mi * 16 + g;
#pragma unroll
        for (int ni = 0; ni < 8; ni++) {
            const int colb = s0 + wn * 64 + ni * 8 + 2 * tg;
#pragma unroll
            for (int r = 0; r < 4; r++) {
                const int rr = row + (r >= 2 ? 8 : 0);
                const int sc = colb + (r & 1);
                float v = acc[mi][ni][r];
                __half h = __float2half_rn(v);
                if (conv < 2) {
                    size_t o = ((size_t)sc * N_ + n) * C_ + rr;
                    oh[o] = h;
                    ol[o] = __float2half_rn(v - __half2float(h));
                } else {
                    oh[((size_t)sc * C_ + rr) * N_ + n] = h;
                }
            }
        }
    }
}

// ---- final conv (+residual): grid (256 n, 4 coblk, 2), block 128 ----
__global__ __launch_bounds__(128)
void conv_final_kernel(const uint32_t* __restrict__ vhi, const uint32_t* __restrict__ wgh,
                       const float* __restrict__ res, float* __restrict__ out)
{
    extern __shared__ uint32_t smu[];
    const uint32_t smb = smem_u32(smu);

    const int tid = threadIdx.x;
    const int wid = tid >> 5, lid = tid & 31;
    const int n     = blockIdx.x;
    const int coblk = blockIdx.y;
    const int co0   = coblk * 128;
    const int s0    = blockIdx.z * 128;
    const int t0    = blockIdx.z * 2;
    const int wm  = wid & 1, wn = wid >> 1;
    const int g   = lid >> 2, tg = lid & 3;

    const uint32_t* wptr = wgh + (size_t)3 * WU32 + (size_t)coblk * 32 * 9216;

    float acc[4][8][4];
#pragma unroll
    for (int mi = 0; mi < 4; mi++)
#pragma unroll
        for (int ni = 0; ni < 8; ni++)
#pragma unroll
            for (int r = 0; r < 4; r++) acc[mi][ni][r] = 0.f;

    conv_mainloop(smu, smb, vhi, wptr, n, t0, tid, wm, wn, g, tg, lid, acc);

#pragma unroll
    for (int mi = 0; mi < 4; mi++) {
        const int row = co0 + wm * 64 + mi * 16 + g;
#pragma unroll
        for (int ni = 0; ni < 8; ni++) {
            const int colb = s0 + wn * 64 + ni * 8 + 2 * tg;
#pragma unroll
            for (int r = 0; r < 4; r++) {
                const int rr = row + (r >= 2 ? 8 : 0);
                const int sc = colb + (r & 1);
                size_t o = ((size_t)n * C_ + rr) * THW_ + sc;
                out[o] = acc[mi][ni][r] + res[o];
            }
        }
    }
}

// ---------------- attention: fp16 mma, register softmax ----------------
#define AT_SMEM_U32 26112
#define AT_ST 8704

__global__ __launch_bounds__(256, 2)
void attn_mma_kernel(const __half* __restrict__ qh, const __half* __restrict__ ql,
                     const __half* __restrict__ kh, const __half* __restrict__ kl,
                     const __half* __restrict__ vt, const int* __restrict__ roi,
                     float* __restrict__ virt)
{
    extern __shared__ uint32_t smu[];
    uint32_t* A  = smu;                       // [64][136]
    int* rois    = (int*)(smu + 25600);
    float* red   = (float*)(smu + 25856);
    const uint32_t smb = smem_u32(smu);
    const uint32_t stb = smb + AT_ST * 4;

    const int tid = threadIdx.x, wid = tid >> 5, lid = tid & 31;
    const int g = lid >> 2, tg = lid & 3;
    const int s = blockIdx.y, i0 = blockIdx.x * 64;
    const int wm = wid & 1, wn = wid >> 1;

    rois[tid] = roi[tid];

    float acc[2][8][4];
#pragma unroll
    for (int mi = 0; mi < 2; mi++)
#pragma unroll
        for (int ni = 0; ni < 8; ni++)
#pragma unroll
            for (int r = 0; r < 4; r++) acc[mi][ni][r] = 0.f;

    for (int ch = 0; ch < 16; ch++) {
        __syncthreads();
#pragma unroll
        for (int r = 0; r < 2; r++) {
            int i = tid + 256 * r;
            int arr = i >> 8, rem = i & 255;
            int row = rem >> 2, t = rem & 3;
            const __half* src = (arr ? ql : qh) + ((size_t)s * 256 + i0 + row) * 512 + ch * 32 + t * 8;
            cpa16(stb + (uint32_t)(arr * 1280 + row * 20 + t * 4) * 4, src);
        }
#pragma unroll
        for (int r = 0; r < 8; r++) {
            int i = tid + 256 * r;
            int arr = i >> 10, rem = i & 1023;
            int row = rem >> 2, t = rem & 3;
            const __half* src = (arr ? kl : kh) + ((size_t)s * 256 + row) * 512 + ch * 32 + t * 8;
            cpa16(stb + (uint32_t)(2560 + arr * 5120 + row * 20 + t * 4) * 4, src);
        }
        asm volatile("cp.async.commit_group;" ::: "memory");
        asm volatile("cp.async.wait_group 0;" ::: "memory");
        __syncthreads();

        const uint32_t* Qh = smu + AT_ST;
        const uint32_t* Ql = Qh + 1280;
        const uint32_t* Kh = Qh + 2560;
        const uint32_t* Kl = Qh + 7680;
#pragma unroll
        for (int ks = 0; ks < 2; ks++) {
            const int kb = ks * 8;
            uint32_t ah[2][4], al[2][4], b[8][2];
#pragma unroll
            for (int mi = 0; mi < 2; mi++) {
                int a0 = (wm * 32 + mi * 16 + g) * 20 + kb + tg;
                ah[mi][0] = Qh[a0]; ah[mi][1] = Qh[a0 + 160];
                ah[mi][2] = Qh[a0 + 4]; ah[mi][3] = Qh[a0 + 164];
                al[mi][0] = Ql[a0]; al[mi][1] = Ql[a0 + 160];
                al[mi][2] = Ql[a0 + 4]; al[mi][3] = Ql[a0 + 164];
            }
#pragma unroll
            for (int ni = 0; ni < 8; ni++) {
                int b0 = (wn * 64 + ni * 8 + g) * 20 + kb + tg;
                b[ni][0] = Kh[b0]; b[ni][1] = Kh[b0 + 4];
            }
#pragma unroll
            for (int mi = 0; mi < 2; mi++)
#pragma unroll
                for (int ni = 0; ni < 8; ni++) {
                    mma_f16(acc[mi][ni], ah[mi], b[ni]);
                    mma_f16(acc[mi][ni], al[mi], b[ni]);
                }
#pragma unroll
            for (int ni = 0; ni < 8; ni++) {
                int b0 = (wn * 64 + ni * 8 + g) * 20 + kb + tg;
                b[ni][0] = Kl[b0]; b[ni][1] = Kl[b0 + 4];
            }
#pragma unroll
            for (int mi = 0; mi < 2; mi++)
#pragma unroll
                for (int ni = 0; ni < 8; ni++)
                    mma_f16(acc[mi][ni], ah[mi], b[ni]);
        }
    }

    const float scale = 0.044194173824159216f;
    int rro[2][2], cro[8][2];
#pragma unroll
    for (int mi = 0; mi < 2; mi++)
#pragma unroll
        for (int h = 0; h < 2; h++)
            rro[mi][h] = rois[i0 + wm * 32 + mi * 16 + g + 8 * h];
#pragma unroll
    for (int ni = 0; ni < 8; ni++)
#pragma unroll
        for (int c = 0; c < 2; c++)
            cro[ni][c] = rois[wn * 64 + ni * 8 + 2 * tg + c];
#pragma unroll
    for (int mi = 0; mi < 2; mi++)
#pragma unroll
        for (int ni = 0; ni < 8; ni++)
#pragma unroll
            for (int r = 0; r < 4; r++) {
                float v = acc[mi][ni][r] * scale;
                acc[mi][ni][r] = (cro[ni][r & 1] == rro[mi][r >> 1]) ? v : -1e30f;
            }

    float mx[2][2] = {{-1e30f, -1e30f}, {-1e30f, -1e30f}};
#pragma unroll
    for (int mi = 0; mi < 2; mi++)
#pragma unroll
        for (int ni = 0; ni < 8; ni++)
#pragma unroll
            for (int r = 0; r < 4; r++)
                mx[mi][r >> 1] = fmaxf(mx[mi][r >> 1], acc[mi][ni][r]);
#pragma unroll
    for (int mi = 0; mi < 2; mi++)
#pragma unroll
        for (int h = 0; h < 2; h++) {
            mx[mi][h] = fmaxf(mx[mi][h], __shfl_xor_sync(0xffffffffu, mx[mi][h], 1));
            mx[mi][h] = fmaxf(mx[mi][h], __shfl_xor_sync(0xffffffffu, mx[mi][h], 2));
        }
    if (tg == 0)
#pragma unroll
        for (int mi = 0; mi < 2; mi++)
#pragma unroll
            for (int h = 0; h < 2; h++)
                red[wn * 64 + wm * 32 + mi * 16 + g + 8 * h] = mx[mi][h];
    __syncthreads();
#pragma unroll
    for (int mi = 0; mi < 2; mi++)
#pragma unroll
        for (int h = 0; h < 2; h++) {
            int row = wm * 32 + mi * 16 + g + 8 * h;
            mx[mi][h] = fmaxf(fmaxf(red[row], red[64 + row]),
                              fmaxf(red[128 + row], red[192 + row]));
        }
    __syncthreads();

    float sm[2][2] = {{0.f, 0.f}, {0.f, 0.f}};
#pragma unroll
    for (int mi = 0; mi < 2; mi++)
#pragma unroll
        for (int ni = 0; ni < 8; ni++)
#pragma unroll
            for (int r = 0; r < 4; r++) {
                float e = __expf(acc[mi][ni][r] - mx[mi][r >> 1]);
                acc[mi][ni][r] = e;
                sm[mi][r >> 1] += e;
            }
#pragma unroll
    for (int mi = 0; mi < 2; mi++)
#pragma unroll
        for (int h = 0; h < 2; h++) {
            sm[mi][h] += __shfl_xor_sync(0xffffffffu, sm[mi][h], 1);
            sm[mi][h] += __shfl_xor_sync(0xffffffffu, sm[mi][h], 2);
        }
    if (tg == 0)
#pragma unroll
        for (int mi = 0; mi < 2; mi++)
#pragma unroll
            for (int h = 0; h < 2; h++)
                red[wn * 64 + wm * 32 + mi * 16 + g + 8 * h] = sm[mi][h];
    __syncthreads();
#pragma unroll
    for (int mi = 0; mi < 2; mi++)
#pragma unroll
        for (int h = 0; h < 2; h++) {
            int row = wm * 32 + mi * 16 + g + 8 * h;
            float tot = red[row] + red[64 + row] + red[128 + row] + red[192 + row];
            sm[mi][h] = 1.f / tot;
        }

#pragma unroll
    for (int mi = 0; mi < 2; mi++)
#pragma unroll
        for (int ni = 0; ni < 8; ni++)
#pragma unroll
            for (int h = 0; h < 2; h++) {
                __half2 p = __floats2half2_rn(acc[mi][ni][2 * h] * sm[mi][h],
                                              acc[mi][ni][2 * h + 1] * sm[mi][h]);
                int row = wm * 32 + mi * 16 + g + 8 * h;
                A[row * 136 + wn * 32 + ni * 4 + tg] = *(uint32_t*)&p;
            }
    __syncthreads();

#pragma unroll
    for (int r = 0; r < 8; r++) {
        int i = tid + 256 * r;
        int row = i >> 5, t = i & 31;
        const __half* src = vt + ((size_t)s * 512 + row) * 256 + t * 8;
        cpa16(stb + (uint32_t)(row * 132 + t * 4) * 4, src);
    }
    asm volatile("cp.async.commit_group;" ::: "memory");

    for (int mc = 0; mc < 8; mc++) {
        if (mc + 1 < 8) {
#pragma unroll
            for (int r = 0; r < 8; r++) {
                int i = tid + 256 * r;
                int row = i >> 5, t = i & 31;
                const __half* src = vt + ((size_t)s * 512 + (mc + 1) * 64 + row) * 256 + t * 8;
                cpa16(stb + (uint32_t)(((mc + 1) & 1) * 8448 + row * 132 + t * 4) * 4, src);
            }
            asm volatile("cp.async.commit_group;" ::: "memory");
            asm volatile("cp.async.wait_group 1;" ::: "memory");
        } else {
            asm volatile("cp.async.wait_group 0;" ::: "memory");
        }
        __syncthreads();

        const uint32_t* Vt = smu + AT_ST + (mc & 1) * 8448;
        float acc2[4][4];
#pragma unroll
        for (int mt = 0; mt < 4; mt++)
#pragma unroll
            for (int r = 0; r < 4; r++) acc2[mt][r] = 0.f;

#pragma unroll
        for (int ks = 0; ks < 16; ks++) {
            uint32_t b2[2], a2[4][4];
            int bb = (wid * 8 + g) * 136 + ks * 8 + tg;
            b2[0] = A[bb]; b2[1] = A[bb + 4];
#pragma unroll
            for (int mt = 0; mt < 4; mt++) {
                int a0 = (mt * 16 + g) * 132 + ks * 8 + tg;
                a2[mt][0] = Vt[a0]; a2[mt][1] = Vt[a0 + 8 * 132];
                a2[mt][2] = Vt[a0 + 4]; a2[mt][3] = Vt[a0 + 8 * 132 + 4];
            }
#pragma unroll
            for (int mt = 0; mt < 4; mt++) mma_f16(acc2[mt], a2[mt], b2);
        }
#pragma unroll
        for (int mt = 0; mt < 4; mt++)
#pragma unroll
            for (int r = 0; r < 4; r++) {
                int c  = mc * 64 + mt * 16 + g + 8 * (r >> 1);
                int ig = i0 + wid * 8 + 2 * tg + (r & 1);
                virt[((size_t)s * 256 + ig) * 512 + c] = acc2[mt][r];
            }
        __syncthreads();
    }
}

// ---------------- GroupNorm + affine + ReLU + fp16 pack (hi only) ----------------
__global__ __launch_bounds__(256)
void gn_relu_pack_kernel(const float* __restrict__ buf, const float* __restrict__ gamma,
                         const float* __restrict__ beta, uint32_t* __restrict__ vhi)
{
    __shared__ double red[256];
    __shared__ double red2[256];
    const int n = blockIdx.x;
    const int M = C_ * THW_;

    double s = 0.0, s2 = 0.0;
    for (int i = threadIdx.x; i < M; i += 256) {
        int ss = i >> 9, c = i & 511;
        float v = buf[((size_t)ss * 256 + n) * 512 + c];
        s  += v;
        s2 += (double)v * v;
    }
    red[threadIdx.x]  = s;
    red2[threadIdx.x] = s2;
    __syncthreads();
    for (int off = 128; off > 0; off >>= 1) {
        if (threadIdx.x < off) {
            red[threadIdx.x]  += red[threadIdx.x + off];
            red2[threadIdx.x] += red2[threadIdx.x + off];
        }
        __syncthreads();
    }
    double mu_d  = red[0] / M;
    double var_d = red2[0] / M - mu_d * mu_d;
    float mu   = (float)mu_d;
    float rstd = rsqrtf((float)var_d + 1e-5f);

    for (int i = threadIdx.x; i < M / 2; i += 256) {
        int c2 = i & 255, ss = i >> 8;
        int c0 = 2 * c2;
        size_t src = ((size_t)ss * 256 + n) * 512 + c0;
        float v0 = (buf[src]     - mu) * rstd * gamma[c0]     + beta[c0];
        float v1 = (buf[src + 1] - mu) * rstd * gamma[c0 + 1] + beta[c0 + 1];
        v0 = fmaxf(v0, 0.f);
        v1 = fmaxf(v1, 0.f);
        __half2 h = __floats2half2_rn(v0, v1);
        vhi[((size_t)n * 256 + c2) * 256 + ss] = *(uint32_t*)&h;
    }
}

// ---------------------------------------------------------------------------
extern "C" void kernel_launch(void* const* d_in, const int* in_sizes, int n_in,
                              void* d_out, int out_size)
{
    const float* x   = (const float*)d_in[0];
    const int*   roi = (const int*)d_in[1];
    const float* Wq  = (const float*)d_in[2];
    const float* Wk  = (const float*)d_in[3];
    const float* Wv  = (const float*)d_in[4];
    const float* Wc  = (const float*)d_in[5];
    const float* gam = (const float*)d_in[6];
    const float* bet = (const float*)d_in[7];
    float* out = (float*)d_out;

    float *virt;
    __half *qh, *ql, *kh, *kl, *vth;
    uint32_t *xhi, *vhi, *wgh;
    cudaGetSymbolAddress((void**)&virt, g_virt);
    cudaGetSymbolAddress((void**)&qh,   g_qh);
    cudaGetSymbolAddress((void**)&ql,   g_ql);
    cudaGetSymbolAddress((void**)&kh,   g_kh);
    cudaGetSymbolAddress((void**)&kl,   g_kl);
    cudaGetSymbolAddress((void**)&vth,  g_vth);
    cudaGetSymbolAddress((void**)&xhi,  g_xhi);
    cudaGetSymbolAddress((void**)&vhi,  g_vhi);
    cudaGetSymbolAddress((void**)&wgh,  g_wgh);

    cudaFuncSetAttribute(conv_qkv_kernel, cudaFuncAttributeMaxDynamicSharedMemorySize,
                         CONV_SMEM);
    cudaFuncSetAttribute(conv_final_kernel, cudaFuncAttributeMaxDynamicSharedMemorySize,
                         CONV_SMEM);
    cudaFuncSetAttribute(attn_mma_kernel, cudaFuncAttributeMaxDynamicSharedMemorySize,
                         AT_SMEM_U32 * 4);

    xsplit_kernel<<<HPAIR / 256, 256>>>(x, xhi);
    wsplit_kernel<<<dim3(1152, 4), 256>>>(Wq, Wk, Wv, Wc, (uint4*)wgh);

    conv_qkv_kernel<<<dim3(256, 12, 2), 128, CONV_SMEM>>>(xhi, wgh, qh, ql, kh, kl, vth);

    attn_mma_kernel<<<dim3(4, 256), 256, AT_SMEM_U32 * 4>>>(qh, ql, kh, kl, vth, roi, virt);

    gn_relu_pack_kernel<<<256, 256>>>(virt, gam, bet, vhi);

    conv_final_kernel<<<dim3(256, 4, 2), 128, CONV_SMEM>>>(vhi, wgh, x, out);
}